// round 1
// baseline (speedup 1.0000x reference)
#include <cuda_runtime.h>

#define BB 4
#define CC 256
#define NN 4096
#define DD 64

// Scratch (device globals: allocation-free kernel_launch)
__device__ float g_q[BB * NN * DD];               // 4 MB  [b][n][d]
__device__ float g_v[(size_t)BB * CC * NN];       // 16 MB [b][c][n]
__device__ float g_E[(size_t)BB * NN * NN];       // 256 MB [b][n][m]
__device__ float g_rowmax[BB * NN];
__device__ float g_rowinv[BB * NN];
__device__ float g_xd[(size_t)BB * CC * NN];      // 16 MB
__device__ float g_t[(size_t)BB * CC * NN];       // 16 MB
__device__ float g_mean[CC];
__device__ float g_rstd[CC];

// ---------------------------------------------------------------------------
// 1x1 conv: out[o,n] = sum_c W[o,c]*x[b,c,n] (+bias). 64x64 tile, BK=16.
// TRANS_OUT=true stores out[(b*N+n)*DD + o] (q layout).
// ---------------------------------------------------------------------------
template <bool TRANS_OUT, bool HAS_BIAS>
__global__ __launch_bounds__(256) void conv1x1_kernel(
    const float* __restrict__ W, const float* __restrict__ x,
    const float* __restrict__ bias, float* __restrict__ out, int O)
{
    const int b  = blockIdx.z;
    const int o0 = blockIdx.y * 64;
    const int n0 = blockIdx.x * 64;
    const float* xb = x + (size_t)b * CC * NN;

    __shared__ float sW[16][64];      // [k][o]
    __shared__ float sX[16][65];      // [k][n]

    const int tid = threadIdx.x;
    const int tx = tid & 15, ty = tid >> 4;

    float acc[4][4] = {};

    for (int c0 = 0; c0 < CC; c0 += 16) {
#pragma unroll
        for (int r = 0; r < 4; r++) {
            int idx = tid + r * 256;           // idx over (o,k): o=idx>>4, k=idx&15
            int o = idx >> 4, k = idx & 15;
            sW[k][o] = W[(size_t)(o0 + o) * CC + c0 + k];
        }
#pragma unroll
        for (int r = 0; r < 4; r++) {
            int idx = tid + r * 256;           // idx over (k,n): k=idx>>6, n=idx&63
            int k = idx >> 6, n = idx & 63;
            sX[k][n] = xb[(size_t)(c0 + k) * NN + n0 + n];
        }
        __syncthreads();
#pragma unroll
        for (int k = 0; k < 16; k++) {
            float a[4], bv2[4];
#pragma unroll
            for (int i = 0; i < 4; i++) a[i] = sW[k][ty * 4 + i];
#pragma unroll
            for (int j = 0; j < 4; j++) bv2[j] = sX[k][tx * 4 + j];
#pragma unroll
            for (int i = 0; i < 4; i++)
#pragma unroll
                for (int j = 0; j < 4; j++) acc[i][j] += a[i] * bv2[j];
        }
        __syncthreads();
    }

#pragma unroll
    for (int i = 0; i < 4; i++) {
        int o = o0 + ty * 4 + i;
        float bi = HAS_BIAS ? bias[o] : 0.f;
        if (TRANS_OUT) {
#pragma unroll
            for (int j = 0; j < 4; j++) {
                int n = n0 + tx * 4 + j;
                out[((size_t)b * NN + n) * DD + o] = acc[i][j] + bi;
            }
        } else {
            float4 v4;
            v4.x = acc[i][0] + bi; v4.y = acc[i][1] + bi;
            v4.z = acc[i][2] + bi; v4.w = acc[i][3] + bi;
            *reinterpret_cast<float4*>(
                &out[((size_t)b * O + o) * NN + n0 + tx * 4]) = v4;
        }
    }
}

// ---------------------------------------------------------------------------
// energy: E[b,n,m] = dot(q[b,n,:], q[b,m,:]).  64x64 tile, full K=64.
// ---------------------------------------------------------------------------
__global__ __launch_bounds__(256) void energy_kernel()
{
    const int b  = blockIdx.z;
    const int n0 = blockIdx.y * 64;
    const int m0 = blockIdx.x * 64;
    const float* q = g_q + (size_t)b * NN * DD;
    float* E = g_E + (size_t)b * NN * NN;

    __shared__ float sA[64][65];
    __shared__ float sB[64][65];

    const int tid = threadIdx.x;
#pragma unroll
    for (int r = 0; r < 16; r++) {
        int idx = tid + r * 256;
        int row = idx >> 6, d = idx & 63;
        sA[row][d] = q[(size_t)(n0 + row) * DD + d];
        sB[row][d] = q[(size_t)(m0 + row) * DD + d];
    }
    __syncthreads();

    const int tx = tid & 15, ty = tid >> 4;
    float acc[4][4] = {};
#pragma unroll 8
    for (int k = 0; k < 64; k++) {
        float a[4], bb[4];
#pragma unroll
        for (int i = 0; i < 4; i++) a[i] = sA[ty * 4 + i][k];
#pragma unroll
        for (int j = 0; j < 4; j++) bb[j] = sB[tx * 4 + j][k];
#pragma unroll
        for (int i = 0; i < 4; i++)
#pragma unroll
            for (int j = 0; j < 4; j++) acc[i][j] += a[i] * bb[j];
    }
#pragma unroll
    for (int i = 0; i < 4; i++) {
        float4 v4;
        v4.x = acc[i][0]; v4.y = acc[i][1]; v4.z = acc[i][2]; v4.w = acc[i][3];
        *reinterpret_cast<float4*>(
            &E[(size_t)(n0 + ty * 4 + i) * NN + m0 + tx * 4]) = v4;
    }
}

// ---------------------------------------------------------------------------
// Row stats: online max + sum(exp) per row of E. One warp per row.
// ---------------------------------------------------------------------------
__global__ __launch_bounds__(256) void rowstats_kernel()
{
    int row = blockIdx.x * 8 + (threadIdx.x >> 5);   // global row in [0, B*N)
    int lane = threadIdx.x & 31;
    const float* r = g_E + (size_t)row * NN;

    float m = -1e30f, s = 0.f;
    for (int i = lane; i < NN; i += 32) {
        float e = r[i];
        if (e <= m) {
            s += __expf(e - m);
        } else {
            s = s * __expf(m - e) + 1.f;
            m = e;
        }
    }
#pragma unroll
    for (int off = 16; off; off >>= 1) {
        float mo = __shfl_xor_sync(0xffffffffu, m, off);
        float so = __shfl_xor_sync(0xffffffffu, s, off);
        float M = fmaxf(m, mo);
        s = s * __expf(m - M) + so * __expf(mo - M);
        m = M;
    }
    if (lane == 0) {
        g_rowmax[row] = m;
        g_rowinv[row] = 1.f / s;
    }
}

// ---------------------------------------------------------------------------
// x_a + x_d: per (b, m-tile of 64), loop n: p = softmax(E) row-normalized,
// accumulate colsum[m] and acc[c,m] += v[c,n]*p[n,m]; write
// x_d = x - acc/(1e-9+colsum).  256x64 output tile, NT=32.
// ---------------------------------------------------------------------------
__global__ __launch_bounds__(256) void xa_kernel(const float* __restrict__ x)
{
    const int b  = blockIdx.y;
    const int m0 = blockIdx.x * 64;
    const float* Eb  = g_E + (size_t)b * NN * NN;
    const float* vb  = g_v + (size_t)b * CC * NN;
    const float* rmx = g_rowmax + b * NN;
    const float* rin = g_rowinv + b * NN;

    __shared__ float sV[256][33];     // [c][n]
    __shared__ float sP[32][65];      // [n][m]
    __shared__ float sCol[64];

    const int tid = threadIdx.x;
    if (tid < 64) sCol[tid] = 0.f;

    const int cg = tid >> 3;          // c base = cg*8
    const int mg = tid & 7;           // m base = mg*8

    float acc[8][8] = {};

    for (int n0 = 0; n0 < NN; n0 += 32) {
#pragma unroll
        for (int r = 0; r < 32; r++) {
            int idx = tid + r * 256;
            int c = idx >> 5, n = idx & 31;
            sV[c][n] = vb[(size_t)c * NN + n0 + n];
        }
#pragma unroll
        for (int r = 0; r < 8; r++) {
            int idx = tid + r * 256;
            int n = idx >> 6, m = idx & 63;
            float e = Eb[(size_t)(n0 + n) * NN + m0 + m];
            sP[n][m] = __expf(e - rmx[n0 + n]) * rin[n0 + n];
        }
        __syncthreads();

        if (tid < 64) {
            float cs = 0.f;
#pragma unroll
            for (int n = 0; n < 32; n++) cs += sP[n][tid];
            sCol[tid] += cs;
        }

#pragma unroll 8
        for (int n = 0; n < 32; n++) {
            float pv[8], vv[8];
#pragma unroll
            for (int j = 0; j < 8; j++) pv[j] = sP[n][mg * 8 + j];
#pragma unroll
            for (int i = 0; i < 8; i++) vv[i] = sV[cg * 8 + i][n];
#pragma unroll
            for (int i = 0; i < 8; i++)
#pragma unroll
                for (int j = 0; j < 8; j++) acc[i][j] += vv[i] * pv[j];
        }
        __syncthreads();
    }

    float inv[8];
#pragma unroll
    for (int j = 0; j < 8; j++) inv[j] = 1.f / (1e-9f + sCol[mg * 8 + j]);

#pragma unroll
    for (int i = 0; i < 8; i++) {
        int c = cg * 8 + i;
        size_t base = ((size_t)b * CC + c) * NN + m0 + mg * 8;
        float4 x0 = *reinterpret_cast<const float4*>(&x[base]);
        float4 x1 = *reinterpret_cast<const float4*>(&x[base + 4]);
        float4 d0, d1;
        d0.x = x0.x - acc[i][0] * inv[0];
        d0.y = x0.y - acc[i][1] * inv[1];
        d0.z = x0.z - acc[i][2] * inv[2];
        d0.w = x0.w - acc[i][3] * inv[3];
        d1.x = x1.x - acc[i][4] * inv[4];
        d1.y = x1.y - acc[i][5] * inv[5];
        d1.z = x1.z - acc[i][6] * inv[6];
        d1.w = x1.w - acc[i][7] * inv[7];
        *reinterpret_cast<float4*>(&g_xd[base]) = d0;
        *reinterpret_cast<float4*>(&g_xd[base + 4]) = d1;
    }
}

// ---------------------------------------------------------------------------
// BN stats: per channel c, mean/var over (B, N).
// ---------------------------------------------------------------------------
__global__ __launch_bounds__(256) void bnstats_kernel()
{
    const int c = blockIdx.x;
    float s = 0.f, s2 = 0.f;
    for (int i = threadIdx.x; i < BB * NN; i += 256) {
        int b = i >> 12;
        int n = i & (NN - 1);
        float v = g_t[((size_t)b * CC + c) * NN + n];
        s += v;
        s2 += v * v;
    }
    __shared__ float rs[256], rs2[256];
    rs[threadIdx.x] = s;
    rs2[threadIdx.x] = s2;
    __syncthreads();
    for (int st = 128; st; st >>= 1) {
        if (threadIdx.x < st) {
            rs[threadIdx.x]  += rs[threadIdx.x + st];
            rs2[threadIdx.x] += rs2[threadIdx.x + st];
        }
        __syncthreads();
    }
    if (threadIdx.x == 0) {
        const float invM = 1.f / (float)(BB * NN);
        float mean = rs[0] * invM;
        float var = rs2[0] * invM - mean * mean;
        g_mean[c] = mean;
        g_rstd[c] = rsqrtf(var + 1e-5f);
    }
}

// ---------------------------------------------------------------------------
// Final: out = x + relu(gamma * (t - mean) * rstd + beta)
// ---------------------------------------------------------------------------
__global__ __launch_bounds__(256) void final_kernel(
    const float* __restrict__ x, const float* __restrict__ gamma,
    const float* __restrict__ beta, float* __restrict__ out)
{
    size_t i = (size_t)blockIdx.x * 256 + threadIdx.x;
    int c = (int)((i >> 12) & 255);
    float t = g_t[i];
    float th = (t - g_mean[c]) * g_rstd[c];
    float r = fmaxf(0.f, gamma[c] * th + beta[c]);
    out[i] = x[i] + r;
}

// ---------------------------------------------------------------------------
extern "C" void kernel_launch(void* const* d_in, const int* in_sizes, int n_in,
                              void* d_out, int out_size)
{
    const float* x     = (const float*)d_in[0];
    const float* wq    = (const float*)d_in[1];
    const float* wv    = (const float*)d_in[2];
    const float* bv    = (const float*)d_in[3];
    const float* wt    = (const float*)d_in[4];
    const float* bt    = (const float*)d_in[5];
    const float* gamma = (const float*)d_in[6];
    const float* beta  = (const float*)d_in[7];
    float* out = (float*)d_out;

    void* p;
    cudaGetSymbolAddress(&p, g_q);  float* qp  = (float*)p;
    cudaGetSymbolAddress(&p, g_v);  float* vp  = (float*)p;
    cudaGetSymbolAddress(&p, g_xd); float* xdp = (float*)p;
    cudaGetSymbolAddress(&p, g_t);  float* tp  = (float*)p;

    // q projection (weight-tied Q/K): [B,N,64]
    conv1x1_kernel<true, false><<<dim3(NN / 64, 1, BB), 256>>>(wq, x, nullptr, qp, DD);
    // v projection: [B,C,N]
    conv1x1_kernel<false, true><<<dim3(NN / 64, CC / 64, BB), 256>>>(wv, x, bv, vp, CC);
    // energy: [B,N,N]
    energy_kernel<<<dim3(NN / 64, NN / 64, BB), 256>>>();
    // per-row softmax stats
    rowstats_kernel<<<(BB * NN) / 8, 256>>>();
    // x_a (with double normalization) and x_d = x - x_a
    xa_kernel<<<dim3(NN / 64, BB), 256>>>(x);
    // trans conv: t = wt @ x_d + bt
    conv1x1_kernel<false, true><<<dim3(NN / 64, CC / 64, BB), 256>>>(wt, xdp, bt, tp, CC);
    // BN stats + final fused relu/residual
    bnstats_kernel<<<CC, 256>>>();
    final_kernel<<<(BB * CC * NN) / 256, 256>>>(x, gamma, beta, out);
}

// round 2
// speedup vs baseline: 1.5616x; 1.5616x over previous
#include <cuda_runtime.h>
#include <cstdint>

#define BB 4
#define CC 256
#define NN 4096
#define DD 64

// Scratch (device globals: allocation-free kernel_launch)
__device__ float g_q[BB * NN * DD];               // 4 MB  [b][n][d]
__device__ float g_v[(size_t)BB * CC * NN];       // 16 MB [b][c][n]
__device__ float g_E[(size_t)BB * NN * NN];       // 256 MB [b][n][m]
__device__ float g_rowmax[BB * NN];
__device__ float g_rowinv[BB * NN];
__device__ float g_xd[(size_t)BB * CC * NN];      // 16 MB
__device__ float g_t[(size_t)BB * CC * NN];       // 16 MB
__device__ float g_mean[CC];
__device__ float g_rstd[CC];

// ---------------------------------------------------------------------------
// tf32 helpers
// ---------------------------------------------------------------------------
__device__ __forceinline__ unsigned f2tf(float f)
{
    unsigned u;
    asm("cvt.rna.tf32.f32 %0, %1;" : "=r"(u) : "f"(f));
    return u;
}

__device__ __forceinline__ void mma_tf32(
    float& c0, float& c1, float& c2, float& c3,
    unsigned a0, unsigned a1, unsigned a2, unsigned a3,
    unsigned b0, unsigned b1)
{
    asm volatile(
        "mma.sync.aligned.m16n8k8.row.col.f32.tf32.tf32.f32 "
        "{%0,%1,%2,%3}, {%4,%5,%6,%7}, {%8,%9}, {%0,%1,%2,%3};\n"
        : "+f"(c0), "+f"(c1), "+f"(c2), "+f"(c3)
        : "r"(a0), "r"(a1), "r"(a2), "r"(a3), "r"(b0), "r"(b1));
}

// ---------------------------------------------------------------------------
// 1x1 conv: out[o,n] = sum_c W[o,c]*x[b,c,n] (+bias). 64x64 tile, BK=16.
// TRANS_OUT=true stores out[(b*N+n)*DD + o] (q layout).
// ---------------------------------------------------------------------------
template <bool TRANS_OUT, bool HAS_BIAS>
__global__ __launch_bounds__(256) void conv1x1_kernel(
    const float* __restrict__ W, const float* __restrict__ x,
    const float* __restrict__ bias, float* __restrict__ out, int O)
{
    const int b  = blockIdx.z;
    const int o0 = blockIdx.y * 64;
    const int n0 = blockIdx.x * 64;
    const float* xb = x + (size_t)b * CC * NN;

    __shared__ float sW[16][64];      // [k][o]
    __shared__ float sX[16][65];      // [k][n]

    const int tid = threadIdx.x;
    const int tx = tid & 15, ty = tid >> 4;

    float acc[4][4] = {};

    for (int c0 = 0; c0 < CC; c0 += 16) {
#pragma unroll
        for (int r = 0; r < 4; r++) {
            int idx = tid + r * 256;           // idx over (o,k)
            int o = idx >> 4, k = idx & 15;
            sW[k][o] = W[(size_t)(o0 + o) * CC + c0 + k];
        }
#pragma unroll
        for (int r = 0; r < 4; r++) {
            int idx = tid + r * 256;           // idx over (k,n)
            int k = idx >> 6, n = idx & 63;
            sX[k][n] = xb[(size_t)(c0 + k) * NN + n0 + n];
        }
        __syncthreads();
#pragma unroll
        for (int k = 0; k < 16; k++) {
            float a[4], bv2[4];
#pragma unroll
            for (int i = 0; i < 4; i++) a[i] = sW[k][ty * 4 + i];
#pragma unroll
            for (int j = 0; j < 4; j++) bv2[j] = sX[k][tx * 4 + j];
#pragma unroll
            for (int i = 0; i < 4; i++)
#pragma unroll
                for (int j = 0; j < 4; j++) acc[i][j] += a[i] * bv2[j];
        }
        __syncthreads();
    }

#pragma unroll
    for (int i = 0; i < 4; i++) {
        int o = o0 + ty * 4 + i;
        float bi = HAS_BIAS ? bias[o] : 0.f;
        if (TRANS_OUT) {
#pragma unroll
            for (int j = 0; j < 4; j++) {
                int n = n0 + tx * 4 + j;
                out[((size_t)b * NN + n) * DD + o] = acc[i][j] + bi;
            }
        } else {
            float4 v4;
            v4.x = acc[i][0] + bi; v4.y = acc[i][1] + bi;
            v4.z = acc[i][2] + bi; v4.w = acc[i][3] + bi;
            *reinterpret_cast<float4*>(
                &out[((size_t)b * O + o) * NN + n0 + tx * 4]) = v4;
        }
    }
}

// ---------------------------------------------------------------------------
// energy (tensor core): E[b,n,m] = dot(q[b,n,:], q[b,m,:]).
// 128x128 tile, 8 warps (2x4), warp tile 64x32, tf32 m16n8k8.
// ---------------------------------------------------------------------------
__global__ __launch_bounds__(256) void energy_tc_kernel()
{
    const int b  = blockIdx.z;
    const int n0 = blockIdx.y * 128;
    const int m0 = blockIdx.x * 128;
    const float* q = g_q + (size_t)b * NN * DD;
    float* E = g_E + (size_t)b * NN * NN;

    __shared__ unsigned sA[128][36];   // [n][k], (4g+k)%32 conflict-free
    __shared__ unsigned sB[128][36];   // [m][k]

    const int tid = threadIdx.x;
    const int lane = tid & 31, wid = tid >> 5;
    const int wm = wid >> 2, wn = wid & 3;
    const int gp = lane >> 2, tg = lane & 3;

    float acc[4][4][4] = {};

    for (int k0 = 0; k0 < DD; k0 += 32) {
        __syncthreads();
#pragma unroll
        for (int r = 0; r < 16; r++) {
            int idx = tid + r * 256;
            int row = idx >> 5, k = idx & 31;
            sA[row][k] = f2tf(q[(size_t)(n0 + row) * DD + k0 + k]);
            sB[row][k] = f2tf(q[(size_t)(m0 + row) * DD + k0 + k]);
        }
        __syncthreads();
#pragma unroll
        for (int kk = 0; kk < 32; kk += 8) {
            unsigned a[4][4], bf[4][2];
#pragma unroll
            for (int i = 0; i < 4; i++) {
                int row = wm * 64 + i * 16 + gp;
                a[i][0] = sA[row][kk + tg];
                a[i][1] = sA[row + 8][kk + tg];
                a[i][2] = sA[row][kk + tg + 4];
                a[i][3] = sA[row + 8][kk + tg + 4];
            }
#pragma unroll
            for (int j = 0; j < 4; j++) {
                int col = wn * 32 + j * 8 + gp;
                bf[j][0] = sB[col][kk + tg];
                bf[j][1] = sB[col][kk + tg + 4];
            }
#pragma unroll
            for (int i = 0; i < 4; i++)
#pragma unroll
                for (int j = 0; j < 4; j++)
                    mma_tf32(acc[i][j][0], acc[i][j][1], acc[i][j][2], acc[i][j][3],
                             a[i][0], a[i][1], a[i][2], a[i][3],
                             bf[j][0], bf[j][1]);
        }
    }

#pragma unroll
    for (int i = 0; i < 4; i++) {
        int r0 = n0 + wm * 64 + i * 16 + gp;
#pragma unroll
        for (int j = 0; j < 4; j++) {
            int c = m0 + wn * 32 + j * 8 + 2 * tg;
            float2 v0 = make_float2(acc[i][j][0], acc[i][j][1]);
            float2 v1 = make_float2(acc[i][j][2], acc[i][j][3]);
            *reinterpret_cast<float2*>(&E[(size_t)r0 * NN + c]) = v0;
            *reinterpret_cast<float2*>(&E[(size_t)(r0 + 8) * NN + c]) = v1;
        }
    }
}

// ---------------------------------------------------------------------------
// Row stats: online max + sum(exp) per row of E. One warp per row.
// ---------------------------------------------------------------------------
__global__ __launch_bounds__(256) void rowstats_kernel()
{
    int row = blockIdx.x * 8 + (threadIdx.x >> 5);   // global row in [0, B*N)
    int lane = threadIdx.x & 31;
    const float* r = g_E + (size_t)row * NN;

    float m = -1e30f, s = 0.f;
    for (int i = lane; i < NN; i += 32) {
        float e = r[i];
        if (e <= m) {
            s += __expf(e - m);
        } else {
            s = s * __expf(m - e) + 1.f;
            m = e;
        }
    }
#pragma unroll
    for (int off = 16; off; off >>= 1) {
        float mo = __shfl_xor_sync(0xffffffffu, m, off);
        float so = __shfl_xor_sync(0xffffffffu, s, off);
        float M = fmaxf(m, mo);
        s = s * __expf(m - M) + so * __expf(mo - M);
        m = M;
    }
    if (lane == 0) {
        g_rowmax[row] = m;
        g_rowinv[row] = 1.f / s;
    }
}

// ---------------------------------------------------------------------------
// x_a + x_d (tensor core): per (b, c-half 128, m-tile 128), loop n in 32s:
// P from E on the fly (tf32), colsum accumulated, acc = V*P via mma,
// write x_d = x - acc/(1e-9+colsum).
// ---------------------------------------------------------------------------
__global__ __launch_bounds__(256) void xa_tc_kernel(const float* __restrict__ x)
{
    const int b  = blockIdx.z;
    const int ch = blockIdx.y * 128;
    const int m0 = blockIdx.x * 128;
    const float* Eb  = g_E + (size_t)b * NN * NN;
    const float* vb  = g_v + (size_t)b * CC * NN + (size_t)ch * NN;
    const float* rmx = g_rowmax + b * NN;
    const float* rin = g_rowinv + b * NN;

    __shared__ unsigned sV[128][36];    // [c][n]
    __shared__ unsigned sP[32][132];    // [n][m], (4k+m)%32 conflict-free
    __shared__ float sCol[128];

    const int tid = threadIdx.x;
    const int lane = tid & 31, wid = tid >> 5;
    const int wm = wid >> 2, wn = wid & 3;
    const int gp = lane >> 2, tg = lane & 3;

    if (tid < 128) sCol[tid] = 0.f;

    float acc[4][4][4] = {};

    for (int n0 = 0; n0 < NN; n0 += 32) {
        __syncthreads();
#pragma unroll
        for (int r = 0; r < 16; r++) {
            int idx = tid + r * 256;
            int c = idx >> 5, n = idx & 31;
            sV[c][n] = f2tf(vb[(size_t)c * NN + n0 + n]);
        }
#pragma unroll
        for (int r = 0; r < 16; r++) {
            int idx = tid + r * 256;
            int k = idx >> 7, m = idx & 127;
            float e = Eb[(size_t)(n0 + k) * NN + m0 + m];
            float p = __expf(e - rmx[n0 + k]) * rin[n0 + k];
            sP[k][m] = f2tf(p);
        }
        __syncthreads();

        if (tid < 128) {
            float cs = 0.f;
#pragma unroll
            for (int k = 0; k < 32; k++) cs += __uint_as_float(sP[k][tid]);
            sCol[tid] += cs;
        }

#pragma unroll
        for (int kk = 0; kk < 32; kk += 8) {
            unsigned a[4][4], bf[4][2];
#pragma unroll
            for (int i = 0; i < 4; i++) {
                int row = wm * 64 + i * 16 + gp;
                a[i][0] = sV[row][kk + tg];
                a[i][1] = sV[row + 8][kk + tg];
                a[i][2] = sV[row][kk + tg + 4];
                a[i][3] = sV[row + 8][kk + tg + 4];
            }
#pragma unroll
            for (int j = 0; j < 4; j++) {
                int col = wn * 32 + j * 8 + gp;
                bf[j][0] = sP[kk + tg][col];
                bf[j][1] = sP[kk + tg + 4][col];
            }
#pragma unroll
            for (int i = 0; i < 4; i++)
#pragma unroll
                for (int j = 0; j < 4; j++)
                    mma_tf32(acc[i][j][0], acc[i][j][1], acc[i][j][2], acc[i][j][3],
                             a[i][0], a[i][1], a[i][2], a[i][3],
                             bf[j][0], bf[j][1]);
        }
    }
    __syncthreads();   // sCol final

#pragma unroll
    for (int j = 0; j < 4; j++) {
        int colr = wn * 32 + j * 8 + 2 * tg;
        float i0 = 1.f / (1e-9f + sCol[colr]);
        float i1 = 1.f / (1e-9f + sCol[colr + 1]);
#pragma unroll
        for (int i = 0; i < 4; i++) {
            int c = ch + wm * 64 + i * 16 + gp;
            size_t base = ((size_t)b * CC + c) * NN + m0 + colr;
            float2 xv = *reinterpret_cast<const float2*>(&x[base]);
            float2 o;
            o.x = xv.x - acc[i][j][0] * i0;
            o.y = xv.y - acc[i][j][1] * i1;
            *reinterpret_cast<float2*>(&g_xd[base]) = o;
            size_t base2 = base + (size_t)8 * NN;
            float2 xv2 = *reinterpret_cast<const float2*>(&x[base2]);
            float2 o2;
            o2.x = xv2.x - acc[i][j][2] * i0;
            o2.y = xv2.y - acc[i][j][3] * i1;
            *reinterpret_cast<float2*>(&g_xd[base2]) = o2;
        }
    }
}

// ---------------------------------------------------------------------------
// BN stats: per channel c, mean/var over (B, N).
// ---------------------------------------------------------------------------
__global__ __launch_bounds__(256) void bnstats_kernel()
{
    const int c = blockIdx.x;
    float s = 0.f, s2 = 0.f;
    for (int i = threadIdx.x; i < BB * NN; i += 256) {
        int b = i >> 12;
        int n = i & (NN - 1);
        float v = g_t[((size_t)b * CC + c) * NN + n];
        s += v;
        s2 += v * v;
    }
    __shared__ float rs[256], rs2[256];
    rs[threadIdx.x] = s;
    rs2[threadIdx.x] = s2;
    __syncthreads();
    for (int st = 128; st; st >>= 1) {
        if (threadIdx.x < st) {
            rs[threadIdx.x]  += rs[threadIdx.x + st];
            rs2[threadIdx.x] += rs2[threadIdx.x + st];
        }
        __syncthreads();
    }
    if (threadIdx.x == 0) {
        const float invM = 1.f / (float)(BB * NN);
        float mean = rs[0] * invM;
        float var = rs2[0] * invM - mean * mean;
        g_mean[c] = mean;
        g_rstd[c] = rsqrtf(var + 1e-5f);
    }
}

// ---------------------------------------------------------------------------
// Final: out = x + relu(gamma * (t - mean) * rstd + beta)
// ---------------------------------------------------------------------------
__global__ __launch_bounds__(256) void final_kernel(
    const float* __restrict__ x, const float* __restrict__ gamma,
    const float* __restrict__ beta, float* __restrict__ out)
{
    size_t i = (size_t)blockIdx.x * 256 + threadIdx.x;
    int c = (int)((i >> 12) & 255);
    float t = g_t[i];
    float th = (t - g_mean[c]) * g_rstd[c];
    float r = fmaxf(0.f, gamma[c] * th + beta[c]);
    out[i] = x[i] + r;
}

// ---------------------------------------------------------------------------
extern "C" void kernel_launch(void* const* d_in, const int* in_sizes, int n_in,
                              void* d_out, int out_size)
{
    const float* x     = (const float*)d_in[0];
    const float* wq    = (const float*)d_in[1];
    const float* wv    = (const float*)d_in[2];
    const float* bv    = (const float*)d_in[3];
    const float* wt    = (const float*)d_in[4];
    const float* bt    = (const float*)d_in[5];
    const float* gamma = (const float*)d_in[6];
    const float* beta  = (const float*)d_in[7];
    float* out = (float*)d_out;

    void* p;
    cudaGetSymbolAddress(&p, g_q);  float* qp  = (float*)p;
    cudaGetSymbolAddress(&p, g_v);  float* vp  = (float*)p;
    cudaGetSymbolAddress(&p, g_xd); float* xdp = (float*)p;
    cudaGetSymbolAddress(&p, g_t);  float* tp  = (float*)p;

    // q projection (weight-tied Q/K): [B,N,64]
    conv1x1_kernel<true, false><<<dim3(NN / 64, 1, BB), 256>>>(wq, x, nullptr, qp, DD);
    // v projection: [B,C,N]
    conv1x1_kernel<false, true><<<dim3(NN / 64, CC / 64, BB), 256>>>(wv, x, bv, vp, CC);
    // energy: [B,N,N] (tensor cores, tf32)
    energy_tc_kernel<<<dim3(NN / 128, NN / 128, BB), 256>>>();
    // per-row softmax stats
    rowstats_kernel<<<(BB * NN) / 8, 256>>>();
    // x_a (with double normalization) and x_d = x - x_a (tensor cores, tf32)
    xa_tc_kernel<<<dim3(NN / 128, CC / 128, BB), 256>>>(x);
    // trans conv: t = wt @ x_d + bt
    conv1x1_kernel<false, true><<<dim3(NN / 64, CC / 64, BB), 256>>>(wt, xdp, bt, tp, CC);
    // BN stats + final fused relu/residual
    bnstats_kernel<<<CC, 256>>>();
    final_kernel<<<(BB * CC * NN) / 256, 256>>>(x, gamma, beta, out);
}

// round 3
// speedup vs baseline: 1.9811x; 1.2687x over previous
#include <cuda_runtime.h>
#include <cstdint>

#define BB 4
#define CC 256
#define NN 4096
#define DD 64

// Scratch (device globals: allocation-free kernel_launch)
__device__ float g_q[BB * NN * DD];               // 4 MB  [b][n][d]
__device__ float g_v[(size_t)BB * CC * NN];       // 16 MB [b][c][n]
__device__ float g_E[(size_t)BB * NN * NN];       // 256 MB [b][n][m]
__device__ float g_rowmax[BB * NN];
__device__ float g_rowinv[BB * NN];
__device__ float g_xd[(size_t)BB * CC * NN];      // 16 MB
__device__ float g_t[(size_t)BB * CC * NN];       // 16 MB
__device__ float g_mean[CC];
__device__ float g_rstd[CC];

// ---------------------------------------------------------------------------
// tf32 helpers
// ---------------------------------------------------------------------------
__device__ __forceinline__ unsigned f2tf(float f)
{
    unsigned u;
    asm("cvt.rna.tf32.f32 %0, %1;" : "=r"(u) : "f"(f));
    return u;
}

__device__ __forceinline__ void mma_tf32(
    float& c0, float& c1, float& c2, float& c3,
    unsigned a0, unsigned a1, unsigned a2, unsigned a3,
    unsigned b0, unsigned b1)
{
    asm volatile(
        "mma.sync.aligned.m16n8k8.row.col.f32.tf32.tf32.f32 "
        "{%0,%1,%2,%3}, {%4,%5,%6,%7}, {%8,%9}, {%0,%1,%2,%3};\n"
        : "+f"(c0), "+f"(c1), "+f"(c2), "+f"(c3)
        : "r"(a0), "r"(a1), "r"(a2), "r"(a3), "r"(b0), "r"(b1));
}

// ---------------------------------------------------------------------------
// 1x1 conv: out[o,n] = sum_c W[o,c]*x[b,c,n] (+bias). 64x64 tile, BK=16.
// TRANS_OUT=true stores out[(b*N+n)*DD + o] (q layout).
// ---------------------------------------------------------------------------
template <bool TRANS_OUT, bool HAS_BIAS>
__global__ __launch_bounds__(256) void conv1x1_kernel(
    const float* __restrict__ W, const float* __restrict__ x,
    const float* __restrict__ bias, float* __restrict__ out, int O)
{
    const int b  = blockIdx.z;
    const int o0 = blockIdx.y * 64;
    const int n0 = blockIdx.x * 64;
    const float* xb = x + (size_t)b * CC * NN;

    __shared__ float sW[16][64];      // [k][o]
    __shared__ float sX[16][65];      // [k][n]

    const int tid = threadIdx.x;
    const int tx = tid & 15, ty = tid >> 4;

    float acc[4][4] = {};

    for (int c0 = 0; c0 < CC; c0 += 16) {
#pragma unroll
        for (int r = 0; r < 4; r++) {
            int idx = tid + r * 256;           // idx over (o,k)
            int o = idx >> 4, k = idx & 15;
            sW[k][o] = W[(size_t)(o0 + o) * CC + c0 + k];
        }
#pragma unroll
        for (int r = 0; r < 4; r++) {
            int idx = tid + r * 256;           // idx over (k,n)
            int k = idx >> 6, n = idx & 63;
            sX[k][n] = xb[(size_t)(c0 + k) * NN + n0 + n];
        }
        __syncthreads();
#pragma unroll
        for (int k = 0; k < 16; k++) {
            float a[4], bv2[4];
#pragma unroll
            for (int i = 0; i < 4; i++) a[i] = sW[k][ty * 4 + i];
#pragma unroll
            for (int j = 0; j < 4; j++) bv2[j] = sX[k][tx * 4 + j];
#pragma unroll
            for (int i = 0; i < 4; i++)
#pragma unroll
                for (int j = 0; j < 4; j++) acc[i][j] += a[i] * bv2[j];
        }
        __syncthreads();
    }

#pragma unroll
    for (int i = 0; i < 4; i++) {
        int o = o0 + ty * 4 + i;
        float bi = HAS_BIAS ? bias[o] : 0.f;
        if (TRANS_OUT) {
#pragma unroll
            for (int j = 0; j < 4; j++) {
                int n = n0 + tx * 4 + j;
                out[((size_t)b * NN + n) * DD + o] = acc[i][j] + bi;
            }
        } else {
            float4 v4;
            v4.x = acc[i][0] + bi; v4.y = acc[i][1] + bi;
            v4.z = acc[i][2] + bi; v4.w = acc[i][3] + bi;
            *reinterpret_cast<float4*>(
                &out[((size_t)b * O + o) * NN + n0 + tx * 4]) = v4;
        }
    }
}

// ---------------------------------------------------------------------------
// energy (tensor core): E[b,n,m] = dot(q[b,n,:], q[b,m,:]).
// 128x128 tile, 8 warps (2x4), warp tile 64x32, tf32 m16n8k8.
// ---------------------------------------------------------------------------
__global__ __launch_bounds__(256) void energy_tc_kernel()
{
    const int b  = blockIdx.z;
    const int n0 = blockIdx.y * 128;
    const int m0 = blockIdx.x * 128;
    const float* q = g_q + (size_t)b * NN * DD;
    float* E = g_E + (size_t)b * NN * NN;

    __shared__ unsigned sA[128][36];   // [n][k], (4g+k)%32 conflict-free
    __shared__ unsigned sB[128][36];   // [m][k]

    const int tid = threadIdx.x;
    const int lane = tid & 31, wid = tid >> 5;
    const int wm = wid >> 2, wn = wid & 3;
    const int gp = lane >> 2, tg = lane & 3;

    float acc[4][4][4] = {};

    for (int k0 = 0; k0 < DD; k0 += 32) {
        __syncthreads();
#pragma unroll
        for (int r = 0; r < 16; r++) {
            int idx = tid + r * 256;
            int row = idx >> 5, k = idx & 31;
            sA[row][k] = f2tf(q[(size_t)(n0 + row) * DD + k0 + k]);
            sB[row][k] = f2tf(q[(size_t)(m0 + row) * DD + k0 + k]);
        }
        __syncthreads();
#pragma unroll
        for (int kk = 0; kk < 32; kk += 8) {
            unsigned a[4][4], bf[4][2];
#pragma unroll
            for (int i = 0; i < 4; i++) {
                int row = wm * 64 + i * 16 + gp;
                a[i][0] = sA[row][kk + tg];
                a[i][1] = sA[row + 8][kk + tg];
                a[i][2] = sA[row][kk + tg + 4];
                a[i][3] = sA[row + 8][kk + tg + 4];
            }
#pragma unroll
            for (int j = 0; j < 4; j++) {
                int col = wn * 32 + j * 8 + gp;
                bf[j][0] = sB[col][kk + tg];
                bf[j][1] = sB[col][kk + tg + 4];
            }
#pragma unroll
            for (int i = 0; i < 4; i++)
#pragma unroll
                for (int j = 0; j < 4; j++)
                    mma_tf32(acc[i][j][0], acc[i][j][1], acc[i][j][2], acc[i][j][3],
                             a[i][0], a[i][1], a[i][2], a[i][3],
                             bf[j][0], bf[j][1]);
        }
    }

#pragma unroll
    for (int i = 0; i < 4; i++) {
        int r0 = n0 + wm * 64 + i * 16 + gp;
#pragma unroll
        for (int j = 0; j < 4; j++) {
            int c = m0 + wn * 32 + j * 8 + 2 * tg;
            float2 v0 = make_float2(acc[i][j][0], acc[i][j][1]);
            float2 v1 = make_float2(acc[i][j][2], acc[i][j][3]);
            *reinterpret_cast<float2*>(&E[(size_t)r0 * NN + c]) = v0;
            *reinterpret_cast<float2*>(&E[(size_t)(r0 + 8) * NN + c]) = v1;
        }
    }
}

// ---------------------------------------------------------------------------
// Row stats: online max + sum(exp) per row of E. One warp per row.
// ---------------------------------------------------------------------------
__global__ __launch_bounds__(256) void rowstats_kernel()
{
    int row = blockIdx.x * 8 + (threadIdx.x >> 5);   // global row in [0, B*N)
    int lane = threadIdx.x & 31;
    const float* r = g_E + (size_t)row * NN;

    float m = -1e30f, s = 0.f;
    for (int i = lane; i < NN; i += 32) {
        float e = r[i];
        if (e <= m) {
            s += __expf(e - m);
        } else {
            s = s * __expf(m - e) + 1.f;
            m = e;
        }
    }
#pragma unroll
    for (int off = 16; off; off >>= 1) {
        float mo = __shfl_xor_sync(0xffffffffu, m, off);
        float so = __shfl_xor_sync(0xffffffffu, s, off);
        float M = fmaxf(m, mo);
        s = s * __expf(m - M) + so * __expf(mo - M);
        m = M;
    }
    if (lane == 0) {
        g_rowmax[row] = m;
        g_rowinv[row] = 1.f / s;
    }
}

// ---------------------------------------------------------------------------
// x_a + x_d (tensor core): per (b, c-half 128, m-tile 128), loop n in 32s:
// P from E on the fly (tf32), colsum accumulated, acc = V*P via mma,
// write x_d = x - acc/(1e-9+colsum).
// ---------------------------------------------------------------------------
__global__ __launch_bounds__(256) void xa_tc_kernel(const float* __restrict__ x)
{
    const int b  = blockIdx.z;
    const int ch = blockIdx.y * 128;
    const int m0 = blockIdx.x * 128;
    const float* Eb  = g_E + (size_t)b * NN * NN;
    const float* vb  = g_v + (size_t)b * CC * NN + (size_t)ch * NN;
    const float* rmx = g_rowmax + b * NN;
    const float* rin = g_rowinv + b * NN;

    __shared__ unsigned sV[128][36];    // [c][n]
    __shared__ unsigned sP[32][132];    // [n][m], (4k+m)%32 conflict-free
    __shared__ float sCol[128];

    const int tid = threadIdx.x;
    const int lane = tid & 31, wid = tid >> 5;
    const int wm = wid >> 2, wn = wid & 3;
    const int gp = lane >> 2, tg = lane & 3;

    if (tid < 128) sCol[tid] = 0.f;

    float acc[4][4][4] = {};

    for (int n0 = 0; n0 < NN; n0 += 32) {
        __syncthreads();
#pragma unroll
        for (int r = 0; r < 16; r++) {
            int idx = tid + r * 256;
            int c = idx >> 5, n = idx & 31;
            sV[c][n] = f2tf(vb[(size_t)c * NN + n0 + n]);
        }
#pragma unroll
        for (int r = 0; r < 16; r++) {
            int idx = tid + r * 256;
            int k = idx >> 7, m = idx & 127;
            float e = Eb[(size_t)(n0 + k) * NN + m0 + m];
            float p = __expf(e - rmx[n0 + k]) * rin[n0 + k];
            sP[k][m] = f2tf(p);
        }
        __syncthreads();

        if (tid < 128) {
            float cs = 0.f;
#pragma unroll
            for (int k = 0; k < 32; k++) cs += __uint_as_float(sP[k][tid]);
            sCol[tid] += cs;
        }

#pragma unroll
        for (int kk = 0; kk < 32; kk += 8) {
            unsigned a[4][4], bf[4][2];
#pragma unroll
            for (int i = 0; i < 4; i++) {
                int row = wm * 64 + i * 16 + gp;
                a[i][0] = sV[row][kk + tg];
                a[i][1] = sV[row + 8][kk + tg];
                a[i][2] = sV[row][kk + tg + 4];
                a[i][3] = sV[row + 8][kk + tg + 4];
            }
#pragma unroll
            for (int j = 0; j < 4; j++) {
                int col = wn * 32 + j * 8 + gp;
                bf[j][0] = sP[kk + tg][col];
                bf[j][1] = sP[kk + tg + 4][col];
            }
#pragma unroll
            for (int i = 0; i < 4; i++)
#pragma unroll
                for (int j = 0; j < 4; j++)
                    mma_tf32(acc[i][j][0], acc[i][j][1], acc[i][j][2], acc[i][j][3],
                             a[i][0], a[i][1], a[i][2], a[i][3],
                             bf[j][0], bf[j][1]);
        }
    }
    __syncthreads();   // sCol final

#pragma unroll
    for (int j = 0; j < 4; j++) {
        int colr = wn * 32 + j * 8 + 2 * tg;
        float i0 = 1.f / (1e-9f + sCol[colr]);
        float i1 = 1.f / (1e-9f + sCol[colr + 1]);
#pragma unroll
        for (int i = 0; i < 4; i++) {
            int c = ch + wm * 64 + i * 16 + gp;
            size_t base = ((size_t)b * CC + c) * NN + m0 + colr;
            float2 xv = *reinterpret_cast<const float2*>(&x[base]);
            float2 o;
            o.x = xv.x - acc[i][j][0] * i0;
            o.y = xv.y - acc[i][j][1] * i1;
            *reinterpret_cast<float2*>(&g_xd[base]) = o;
            size_t base2 = base + (size_t)8 * NN;
            float2 xv2 = *reinterpret_cast<const float2*>(&x[base2]);
            float2 o2;
            o2.x = xv2.x - acc[i][j][2] * i0;
            o2.y = xv2.y - acc[i][j][3] * i1;
            *reinterpret_cast<float2*>(&g_xd[base2]) = o2;
        }
    }
}

// ---------------------------------------------------------------------------
// BN stats: per channel c, mean/var over (B, N).
// ---------------------------------------------------------------------------
__global__ __launch_bounds__(256) void bnstats_kernel()
{
    const int c = blockIdx.x;
    float s = 0.f, s2 = 0.f;
    for (int i = threadIdx.x; i < BB * NN; i += 256) {
        int b = i >> 12;
        int n = i & (NN - 1);
        float v = g_t[((size_t)b * CC + c) * NN + n];
        s += v;
        s2 += v * v;
    }
    __shared__ float rs[256], rs2[256];
    rs[threadIdx.x] = s;
    rs2[threadIdx.x] = s2;
    __syncthreads();
    for (int st = 128; st; st >>= 1) {
        if (threadIdx.x < st) {
            rs[threadIdx.x]  += rs[threadIdx.x + st];
            rs2[threadIdx.x] += rs2[threadIdx.x + st];
        }
        __syncthreads();
    }
    if (threadIdx.x == 0) {
        const float invM = 1.f / (float)(BB * NN);
        float mean = rs[0] * invM;
        float var = rs2[0] * invM - mean * mean;
        g_mean[c] = mean;
        g_rstd[c] = rsqrtf(var + 1e-5f);
    }
}

// ---------------------------------------------------------------------------
// Final: out = x + relu(gamma * (t - mean) * rstd + beta)
// ---------------------------------------------------------------------------
__global__ __launch_bounds__(256) void final_kernel(
    const float* __restrict__ x, const float* __restrict__ gamma,
    const float* __restrict__ beta, float* __restrict__ out)
{
    size_t i = (size_t)blockIdx.x * 256 + threadIdx.x;
    int c = (int)((i >> 12) & 255);
    float t = g_t[i];
    float th = (t - g_mean[c]) * g_rstd[c];
    float r = fmaxf(0.f, gamma[c] * th + beta[c]);
    out[i] = x[i] + r;
}

// ---------------------------------------------------------------------------
extern "C" void kernel_launch(void* const* d_in, const int* in_sizes, int n_in,
                              void* d_out, int out_size)
{
    const float* x     = (const float*)d_in[0];
    const float* wq    = (const float*)d_in[1];
    const float* wv    = (const float*)d_in[2];
    const float* bv    = (const float*)d_in[3];
    const float* wt    = (const float*)d_in[4];
    const float* bt    = (const float*)d_in[5];
    const float* gamma = (const float*)d_in[6];
    const float* beta  = (const float*)d_in[7];
    float* out = (float*)d_out;

    void* p;
    cudaGetSymbolAddress(&p, g_q);  float* qp  = (float*)p;
    cudaGetSymbolAddress(&p, g_v);  float* vp  = (float*)p;
    cudaGetSymbolAddress(&p, g_xd); float* xdp = (float*)p;
    cudaGetSymbolAddress(&p, g_t);  float* tp  = (float*)p;

    // q projection (weight-tied Q/K): [B,N,64]
    conv1x1_kernel<true, false><<<dim3(NN / 64, 1, BB), 256>>>(wq, x, nullptr, qp, DD);
    // v projection: [B,C,N]
    conv1x1_kernel<false, true><<<dim3(NN / 64, CC / 64, BB), 256>>>(wv, x, bv, vp, CC);
    // energy: [B,N,N] (tensor cores, tf32)
    energy_tc_kernel<<<dim3(NN / 128, NN / 128, BB), 256>>>();
    // per-row softmax stats
    rowstats_kernel<<<(BB * NN) / 8, 256>>>();
    // x_a (with double normalization) and x_d = x - x_a (tensor cores, tf32)
    xa_tc_kernel<<<dim3(NN / 128, CC / 128, BB), 256>>>(x);
    // trans conv: t = wt @ x_d + bt
    conv1x1_kernel<false, true><<<dim3(NN / 64, CC / 64, BB), 256>>>(wt, xdp, bt, tp, CC);
    // BN stats + final fused relu/residual
    bnstats_kernel<<<CC, 256>>>();
    final_kernel<<<(BB * CC * NN) / 256, 256>>>(x, gamma, beta, out);
}

// round 4
// speedup vs baseline: 2.3539x; 1.1882x over previous
#include <cuda_runtime.h>
#include <cuda_fp16.h>
#include <cstdint>

#define BB 4
#define CC 256
#define NN 4096
#define DD 64

// Scratch (device globals: allocation-free kernel_launch)
__device__ unsigned g_qh[(size_t)BB * NN * 32];   // 2 MB  q fp16 pairs [b][n][k/2]
__device__ float g_v[(size_t)BB * CC * NN];       // 16 MB [b][c][n]
__device__ float g_rowmax[BB * NN];
__device__ float g_rowinv[BB * NN];
__device__ float g_xd[(size_t)BB * CC * NN];      // 16 MB
__device__ float g_t[(size_t)BB * CC * NN];       // 16 MB
__device__ float g_mean[CC];
__device__ float g_rstd[CC];

// ---------------------------------------------------------------------------
// helpers
// ---------------------------------------------------------------------------
__device__ __forceinline__ unsigned f2tf(float f)
{
    unsigned u;
    asm("cvt.rna.tf32.f32 %0, %1;" : "=r"(u) : "f"(f));
    return u;
}

__device__ __forceinline__ void mma_tf32(
    float& c0, float& c1, float& c2, float& c3,
    unsigned a0, unsigned a1, unsigned a2, unsigned a3,
    unsigned b0, unsigned b1)
{
    asm volatile(
        "mma.sync.aligned.m16n8k8.row.col.f32.tf32.tf32.f32 "
        "{%0,%1,%2,%3}, {%4,%5,%6,%7}, {%8,%9}, {%0,%1,%2,%3};\n"
        : "+f"(c0), "+f"(c1), "+f"(c2), "+f"(c3)
        : "r"(a0), "r"(a1), "r"(a2), "r"(a3), "r"(b0), "r"(b1));
}

__device__ __forceinline__ void mma_fp16(
    float* c,
    unsigned a0, unsigned a1, unsigned a2, unsigned a3,
    unsigned b0, unsigned b1)
{
    asm volatile(
        "mma.sync.aligned.m16n8k16.row.col.f32.f16.f16.f32 "
        "{%0,%1,%2,%3}, {%4,%5,%6,%7}, {%8,%9}, {%0,%1,%2,%3};\n"
        : "+f"(c[0]), "+f"(c[1]), "+f"(c[2]), "+f"(c[3])
        : "r"(a0), "r"(a1), "r"(a2), "r"(a3), "r"(b0), "r"(b1));
}

// ---------------------------------------------------------------------------
// 1x1 conv: out[o,n] = sum_c W[o,c]*x[b,c,n] (+bias). 64x64 tile, BK=16.
// ---------------------------------------------------------------------------
template <bool HAS_BIAS>
__global__ __launch_bounds__(256) void conv1x1_kernel(
    const float* __restrict__ W, const float* __restrict__ x,
    const float* __restrict__ bias, float* __restrict__ out, int O)
{
    const int b  = blockIdx.z;
    const int o0 = blockIdx.y * 64;
    const int n0 = blockIdx.x * 64;
    const float* xb = x + (size_t)b * CC * NN;

    __shared__ float sW[16][64];      // [k][o]
    __shared__ float sX[16][65];      // [k][n]

    const int tid = threadIdx.x;
    const int tx = tid & 15, ty = tid >> 4;

    float acc[4][4] = {};

    for (int c0 = 0; c0 < CC; c0 += 16) {
#pragma unroll
        for (int r = 0; r < 4; r++) {
            int idx = tid + r * 256;
            int o = idx >> 4, k = idx & 15;
            sW[k][o] = W[(size_t)(o0 + o) * CC + c0 + k];
        }
#pragma unroll
        for (int r = 0; r < 4; r++) {
            int idx = tid + r * 256;
            int k = idx >> 6, n = idx & 63;
            sX[k][n] = xb[(size_t)(c0 + k) * NN + n0 + n];
        }
        __syncthreads();
#pragma unroll
        for (int k = 0; k < 16; k++) {
            float a[4], bv2[4];
#pragma unroll
            for (int i = 0; i < 4; i++) a[i] = sW[k][ty * 4 + i];
#pragma unroll
            for (int j = 0; j < 4; j++) bv2[j] = sX[k][tx * 4 + j];
#pragma unroll
            for (int i = 0; i < 4; i++)
#pragma unroll
                for (int j = 0; j < 4; j++) acc[i][j] += a[i] * bv2[j];
        }
        __syncthreads();
    }

#pragma unroll
    for (int i = 0; i < 4; i++) {
        int o = o0 + ty * 4 + i;
        float bi = HAS_BIAS ? bias[o] : 0.f;
        float4 v4;
        v4.x = acc[i][0] + bi; v4.y = acc[i][1] + bi;
        v4.z = acc[i][2] + bi; v4.w = acc[i][3] + bi;
        *reinterpret_cast<float4*>(
            &out[((size_t)b * O + o) * NN + n0 + tx * 4]) = v4;
    }
}

// ---------------------------------------------------------------------------
// q projection writing fp16 pairs: g_qh[(b*N+n)*32 + o/2]
// ---------------------------------------------------------------------------
__global__ __launch_bounds__(256) void convq_kernel(
    const float* __restrict__ W, const float* __restrict__ x)
{
    const int b  = blockIdx.z;
    const int n0 = blockIdx.x * 64;
    const float* xb = x + (size_t)b * CC * NN;

    __shared__ float sW[16][64];
    __shared__ float sX[16][65];

    const int tid = threadIdx.x;
    const int tx = tid & 15, ty = tid >> 4;

    float acc[4][4] = {};

    for (int c0 = 0; c0 < CC; c0 += 16) {
#pragma unroll
        for (int r = 0; r < 4; r++) {
            int idx = tid + r * 256;
            int o = idx >> 4, k = idx & 15;
            sW[k][o] = W[(size_t)o * CC + c0 + k];
        }
#pragma unroll
        for (int r = 0; r < 4; r++) {
            int idx = tid + r * 256;
            int k = idx >> 6, n = idx & 63;
            sX[k][n] = xb[(size_t)(c0 + k) * NN + n0 + n];
        }
        __syncthreads();
#pragma unroll
        for (int k = 0; k < 16; k++) {
            float a[4], bv2[4];
#pragma unroll
            for (int i = 0; i < 4; i++) a[i] = sW[k][ty * 4 + i];
#pragma unroll
            for (int j = 0; j < 4; j++) bv2[j] = sX[k][tx * 4 + j];
#pragma unroll
            for (int i = 0; i < 4; i++)
#pragma unroll
                for (int j = 0; j < 4; j++) acc[i][j] += a[i] * bv2[j];
        }
        __syncthreads();
    }

#pragma unroll
    for (int j = 0; j < 4; j++) {
        int n = n0 + tx * 4 + j;
        __half2 h0 = __floats2half2_rn(acc[0][j], acc[1][j]);
        __half2 h1 = __floats2half2_rn(acc[2][j], acc[3][j]);
        size_t base = ((size_t)b * NN + n) * 32 + ty * 2;
        g_qh[base]     = *reinterpret_cast<unsigned*>(&h0);
        g_qh[base + 1] = *reinterpret_cast<unsigned*>(&h1);
    }
}

// ---------------------------------------------------------------------------
// pass1: fused energy + row softmax stats (flash pass). 128-row n-tile per
// block; loops m in 128-chunks, E tile in regs (fp16 mma), online max/sumexp.
// Writes g_rowmax / g_rowinv only.
// ---------------------------------------------------------------------------
__global__ __launch_bounds__(256) void pass1_kernel()
{
    const int b  = blockIdx.y;
    const int n0 = blockIdx.x * 128;
    const unsigned* qh = g_qh + (size_t)b * NN * 32;

    __shared__ unsigned sA[128][36];     // q_n fp16 pairs [row][k/2]
    __shared__ unsigned sB[128][36];     // q_m chunk
    __shared__ float2 sMrg[4][128];

    const int tid = threadIdx.x;
    const int lane = tid & 31, wid = tid >> 5;
    const int wm = wid >> 2, wn = wid & 3;
    const int gp = lane >> 2, tg = lane & 3;

#pragma unroll
    for (int r = 0; r < 16; r++) {
        int idx = tid + r * 256;
        int row = idx >> 5, kp = idx & 31;
        sA[row][kp] = qh[(size_t)(n0 + row) * 32 + kp];
    }

    float rmax[8], rsum[8];
#pragma unroll
    for (int i = 0; i < 8; i++) { rmax[i] = -1e30f; rsum[i] = 0.f; }

    for (int m0 = 0; m0 < NN; m0 += 128) {
        __syncthreads();
#pragma unroll
        for (int r = 0; r < 16; r++) {
            int idx = tid + r * 256;
            int row = idx >> 5, kp = idx & 31;
            sB[row][kp] = qh[(size_t)(m0 + row) * 32 + kp];
        }
        __syncthreads();

        float acc[4][4][4] = {};
#pragma unroll
        for (int ks = 0; ks < 4; ks++) {
            int kp0 = ks * 8;
            unsigned a[4][4], bf[4][2];
#pragma unroll
            for (int i = 0; i < 4; i++) {
                int row = wm * 64 + i * 16 + gp;
                a[i][0] = sA[row][kp0 + tg];
                a[i][1] = sA[row + 8][kp0 + tg];
                a[i][2] = sA[row][kp0 + 4 + tg];
                a[i][3] = sA[row + 8][kp0 + 4 + tg];
            }
#pragma unroll
            for (int j = 0; j < 4; j++) {
                int col = wn * 32 + j * 8 + gp;
                bf[j][0] = sB[col][kp0 + tg];
                bf[j][1] = sB[col][kp0 + 4 + tg];
            }
#pragma unroll
            for (int i = 0; i < 4; i++)
#pragma unroll
                for (int j = 0; j < 4; j++)
                    mma_fp16(acc[i][j], a[i][0], a[i][1], a[i][2], a[i][3],
                             bf[j][0], bf[j][1]);
        }

        // online stats update (rows r = wm*64+i*16+gp and +8)
#pragma unroll
        for (int i = 0; i < 4; i++) {
            float m0v = -1e30f, m1v = -1e30f;
#pragma unroll
            for (int j = 0; j < 4; j++) {
                m0v = fmaxf(m0v, fmaxf(acc[i][j][0], acc[i][j][1]));
                m1v = fmaxf(m1v, fmaxf(acc[i][j][2], acc[i][j][3]));
            }
            m0v = fmaxf(m0v, __shfl_xor_sync(0xffffffffu, m0v, 1));
            m0v = fmaxf(m0v, __shfl_xor_sync(0xffffffffu, m0v, 2));
            m1v = fmaxf(m1v, __shfl_xor_sync(0xffffffffu, m1v, 1));
            m1v = fmaxf(m1v, __shfl_xor_sync(0xffffffffu, m1v, 2));
            float nm0 = fmaxf(rmax[2 * i],     m0v);
            float nm1 = fmaxf(rmax[2 * i + 1], m1v);
            float s0 = 0.f, s1 = 0.f;
#pragma unroll
            for (int j = 0; j < 4; j++) {
                s0 += __expf(acc[i][j][0] - nm0) + __expf(acc[i][j][1] - nm0);
                s1 += __expf(acc[i][j][2] - nm1) + __expf(acc[i][j][3] - nm1);
            }
            s0 += __shfl_xor_sync(0xffffffffu, s0, 1);
            s0 += __shfl_xor_sync(0xffffffffu, s0, 2);
            s1 += __shfl_xor_sync(0xffffffffu, s1, 1);
            s1 += __shfl_xor_sync(0xffffffffu, s1, 2);
            rsum[2 * i]     = rsum[2 * i]     * __expf(rmax[2 * i]     - nm0) + s0;
            rsum[2 * i + 1] = rsum[2 * i + 1] * __expf(rmax[2 * i + 1] - nm1) + s1;
            rmax[2 * i]     = nm0;
            rmax[2 * i + 1] = nm1;
        }
    }

    if (tg == 0) {
#pragma unroll
        for (int i = 0; i < 4; i++) {
            int row = wm * 64 + i * 16 + gp;
            sMrg[wn][row]     = make_float2(rmax[2 * i],     rsum[2 * i]);
            sMrg[wn][row + 8] = make_float2(rmax[2 * i + 1], rsum[2 * i + 1]);
        }
    }
    __syncthreads();
    if (tid < 128) {
        float2 v0 = sMrg[0][tid], v1 = sMrg[1][tid];
        float2 v2 = sMrg[2][tid], v3 = sMrg[3][tid];
        float M = fmaxf(fmaxf(v0.x, v1.x), fmaxf(v2.x, v3.x));
        float S = v0.y * __expf(v0.x - M) + v1.y * __expf(v1.x - M)
                + v2.y * __expf(v2.x - M) + v3.y * __expf(v3.x - M);
        g_rowmax[b * NN + n0 + tid] = M;
        g_rowinv[b * NN + n0 + tid] = 1.f / S;
    }
}

// ---------------------------------------------------------------------------
// xa: fused E-recompute + P + colsum + V*P (tensor cores).
// Per (b, ch 128, m-tile 128): loop n in 32s:
//   mma1 (fp16): E chunk [32,128] from q; exp -> tf32 P smem; colsum;
//   mma2 (tf32): acc += V * P.  Epilogue: x_d = x - acc/(1e-9+colsum).
// q_m B-fragments live in registers for the whole block.
// ---------------------------------------------------------------------------
__global__ __launch_bounds__(256, 1) void xa_kernel(const float* __restrict__ x)
{
    const int b  = blockIdx.z;
    const int ch = blockIdx.y * 128;
    const int m0 = blockIdx.x * 128;
    const float* vb  = g_v + (size_t)b * CC * NN + (size_t)ch * NN;
    const float* rmx = g_rowmax + b * NN;
    const float* rin = g_rowinv + b * NN;
    const unsigned* qh = g_qh + (size_t)b * NN * 32;

    __shared__ unsigned sQn[32][36];    // q_n chunk fp16 pairs
    __shared__ unsigned sV[128][36];    // V tf32 [c][n]
    __shared__ unsigned sP[32][132];    // P tf32 [n][m]
    __shared__ float sCol[128];

    const int tid = threadIdx.x;
    const int lane = tid & 31, wid = tid >> 5;
    const int gp = lane >> 2, tg = lane & 3;
    // mma1 roles
    const int h1 = wid & 1;             // m16 row-half of E chunk
    const int wc1 = wid >> 1;           // col quarter (32 cols)
    // mma2 roles
    const int wm = wid >> 2, wn = wid & 3;

    if (tid < 128) sCol[tid] = 0.f;

    // q_m fragments in registers (fixed for the block)
    unsigned bq[4][4][2];
#pragma unroll
    for (int j = 0; j < 4; j++) {
        int col = m0 + wc1 * 32 + j * 8 + gp;
#pragma unroll
        for (int ks = 0; ks < 4; ks++) {
            int kp0 = ks * 8;
            bq[j][ks][0] = __ldg(&qh[(size_t)col * 32 + kp0 + tg]);
            bq[j][ks][1] = __ldg(&qh[(size_t)col * 32 + kp0 + 4 + tg]);
        }
    }

    float acc[4][4][4] = {};

    for (int n0 = 0; n0 < NN; n0 += 32) {
        __syncthreads();
#pragma unroll
        for (int r = 0; r < 4; r++) {
            int idx = tid + r * 256;
            int row = idx >> 5, kp = idx & 31;
            sQn[row][kp] = qh[(size_t)(n0 + row) * 32 + kp];
        }
#pragma unroll
        for (int r = 0; r < 16; r++) {
            int idx = tid + r * 256;
            int c = idx >> 5, n = idx & 31;
            sV[c][n] = f2tf(vb[(size_t)c * NN + n0 + n]);
        }
        __syncthreads();

        // mma1: E chunk rows h1*16+gp(+8), cols wc1*32 + j*8 + 2tg(+1)
        float e[4][4] = {};
#pragma unroll
        for (int ks = 0; ks < 4; ks++) {
            int kp0 = ks * 8;
            unsigned a0 = sQn[h1 * 16 + gp][kp0 + tg];
            unsigned a1 = sQn[h1 * 16 + gp + 8][kp0 + tg];
            unsigned a2 = sQn[h1 * 16 + gp][kp0 + 4 + tg];
            unsigned a3 = sQn[h1 * 16 + gp + 8][kp0 + 4 + tg];
#pragma unroll
            for (int j = 0; j < 4; j++)
                mma_fp16(e[j], a0, a1, a2, a3, bq[j][ks][0], bq[j][ks][1]);
        }

        int r0 = n0 + h1 * 16 + gp;
        float mx0 = __ldg(&rmx[r0]),     iv0 = __ldg(&rin[r0]);
        float mx1 = __ldg(&rmx[r0 + 8]), iv1 = __ldg(&rin[r0 + 8]);
#pragma unroll
        for (int j = 0; j < 4; j++) {
            int cb = wc1 * 32 + j * 8 + 2 * tg;
            sP[h1 * 16 + gp][cb]         = f2tf(__expf(e[j][0] - mx0) * iv0);
            sP[h1 * 16 + gp][cb + 1]     = f2tf(__expf(e[j][1] - mx0) * iv0);
            sP[h1 * 16 + gp + 8][cb]     = f2tf(__expf(e[j][2] - mx1) * iv1);
            sP[h1 * 16 + gp + 8][cb + 1] = f2tf(__expf(e[j][3] - mx1) * iv1);
        }
        __syncthreads();

        if (tid < 128) {
            float cs = 0.f;
#pragma unroll
            for (int k = 0; k < 32; k++) cs += __uint_as_float(sP[k][tid]);
            sCol[tid] += cs;
        }

        // mma2: warp tile 64x32 over [128c,128m]
#pragma unroll
        for (int kk = 0; kk < 32; kk += 8) {
            unsigned a[4][4], bf[4][2];
#pragma unroll
            for (int i = 0; i < 4; i++) {
                int row = wm * 64 + i * 16 + gp;
                a[i][0] = sV[row][kk + tg];
                a[i][1] = sV[row + 8][kk + tg];
                a[i][2] = sV[row][kk + tg + 4];
                a[i][3] = sV[row + 8][kk + tg + 4];
            }
#pragma unroll
            for (int j = 0; j < 4; j++) {
                int col = wn * 32 + j * 8 + gp;
                bf[j][0] = sP[kk + tg][col];
                bf[j][1] = sP[kk + tg + 4][col];
            }
#pragma unroll
            for (int i = 0; i < 4; i++)
#pragma unroll
                for (int j = 0; j < 4; j++)
                    mma_tf32(acc[i][j][0], acc[i][j][1], acc[i][j][2], acc[i][j][3],
                             a[i][0], a[i][1], a[i][2], a[i][3],
                             bf[j][0], bf[j][1]);
        }
    }
    __syncthreads();   // sCol final

#pragma unroll
    for (int j = 0; j < 4; j++) {
        int colr = wn * 32 + j * 8 + 2 * tg;
        float i0 = 1.f / (1e-9f + sCol[colr]);
        float i1 = 1.f / (1e-9f + sCol[colr + 1]);
#pragma unroll
        for (int i = 0; i < 4; i++) {
            int c = ch + wm * 64 + i * 16 + gp;
            size_t base = ((size_t)b * CC + c) * NN + m0 + colr;
            float2 xv = *reinterpret_cast<const float2*>(&x[base]);
            float2 o;
            o.x = xv.x - acc[i][j][0] * i0;
            o.y = xv.y - acc[i][j][1] * i1;
            *reinterpret_cast<float2*>(&g_xd[base]) = o;
            size_t base2 = base + (size_t)8 * NN;
            float2 xv2 = *reinterpret_cast<const float2*>(&x[base2]);
            float2 o2;
            o2.x = xv2.x - acc[i][j][2] * i0;
            o2.y = xv2.y - acc[i][j][3] * i1;
            *reinterpret_cast<float2*>(&g_xd[base2]) = o2;
        }
    }
}

// ---------------------------------------------------------------------------
// BN stats: per channel c, mean/var over (B, N).
// ---------------------------------------------------------------------------
__global__ __launch_bounds__(256) void bnstats_kernel()
{
    const int c = blockIdx.x;
    float s = 0.f, s2 = 0.f;
    for (int i = threadIdx.x; i < BB * NN; i += 256) {
        int b = i >> 12;
        int n = i & (NN - 1);
        float v = g_t[((size_t)b * CC + c) * NN + n];
        s += v;
        s2 += v * v;
    }
    __shared__ float rs[256], rs2[256];
    rs[threadIdx.x] = s;
    rs2[threadIdx.x] = s2;
    __syncthreads();
    for (int st = 128; st; st >>= 1) {
        if (threadIdx.x < st) {
            rs[threadIdx.x]  += rs[threadIdx.x + st];
            rs2[threadIdx.x] += rs2[threadIdx.x + st];
        }
        __syncthreads();
    }
    if (threadIdx.x == 0) {
        const float invM = 1.f / (float)(BB * NN);
        float mean = rs[0] * invM;
        float var = rs2[0] * invM - mean * mean;
        g_mean[c] = mean;
        g_rstd[c] = rsqrtf(var + 1e-5f);
    }
}

// ---------------------------------------------------------------------------
// Final: out = x + relu(gamma * (t - mean) * rstd + beta)
// ---------------------------------------------------------------------------
__global__ __launch_bounds__(256) void final_kernel(
    const float* __restrict__ x, const float* __restrict__ gamma,
    const float* __restrict__ beta, float* __restrict__ out)
{
    size_t i = (size_t)blockIdx.x * 256 + threadIdx.x;
    int c = (int)((i >> 12) & 255);
    float t = g_t[i];
    float th = (t - g_mean[c]) * g_rstd[c];
    float r = fmaxf(0.f, gamma[c] * th + beta[c]);
    out[i] = x[i] + r;
}

// ---------------------------------------------------------------------------
extern "C" void kernel_launch(void* const* d_in, const int* in_sizes, int n_in,
                              void* d_out, int out_size)
{
    const float* x     = (const float*)d_in[0];
    const float* wq    = (const float*)d_in[1];
    const float* wv    = (const float*)d_in[2];
    const float* bv    = (const float*)d_in[3];
    const float* wt    = (const float*)d_in[4];
    const float* bt    = (const float*)d_in[5];
    const float* gamma = (const float*)d_in[6];
    const float* beta  = (const float*)d_in[7];
    float* out = (float*)d_out;

    void* p;
    cudaGetSymbolAddress(&p, g_v);  float* vp  = (float*)p;
    cudaGetSymbolAddress(&p, g_xd); float* xdp = (float*)p;
    cudaGetSymbolAddress(&p, g_t);  float* tp  = (float*)p;

    // q projection (weight-tied Q/K) -> fp16 [B,N,64]
    convq_kernel<<<dim3(NN / 64, 1, BB), 256>>>(wq, x);
    // v projection: [B,C,N] fp32
    conv1x1_kernel<true><<<dim3(NN / 64, CC / 64, BB), 256>>>(wv, x, bv, vp, CC);
    // fused energy + row softmax stats (no E materialization)
    pass1_kernel<<<dim3(NN / 128, BB), 256>>>();
    // fused E-recompute + softmax + double-norm + V*P -> x_d
    xa_kernel<<<dim3(NN / 128, CC / 128, BB), 256>>>(x);
    // trans conv: t = wt @ x_d + bt
    conv1x1_kernel<true><<<dim3(NN / 64, CC / 64, BB), 256>>>(wt, xdp, bt, tp, CC);
    // BN stats + final fused relu/residual
    bnstats_kernel<<<CC, 256>>>();
    final_kernel<<<(BB * CC * NN) / 256, 256>>>(x, gamma, beta, out);
}

// round 5
// speedup vs baseline: 2.7990x; 1.1891x over previous
#include <cuda_runtime.h>
#include <cuda_fp16.h>
#include <cstdint>

#define BB 4
#define CC 256
#define NN 4096
#define DD 64

// Scratch (device globals: allocation-free kernel_launch)
__device__ unsigned g_qh[(size_t)BB * NN * 32];   // 2 MB  q fp16 pairs [b][n][k/2]
__device__ float g_v[(size_t)BB * CC * NN];       // 16 MB [b][c][n]
__device__ float g_rowmax[BB * NN];
__device__ float g_rowinv[BB * NN];
__device__ float g_xd[(size_t)BB * CC * NN];      // 16 MB
__device__ float g_t[(size_t)BB * CC * NN];       // 16 MB
__device__ float g_mean[CC];
__device__ float g_rstd[CC];

// ---------------------------------------------------------------------------
// helpers
// ---------------------------------------------------------------------------
__device__ __forceinline__ unsigned f2tf(float f)
{
    unsigned u;
    asm("cvt.rna.tf32.f32 %0, %1;" : "=r"(u) : "f"(f));
    return u;
}

__device__ __forceinline__ void mma_tf32(
    float& c0, float& c1, float& c2, float& c3,
    unsigned a0, unsigned a1, unsigned a2, unsigned a3,
    unsigned b0, unsigned b1)
{
    asm volatile(
        "mma.sync.aligned.m16n8k8.row.col.f32.tf32.tf32.f32 "
        "{%0,%1,%2,%3}, {%4,%5,%6,%7}, {%8,%9}, {%0,%1,%2,%3};\n"
        : "+f"(c0), "+f"(c1), "+f"(c2), "+f"(c3)
        : "r"(a0), "r"(a1), "r"(a2), "r"(a3), "r"(b0), "r"(b1));
}

__device__ __forceinline__ void mma_fp16(
    float* c,
    unsigned a0, unsigned a1, unsigned a2, unsigned a3,
    unsigned b0, unsigned b1)
{
    asm volatile(
        "mma.sync.aligned.m16n8k16.row.col.f32.f16.f16.f32 "
        "{%0,%1,%2,%3}, {%4,%5,%6,%7}, {%8,%9}, {%0,%1,%2,%3};\n"
        : "+f"(c[0]), "+f"(c[1]), "+f"(c[2]), "+f"(c[3])
        : "r"(a0), "r"(a1), "r"(a2), "r"(a3), "r"(b0), "r"(b1));
}

// ---------------------------------------------------------------------------
// 1x1 conv: out[o,n] = sum_c W[o,c]*x[b,c,n] (+bias). 64x64 tile, BK=16.
// ---------------------------------------------------------------------------
template <bool HAS_BIAS>
__global__ __launch_bounds__(256) void conv1x1_kernel(
    const float* __restrict__ W, const float* __restrict__ x,
    const float* __restrict__ bias, float* __restrict__ out, int O)
{
    const int b  = blockIdx.z;
    const int o0 = blockIdx.y * 64;
    const int n0 = blockIdx.x * 64;
    const float* xb = x + (size_t)b * CC * NN;

    __shared__ float sW[16][64];      // [k][o]
    __shared__ float sX[16][65];      // [k][n]

    const int tid = threadIdx.x;
    const int tx = tid & 15, ty = tid >> 4;

    float acc[4][4] = {};

    for (int c0 = 0; c0 < CC; c0 += 16) {
#pragma unroll
        for (int r = 0; r < 4; r++) {
            int idx = tid + r * 256;
            int o = idx >> 4, k = idx & 15;
            sW[k][o] = W[(size_t)(o0 + o) * CC + c0 + k];
        }
#pragma unroll
        for (int r = 0; r < 4; r++) {
            int idx = tid + r * 256;
            int k = idx >> 6, n = idx & 63;
            sX[k][n] = xb[(size_t)(c0 + k) * NN + n0 + n];
        }
        __syncthreads();
#pragma unroll
        for (int k = 0; k < 16; k++) {
            float a[4], bv2[4];
#pragma unroll
            for (int i = 0; i < 4; i++) a[i] = sW[k][ty * 4 + i];
#pragma unroll
            for (int j = 0; j < 4; j++) bv2[j] = sX[k][tx * 4 + j];
#pragma unroll
            for (int i = 0; i < 4; i++)
#pragma unroll
                for (int j = 0; j < 4; j++) acc[i][j] += a[i] * bv2[j];
        }
        __syncthreads();
    }

#pragma unroll
    for (int i = 0; i < 4; i++) {
        int o = o0 + ty * 4 + i;
        float bi = HAS_BIAS ? bias[o] : 0.f;
        float4 v4;
        v4.x = acc[i][0] + bi; v4.y = acc[i][1] + bi;
        v4.z = acc[i][2] + bi; v4.w = acc[i][3] + bi;
        *reinterpret_cast<float4*>(
            &out[((size_t)b * O + o) * NN + n0 + tx * 4]) = v4;
    }
}

// ---------------------------------------------------------------------------
// q projection writing fp16 pairs: g_qh[(b*N+n)*32 + o/2]
// ---------------------------------------------------------------------------
__global__ __launch_bounds__(256) void convq_kernel(
    const float* __restrict__ W, const float* __restrict__ x)
{
    const int b  = blockIdx.z;
    const int n0 = blockIdx.x * 64;
    const float* xb = x + (size_t)b * CC * NN;

    __shared__ float sW[16][64];
    __shared__ float sX[16][65];

    const int tid = threadIdx.x;
    const int tx = tid & 15, ty = tid >> 4;

    float acc[4][4] = {};

    for (int c0 = 0; c0 < CC; c0 += 16) {
#pragma unroll
        for (int r = 0; r < 4; r++) {
            int idx = tid + r * 256;
            int o = idx >> 4, k = idx & 15;
            sW[k][o] = W[(size_t)o * CC + c0 + k];
        }
#pragma unroll
        for (int r = 0; r < 4; r++) {
            int idx = tid + r * 256;
            int k = idx >> 6, n = idx & 63;
            sX[k][n] = xb[(size_t)(c0 + k) * NN + n0 + n];
        }
        __syncthreads();
#pragma unroll
        for (int k = 0; k < 16; k++) {
            float a[4], bv2[4];
#pragma unroll
            for (int i = 0; i < 4; i++) a[i] = sW[k][ty * 4 + i];
#pragma unroll
            for (int j = 0; j < 4; j++) bv2[j] = sX[k][tx * 4 + j];
#pragma unroll
            for (int i = 0; i < 4; i++)
#pragma unroll
                for (int j = 0; j < 4; j++) acc[i][j] += a[i] * bv2[j];
        }
        __syncthreads();
    }

#pragma unroll
    for (int j = 0; j < 4; j++) {
        int n = n0 + tx * 4 + j;
        __half2 h0 = __floats2half2_rn(acc[0][j], acc[1][j]);
        __half2 h1 = __floats2half2_rn(acc[2][j], acc[3][j]);
        size_t base = ((size_t)b * NN + n) * 32 + ty * 2;
        g_qh[base]     = *reinterpret_cast<unsigned*>(&h0);
        g_qh[base + 1] = *reinterpret_cast<unsigned*>(&h1);
    }
}

// ---------------------------------------------------------------------------
// pass1: fused energy + row softmax stats (flash pass). 128-row n-tile per
// block; loops m in 128-chunks, E tile in regs (fp16 mma), online max/sumexp.
// ---------------------------------------------------------------------------
__global__ __launch_bounds__(256) void pass1_kernel()
{
    const int b  = blockIdx.y;
    const int n0 = blockIdx.x * 128;
    const unsigned* qh = g_qh + (size_t)b * NN * 32;

    __shared__ unsigned sA[128][36];     // q_n fp16 pairs [row][k/2]
    __shared__ unsigned sB[128][36];     // q_m chunk
    __shared__ float2 sMrg[4][128];

    const int tid = threadIdx.x;
    const int lane = tid & 31, wid = tid >> 5;
    const int wm = wid >> 2, wn = wid & 3;
    const int gp = lane >> 2, tg = lane & 3;

#pragma unroll
    for (int r = 0; r < 16; r++) {
        int idx = tid + r * 256;
        int row = idx >> 5, kp = idx & 31;
        sA[row][kp] = qh[(size_t)(n0 + row) * 32 + kp];
    }

    float rmax[8], rsum[8];
#pragma unroll
    for (int i = 0; i < 8; i++) { rmax[i] = -1e30f; rsum[i] = 0.f; }

    for (int m0 = 0; m0 < NN; m0 += 128) {
        __syncthreads();
#pragma unroll
        for (int r = 0; r < 16; r++) {
            int idx = tid + r * 256;
            int row = idx >> 5, kp = idx & 31;
            sB[row][kp] = qh[(size_t)(m0 + row) * 32 + kp];
        }
        __syncthreads();

        float acc[4][4][4] = {};
#pragma unroll
        for (int ks = 0; ks < 4; ks++) {
            int kp0 = ks * 8;
            unsigned a[4][4], bf[4][2];
#pragma unroll
            for (int i = 0; i < 4; i++) {
                int row = wm * 64 + i * 16 + gp;
                a[i][0] = sA[row][kp0 + tg];
                a[i][1] = sA[row + 8][kp0 + tg];
                a[i][2] = sA[row][kp0 + 4 + tg];
                a[i][3] = sA[row + 8][kp0 + 4 + tg];
            }
#pragma unroll
            for (int j = 0; j < 4; j++) {
                int col = wn * 32 + j * 8 + gp;
                bf[j][0] = sB[col][kp0 + tg];
                bf[j][1] = sB[col][kp0 + 4 + tg];
            }
#pragma unroll
            for (int i = 0; i < 4; i++)
#pragma unroll
                for (int j = 0; j < 4; j++)
                    mma_fp16(acc[i][j], a[i][0], a[i][1], a[i][2], a[i][3],
                             bf[j][0], bf[j][1]);
        }

#pragma unroll
        for (int i = 0; i < 4; i++) {
            float m0v = -1e30f, m1v = -1e30f;
#pragma unroll
            for (int j = 0; j < 4; j++) {
                m0v = fmaxf(m0v, fmaxf(acc[i][j][0], acc[i][j][1]));
                m1v = fmaxf(m1v, fmaxf(acc[i][j][2], acc[i][j][3]));
            }
            m0v = fmaxf(m0v, __shfl_xor_sync(0xffffffffu, m0v, 1));
            m0v = fmaxf(m0v, __shfl_xor_sync(0xffffffffu, m0v, 2));
            m1v = fmaxf(m1v, __shfl_xor_sync(0xffffffffu, m1v, 1));
            m1v = fmaxf(m1v, __shfl_xor_sync(0xffffffffu, m1v, 2));
            float nm0 = fmaxf(rmax[2 * i],     m0v);
            float nm1 = fmaxf(rmax[2 * i + 1], m1v);
            float s0 = 0.f, s1 = 0.f;
#pragma unroll
            for (int j = 0; j < 4; j++) {
                s0 += __expf(acc[i][j][0] - nm0) + __expf(acc[i][j][1] - nm0);
                s1 += __expf(acc[i][j][2] - nm1) + __expf(acc[i][j][3] - nm1);
            }
            s0 += __shfl_xor_sync(0xffffffffu, s0, 1);
            s0 += __shfl_xor_sync(0xffffffffu, s0, 2);
            s1 += __shfl_xor_sync(0xffffffffu, s1, 1);
            s1 += __shfl_xor_sync(0xffffffffu, s1, 2);
            rsum[2 * i]     = rsum[2 * i]     * __expf(rmax[2 * i]     - nm0) + s0;
            rsum[2 * i + 1] = rsum[2 * i + 1] * __expf(rmax[2 * i + 1] - nm1) + s1;
            rmax[2 * i]     = nm0;
            rmax[2 * i + 1] = nm1;
        }
    }

    if (tg == 0) {
#pragma unroll
        for (int i = 0; i < 4; i++) {
            int row = wm * 64 + i * 16 + gp;
            sMrg[wn][row]     = make_float2(rmax[2 * i],     rsum[2 * i]);
            sMrg[wn][row + 8] = make_float2(rmax[2 * i + 1], rsum[2 * i + 1]);
        }
    }
    __syncthreads();
    if (tid < 128) {
        float2 v0 = sMrg[0][tid], v1 = sMrg[1][tid];
        float2 v2 = sMrg[2][tid], v3 = sMrg[3][tid];
        float M = fmaxf(fmaxf(v0.x, v1.x), fmaxf(v2.x, v3.x));
        float S = v0.y * __expf(v0.x - M) + v1.y * __expf(v1.x - M)
                + v2.y * __expf(v2.x - M) + v3.y * __expf(v3.x - M);
        g_rowmax[b * NN + n0 + tid] = M;
        g_rowinv[b * NN + n0 + tid] = 1.f / S;
    }
}

// ---------------------------------------------------------------------------
// xa: fused E-recompute + P + colsum + V*P. 512 threads (16 warps), one CTA
// covers ALL 256 channels x 128 m-cols -> grid 32x4 = 128 CTAs (one wave).
// mma1 warp roles: h1=wid&1 (n row-half), wc1=wid>>1 (16-col group).
// mma2 warp roles: wm=wid>>2 (64 c), wn=wid&3 (32 m).
// ---------------------------------------------------------------------------
#define XA_SMEM_WORDS (256 * 36 + 128 * 36 + 32 * 36 + 32 * 132 + 128)

__global__ __launch_bounds__(512, 1) void xa_kernel(const float* __restrict__ x)
{
    const int b  = blockIdx.y;
    const int m0 = blockIdx.x * 128;
    const float* vb  = g_v + (size_t)b * CC * NN;
    const float* rmx = g_rowmax + b * NN;
    const float* rin = g_rowinv + b * NN;
    const unsigned* qh = g_qh + (size_t)b * NN * 32;

    extern __shared__ unsigned shm[];
    unsigned (*sV)[36]  = reinterpret_cast<unsigned(*)[36]>(shm);               // 256x36
    unsigned (*sQm)[36] = reinterpret_cast<unsigned(*)[36]>(shm + 256 * 36);    // 128x36
    unsigned (*sQn)[36] = reinterpret_cast<unsigned(*)[36]>(shm + 384 * 36);    // 32x36
    unsigned (*sP)[132] = reinterpret_cast<unsigned(*)[132]>(shm + 416 * 36);   // 32x132
    float* sCol = reinterpret_cast<float*>(shm + 416 * 36 + 32 * 132);          // 128

    const int tid = threadIdx.x;
    const int lane = tid & 31, wid = tid >> 5;
    const int gp = lane >> 2, tg = lane & 3;
    const int h1 = wid & 1, wc1 = wid >> 1;      // mma1
    const int wm = wid >> 2, wn = wid & 3;       // mma2

    // q_m tile (constant for the block)
#pragma unroll
    for (int r = 0; r < 8; r++) {
        int idx = tid + r * 512;
        int row = idx >> 5, kp = idx & 31;
        sQm[row][kp] = qh[(size_t)(m0 + row) * 32 + kp];
    }
    if (tid < 128) sCol[tid] = 0.f;

    float acc[4][4][4] = {};

    for (int n0 = 0; n0 < NN; n0 += 32) {
        __syncthreads();
#pragma unroll
        for (int r = 0; r < 2; r++) {
            int idx = tid + r * 512;
            int row = idx >> 5, kp = idx & 31;
            sQn[row][kp] = qh[(size_t)(n0 + row) * 32 + kp];
        }
#pragma unroll
        for (int r = 0; r < 16; r++) {
            int idx = tid + r * 512;
            int c = idx >> 5, n = idx & 31;
            sV[c][n] = f2tf(vb[(size_t)c * NN + n0 + n]);
        }
        __syncthreads();

        // mma1: E chunk rows h1*16+gp(+8), cols wc1*16 + j*8 + 2tg(+1)
        float e[2][4] = {};
#pragma unroll
        for (int ks = 0; ks < 4; ks++) {
            int kp0 = ks * 8;
            unsigned a0 = sQn[h1 * 16 + gp][kp0 + tg];
            unsigned a1 = sQn[h1 * 16 + gp + 8][kp0 + tg];
            unsigned a2 = sQn[h1 * 16 + gp][kp0 + 4 + tg];
            unsigned a3 = sQn[h1 * 16 + gp + 8][kp0 + 4 + tg];
#pragma unroll
            for (int j = 0; j < 2; j++) {
                int col = wc1 * 16 + j * 8 + gp;
                mma_fp16(e[j], a0, a1, a2, a3,
                         sQm[col][kp0 + tg], sQm[col][kp0 + 4 + tg]);
            }
        }

        int r0 = n0 + h1 * 16 + gp;
        float mx0 = __ldg(&rmx[r0]),     iv0 = __ldg(&rin[r0]);
        float mx1 = __ldg(&rmx[r0 + 8]), iv1 = __ldg(&rin[r0 + 8]);
#pragma unroll
        for (int j = 0; j < 2; j++) {
            int cb = wc1 * 16 + j * 8 + 2 * tg;
            sP[h1 * 16 + gp][cb]         = f2tf(__expf(e[j][0] - mx0) * iv0);
            sP[h1 * 16 + gp][cb + 1]     = f2tf(__expf(e[j][1] - mx0) * iv0);
            sP[h1 * 16 + gp + 8][cb]     = f2tf(__expf(e[j][2] - mx1) * iv1);
            sP[h1 * 16 + gp + 8][cb + 1] = f2tf(__expf(e[j][3] - mx1) * iv1);
        }
        __syncthreads();

        if (tid < 128) {
            float cs = 0.f;
#pragma unroll
            for (int k = 0; k < 32; k++) cs += __uint_as_float(sP[k][tid]);
            sCol[tid] += cs;
        }

        // mma2: warp tile 64c x 32m over [256c, 128m]
#pragma unroll
        for (int kk = 0; kk < 32; kk += 8) {
            unsigned a[4][4], bf[4][2];
#pragma unroll
            for (int i = 0; i < 4; i++) {
                int row = wm * 64 + i * 16 + gp;
                a[i][0] = sV[row][kk + tg];
                a[i][1] = sV[row + 8][kk + tg];
                a[i][2] = sV[row][kk + tg + 4];
                a[i][3] = sV[row + 8][kk + tg + 4];
            }
#pragma unroll
            for (int j = 0; j < 4; j++) {
                int col = wn * 32 + j * 8 + gp;
                bf[j][0] = sP[kk + tg][col];
                bf[j][1] = sP[kk + tg + 4][col];
            }
#pragma unroll
            for (int i = 0; i < 4; i++)
#pragma unroll
                for (int j = 0; j < 4; j++)
                    mma_tf32(acc[i][j][0], acc[i][j][1], acc[i][j][2], acc[i][j][3],
                             a[i][0], a[i][1], a[i][2], a[i][3],
                             bf[j][0], bf[j][1]);
        }
    }
    __syncthreads();   // sCol final

#pragma unroll
    for (int j = 0; j < 4; j++) {
        int colr = wn * 32 + j * 8 + 2 * tg;
        float i0 = 1.f / (1e-9f + sCol[colr]);
        float i1 = 1.f / (1e-9f + sCol[colr + 1]);
#pragma unroll
        for (int i = 0; i < 4; i++) {
            int c = wm * 64 + i * 16 + gp;
            size_t base = ((size_t)b * CC + c) * NN + m0 + colr;
            float2 xv = *reinterpret_cast<const float2*>(&x[base]);
            float2 o;
            o.x = xv.x - acc[i][j][0] * i0;
            o.y = xv.y - acc[i][j][1] * i1;
            *reinterpret_cast<float2*>(&g_xd[base]) = o;
            size_t base2 = base + (size_t)8 * NN;
            float2 xv2 = *reinterpret_cast<const float2*>(&x[base2]);
            float2 o2;
            o2.x = xv2.x - acc[i][j][2] * i0;
            o2.y = xv2.y - acc[i][j][3] * i1;
            *reinterpret_cast<float2*>(&g_xd[base2]) = o2;
        }
    }
}

// ---------------------------------------------------------------------------
// BN stats: per channel c, mean/var over (B, N).
// ---------------------------------------------------------------------------
__global__ __launch_bounds__(256) void bnstats_kernel()
{
    const int c = blockIdx.x;
    float s = 0.f, s2 = 0.f;
    for (int i = threadIdx.x; i < BB * NN; i += 256) {
        int b = i >> 12;
        int n = i & (NN - 1);
        float v = g_t[((size_t)b * CC + c) * NN + n];
        s += v;
        s2 += v * v;
    }
    __shared__ float rs[256], rs2[256];
    rs[threadIdx.x] = s;
    rs2[threadIdx.x] = s2;
    __syncthreads();
    for (int st = 128; st; st >>= 1) {
        if (threadIdx.x < st) {
            rs[threadIdx.x]  += rs[threadIdx.x + st];
            rs2[threadIdx.x] += rs2[threadIdx.x + st];
        }
        __syncthreads();
    }
    if (threadIdx.x == 0) {
        const float invM = 1.f / (float)(BB * NN);
        float mean = rs[0] * invM;
        float var = rs2[0] * invM - mean * mean;
        g_mean[c] = mean;
        g_rstd[c] = rsqrtf(var + 1e-5f);
    }
}

// ---------------------------------------------------------------------------
// Final: out = x + relu(gamma * (t - mean) * rstd + beta)
// ---------------------------------------------------------------------------
__global__ __launch_bounds__(256) void final_kernel(
    const float* __restrict__ x, const float* __restrict__ gamma,
    const float* __restrict__ beta, float* __restrict__ out)
{
    size_t i = (size_t)blockIdx.x * 256 + threadIdx.x;
    int c = (int)((i >> 12) & 255);
    float t = g_t[i];
    float th = (t - g_mean[c]) * g_rstd[c];
    float r = fmaxf(0.f, gamma[c] * th + beta[c]);
    out[i] = x[i] + r;
}

// ---------------------------------------------------------------------------
extern "C" void kernel_launch(void* const* d_in, const int* in_sizes, int n_in,
                              void* d_out, int out_size)
{
    const float* x     = (const float*)d_in[0];
    const float* wq    = (const float*)d_in[1];
    const float* wv    = (const float*)d_in[2];
    const float* bv    = (const float*)d_in[3];
    const float* wt    = (const float*)d_in[4];
    const float* bt    = (const float*)d_in[5];
    const float* gamma = (const float*)d_in[6];
    const float* beta  = (const float*)d_in[7];
    float* out = (float*)d_out;

    void* p;
    cudaGetSymbolAddress(&p, g_v);  float* vp  = (float*)p;
    cudaGetSymbolAddress(&p, g_xd); float* xdp = (float*)p;
    cudaGetSymbolAddress(&p, g_t);  float* tp  = (float*)p;

    const int xa_smem = XA_SMEM_WORDS * 4;  // 77312 B
    cudaFuncSetAttribute(xa_kernel,
                         cudaFuncAttributeMaxDynamicSharedMemorySize, xa_smem);

    // q projection (weight-tied Q/K) -> fp16 [B,N,64]
    convq_kernel<<<dim3(NN / 64, 1, BB), 256>>>(wq, x);
    // v projection: [B,C,N] fp32
    conv1x1_kernel<true><<<dim3(NN / 64, CC / 64, BB), 256>>>(wv, x, bv, vp, CC);
    // fused energy + row softmax stats (no E materialization)
    pass1_kernel<<<dim3(NN / 128, BB), 256>>>();
    // fused E-recompute + softmax + double-norm + V*P -> x_d (one wave)
    xa_kernel<<<dim3(NN / 128, BB), 512, xa_smem>>>(x);
    // trans conv: t = wt @ x_d + bt
    conv1x1_kernel<true><<<dim3(NN / 64, CC / 64, BB), 256>>>(wt, xdp, bt, tp, CC);
    // BN stats + final fused relu/residual
    bnstats_kernel<<<CC, 256>>>();
    final_kernel<<<(BB * CC * NN) / 256, 256>>>(x, gamma, beta, out);
}

// round 6
// speedup vs baseline: 3.4987x; 1.2500x over previous
#include <cuda_runtime.h>
#include <cuda_fp16.h>
#include <cstdint>

#define BB 4
#define CC 256
#define NN 4096
#define DD 64

// Scratch (device globals: allocation-free kernel_launch)
__device__ unsigned g_qh[(size_t)BB * NN * 32];   // 2 MB  q fp16 pairs [b][n][k/2]
__device__ float g_v[(size_t)BB * CC * NN];       // 16 MB [b][c][n]
__device__ float g_rowmax[BB * NN];
__device__ float g_rowinv[BB * NN];
__device__ float g_xd[(size_t)BB * CC * NN];      // 16 MB
__device__ float g_t[(size_t)BB * CC * NN];       // 16 MB
__device__ float g_mean[CC];
__device__ float g_rstd[CC];

// ---------------------------------------------------------------------------
// helpers
// ---------------------------------------------------------------------------
__device__ __forceinline__ void mma_fp16(
    float* c,
    unsigned a0, unsigned a1, unsigned a2, unsigned a3,
    unsigned b0, unsigned b1)
{
    asm volatile(
        "mma.sync.aligned.m16n8k16.row.col.f32.f16.f16.f32 "
        "{%0,%1,%2,%3}, {%4,%5,%6,%7}, {%8,%9}, {%0,%1,%2,%3};\n"
        : "+f"(c[0]), "+f"(c[1]), "+f"(c[2]), "+f"(c[3])
        : "r"(a0), "r"(a1), "r"(a2), "r"(a3), "r"(b0), "r"(b1));
}

// ---------------------------------------------------------------------------
// 1x1 conv: out[o,n] = sum_c W[o,c]*x[b,c,n] (+bias). 64x64 tile, BK=16.
// ---------------------------------------------------------------------------
template <bool HAS_BIAS>
__global__ __launch_bounds__(256) void conv1x1_kernel(
    const float* __restrict__ W, const float* __restrict__ x,
    const float* __restrict__ bias, float* __restrict__ out, int O)
{
    const int b  = blockIdx.z;
    const int o0 = blockIdx.y * 64;
    const int n0 = blockIdx.x * 64;
    const float* xb = x + (size_t)b * CC * NN;

    __shared__ float sW[16][64];      // [k][o]
    __shared__ float sX[16][65];      // [k][n]

    const int tid = threadIdx.x;
    const int tx = tid & 15, ty = tid >> 4;

    float acc[4][4] = {};

    for (int c0 = 0; c0 < CC; c0 += 16) {
#pragma unroll
        for (int r = 0; r < 4; r++) {
            int idx = tid + r * 256;
            int o = idx >> 4, k = idx & 15;
            sW[k][o] = W[(size_t)(o0 + o) * CC + c0 + k];
        }
#pragma unroll
        for (int r = 0; r < 4; r++) {
            int idx = tid + r * 256;
            int k = idx >> 6, n = idx & 63;
            sX[k][n] = xb[(size_t)(c0 + k) * NN + n0 + n];
        }
        __syncthreads();
#pragma unroll
        for (int k = 0; k < 16; k++) {
            float a[4], bv2[4];
#pragma unroll
            for (int i = 0; i < 4; i++) a[i] = sW[k][ty * 4 + i];
#pragma unroll
            for (int j = 0; j < 4; j++) bv2[j] = sX[k][tx * 4 + j];
#pragma unroll
            for (int i = 0; i < 4; i++)
#pragma unroll
                for (int j = 0; j < 4; j++) acc[i][j] += a[i] * bv2[j];
        }
        __syncthreads();
    }

#pragma unroll
    for (int i = 0; i < 4; i++) {
        int o = o0 + ty * 4 + i;
        float bi = HAS_BIAS ? bias[o] : 0.f;
        float4 v4;
        v4.x = acc[i][0] + bi; v4.y = acc[i][1] + bi;
        v4.z = acc[i][2] + bi; v4.w = acc[i][3] + bi;
        *reinterpret_cast<float4*>(
            &out[((size_t)b * O + o) * NN + n0 + tx * 4]) = v4;
    }
}

// ---------------------------------------------------------------------------
// q projection writing fp16 pairs: g_qh[(b*N+n)*32 + o/2]
// ---------------------------------------------------------------------------
__global__ __launch_bounds__(256) void convq_kernel(
    const float* __restrict__ W, const float* __restrict__ x)
{
    const int b  = blockIdx.z;
    const int n0 = blockIdx.x * 64;
    const float* xb = x + (size_t)b * CC * NN;

    __shared__ float sW[16][64];
    __shared__ float sX[16][65];

    const int tid = threadIdx.x;
    const int tx = tid & 15, ty = tid >> 4;

    float acc[4][4] = {};

    for (int c0 = 0; c0 < CC; c0 += 16) {
#pragma unroll
        for (int r = 0; r < 4; r++) {
            int idx = tid + r * 256;
            int o = idx >> 4, k = idx & 15;
            sW[k][o] = W[(size_t)o * CC + c0 + k];
        }
#pragma unroll
        for (int r = 0; r < 4; r++) {
            int idx = tid + r * 256;
            int k = idx >> 6, n = idx & 63;
            sX[k][n] = xb[(size_t)(c0 + k) * NN + n0 + n];
        }
        __syncthreads();
#pragma unroll
        for (int k = 0; k < 16; k++) {
            float a[4], bv2[4];
#pragma unroll
            for (int i = 0; i < 4; i++) a[i] = sW[k][ty * 4 + i];
#pragma unroll
            for (int j = 0; j < 4; j++) bv2[j] = sX[k][tx * 4 + j];
#pragma unroll
            for (int i = 0; i < 4; i++)
#pragma unroll
                for (int j = 0; j < 4; j++) acc[i][j] += a[i] * bv2[j];
        }
        __syncthreads();
    }

#pragma unroll
    for (int j = 0; j < 4; j++) {
        int n = n0 + tx * 4 + j;
        __half2 h0 = __floats2half2_rn(acc[0][j], acc[1][j]);
        __half2 h1 = __floats2half2_rn(acc[2][j], acc[3][j]);
        size_t base = ((size_t)b * NN + n) * 32 + ty * 2;
        g_qh[base]     = *reinterpret_cast<unsigned*>(&h0);
        g_qh[base + 1] = *reinterpret_cast<unsigned*>(&h1);
    }
}

// ---------------------------------------------------------------------------
// pass1: fused energy + row softmax stats (flash pass). 128-row n-tile per
// block; loops m in 128-chunks, E tile in regs (fp16 mma), online max/sumexp.
// ---------------------------------------------------------------------------
__global__ __launch_bounds__(256) void pass1_kernel()
{
    const int b  = blockIdx.y;
    const int n0 = blockIdx.x * 128;
    const unsigned* qh = g_qh + (size_t)b * NN * 32;

    __shared__ unsigned sA[128][36];     // q_n fp16 pairs [row][k/2]
    __shared__ unsigned sB[128][36];     // q_m chunk
    __shared__ float2 sMrg[4][128];

    const int tid = threadIdx.x;
    const int lane = tid & 31, wid = tid >> 5;
    const int wm = wid >> 2, wn = wid & 3;
    const int gp = lane >> 2, tg = lane & 3;

#pragma unroll
    for (int r = 0; r < 16; r++) {
        int idx = tid + r * 256;
        int row = idx >> 5, kp = idx & 31;
        sA[row][kp] = qh[(size_t)(n0 + row) * 32 + kp];
    }

    float rmax[8], rsum[8];
#pragma unroll
    for (int i = 0; i < 8; i++) { rmax[i] = -1e30f; rsum[i] = 0.f; }

    for (int m0 = 0; m0 < NN; m0 += 128) {
        __syncthreads();
#pragma unroll
        for (int r = 0; r < 16; r++) {
            int idx = tid + r * 256;
            int row = idx >> 5, kp = idx & 31;
            sB[row][kp] = qh[(size_t)(m0 + row) * 32 + kp];
        }
        __syncthreads();

        float acc[4][4][4] = {};
#pragma unroll
        for (int ks = 0; ks < 4; ks++) {
            int kp0 = ks * 8;
            unsigned a[4][4], bf[4][2];
#pragma unroll
            for (int i = 0; i < 4; i++) {
                int row = wm * 64 + i * 16 + gp;
                a[i][0] = sA[row][kp0 + tg];
                a[i][1] = sA[row + 8][kp0 + tg];
                a[i][2] = sA[row][kp0 + 4 + tg];
                a[i][3] = sA[row + 8][kp0 + 4 + tg];
            }
#pragma unroll
            for (int j = 0; j < 4; j++) {
                int col = wn * 32 + j * 8 + gp;
                bf[j][0] = sB[col][kp0 + tg];
                bf[j][1] = sB[col][kp0 + 4 + tg];
            }
#pragma unroll
            for (int i = 0; i < 4; i++)
#pragma unroll
                for (int j = 0; j < 4; j++)
                    mma_fp16(acc[i][j], a[i][0], a[i][1], a[i][2], a[i][3],
                             bf[j][0], bf[j][1]);
        }

#pragma unroll
        for (int i = 0; i < 4; i++) {
            float m0v = -1e30f, m1v = -1e30f;
#pragma unroll
            for (int j = 0; j < 4; j++) {
                m0v = fmaxf(m0v, fmaxf(acc[i][j][0], acc[i][j][1]));
                m1v = fmaxf(m1v, fmaxf(acc[i][j][2], acc[i][j][3]));
            }
            m0v = fmaxf(m0v, __shfl_xor_sync(0xffffffffu, m0v, 1));
            m0v = fmaxf(m0v, __shfl_xor_sync(0xffffffffu, m0v, 2));
            m1v = fmaxf(m1v, __shfl_xor_sync(0xffffffffu, m1v, 1));
            m1v = fmaxf(m1v, __shfl_xor_sync(0xffffffffu, m1v, 2));
            float nm0 = fmaxf(rmax[2 * i],     m0v);
            float nm1 = fmaxf(rmax[2 * i + 1], m1v);
            float s0 = 0.f, s1 = 0.f;
#pragma unroll
            for (int j = 0; j < 4; j++) {
                s0 += __expf(acc[i][j][0] - nm0) + __expf(acc[i][j][1] - nm0);
                s1 += __expf(acc[i][j][2] - nm1) + __expf(acc[i][j][3] - nm1);
            }
            s0 += __shfl_xor_sync(0xffffffffu, s0, 1);
            s0 += __shfl_xor_sync(0xffffffffu, s0, 2);
            s1 += __shfl_xor_sync(0xffffffffu, s1, 1);
            s1 += __shfl_xor_sync(0xffffffffu, s1, 2);
            rsum[2 * i]     = rsum[2 * i]     * __expf(rmax[2 * i]     - nm0) + s0;
            rsum[2 * i + 1] = rsum[2 * i + 1] * __expf(rmax[2 * i + 1] - nm1) + s1;
            rmax[2 * i]     = nm0;
            rmax[2 * i + 1] = nm1;
        }
    }

    if (tg == 0) {
#pragma unroll
        for (int i = 0; i < 4; i++) {
            int row = wm * 64 + i * 16 + gp;
            sMrg[wn][row]     = make_float2(rmax[2 * i],     rsum[2 * i]);
            sMrg[wn][row + 8] = make_float2(rmax[2 * i + 1], rsum[2 * i + 1]);
        }
    }
    __syncthreads();
    if (tid < 128) {
        float2 v0 = sMrg[0][tid], v1 = sMrg[1][tid];
        float2 v2 = sMrg[2][tid], v3 = sMrg[3][tid];
        float M = fmaxf(fmaxf(v0.x, v1.x), fmaxf(v2.x, v3.x));
        float S = v0.y * __expf(v0.x - M) + v1.y * __expf(v1.x - M)
                + v2.y * __expf(v2.x - M) + v3.y * __expf(v3.x - M);
        g_rowmax[b * NN + n0 + tid] = M;
        g_rowinv[b * NN + n0 + tid] = 1.f / S;
    }
}

// ---------------------------------------------------------------------------
// xa: fused E-recompute + P + colsum + V*P, all-fp16 mma. 512 threads,
// CTA = [256c x 128m], NT=64 n-chunks. grid 32x4 = 128 CTAs (one wave).
// smem (unsigned words): sVh 256x36 | sQm 128x36 | sQn 64x36 | sPh 128x72h | sCol
// ---------------------------------------------------------------------------
#define XA_W_SVH 0
#define XA_W_SQM (256 * 36)
#define XA_W_SQN (XA_W_SQM + 128 * 36)
#define XA_W_SPH (XA_W_SQN + 64 * 36)
#define XA_W_COL (XA_W_SPH + 128 * 36)
#define XA_SMEM_WORDS (XA_W_COL + 128)

__global__ __launch_bounds__(512, 1) void xa_kernel(const float* __restrict__ x)
{
    const int b  = blockIdx.y;
    const int m0 = blockIdx.x * 128;
    const float* vb  = g_v + (size_t)b * CC * NN;
    const float* rmx = g_rowmax + b * NN;
    const float* rin = g_rowinv + b * NN;
    const unsigned* qh = g_qh + (size_t)b * NN * 32;

    extern __shared__ unsigned shm[];
    unsigned (*sVh)[36] = reinterpret_cast<unsigned(*)[36]>(shm + XA_W_SVH); // V pairs [c][np]
    unsigned (*sQm)[36] = reinterpret_cast<unsigned(*)[36]>(shm + XA_W_SQM);
    unsigned (*sQn)[36] = reinterpret_cast<unsigned(*)[36]>(shm + XA_W_SQN);
    __half  (*sPh)[72]  = reinterpret_cast<__half(*)[72]>(shm + XA_W_SPH);   // P [m][n]
    float* sCol = reinterpret_cast<float*>(shm + XA_W_COL);

    const int tid = threadIdx.x;
    const int lane = tid & 31, wid = tid >> 5;
    const int gp = lane >> 2, tg = lane & 3;
    const int nh = wid & 3, mh = wid >> 2;       // mma1 roles (4x4)
    const int wm = wid >> 2, wn = wid & 3;       // mma2 roles

    // q_m tile (constant for the block)
#pragma unroll
    for (int r = 0; r < 8; r++) {
        int idx = tid + r * 512;
        int row = idx >> 5, kp = idx & 31;
        sQm[row][kp] = qh[(size_t)(m0 + row) * 32 + kp];
    }
    if (tid < 128) sCol[tid] = 0.f;

    float acc[4][4][4] = {};

    for (int n0 = 0; n0 < NN; n0 += 64) {
        __syncthreads();
#pragma unroll
        for (int r = 0; r < 4; r++) {
            int idx = tid + r * 512;
            int row = idx >> 5, kp = idx & 31;
            sQn[row][kp] = qh[(size_t)(n0 + row) * 32 + kp];
        }
#pragma unroll
        for (int r = 0; r < 16; r++) {
            int idx = tid + r * 512;
            int c = idx >> 5, np = idx & 31;
            float2 v2 = *reinterpret_cast<const float2*>(&vb[(size_t)c * NN + n0 + 2 * np]);
            __half2 h = __floats2half2_rn(v2.x, v2.y);
            sVh[c][np] = *reinterpret_cast<unsigned*>(&h);
        }
        __syncthreads();

        // mma1: E chunk [64n x 128m]; warp rows nh*16+gp(+8), cols mh*32+j*8
        float e[4][4] = {};
#pragma unroll
        for (int ks = 0; ks < 4; ks++) {
            int kp0 = ks * 8;
            unsigned a0 = sQn[nh * 16 + gp][kp0 + tg];
            unsigned a1 = sQn[nh * 16 + gp + 8][kp0 + tg];
            unsigned a2 = sQn[nh * 16 + gp][kp0 + 4 + tg];
            unsigned a3 = sQn[nh * 16 + gp + 8][kp0 + 4 + tg];
#pragma unroll
            for (int j = 0; j < 4; j++) {
                int col = mh * 32 + j * 8 + gp;
                mma_fp16(e[j], a0, a1, a2, a3,
                         sQm[col][kp0 + tg], sQm[col][kp0 + 4 + tg]);
            }
        }

        int r0 = n0 + nh * 16 + gp;
        float mx0 = __ldg(&rmx[r0]),     iv0 = __ldg(&rin[r0]);
        float mx1 = __ldg(&rmx[r0 + 8]), iv1 = __ldg(&rin[r0 + 8]);
        int nr0 = nh * 16 + gp, nr1 = nr0 + 8;
#pragma unroll
        for (int j = 0; j < 4; j++) {
            int cb = mh * 32 + j * 8 + 2 * tg;
            sPh[cb][nr0]     = __float2half(__expf(e[j][0] - mx0) * iv0);
            sPh[cb + 1][nr0] = __float2half(__expf(e[j][1] - mx0) * iv0);
            sPh[cb][nr1]     = __float2half(__expf(e[j][2] - mx1) * iv1);
            sPh[cb + 1][nr1] = __float2half(__expf(e[j][3] - mx1) * iv1);
        }
        __syncthreads();

        if (tid < 128) {
            float cs = 0.f;
            const __half2* prow = reinterpret_cast<const __half2*>(sPh[tid]);
#pragma unroll
            for (int k = 0; k < 32; k++) {
                float2 f = __half22float2(prow[k]);
                cs += f.x + f.y;
            }
            sCol[tid] += cs;
        }

        // mma2: acc[c,m] += V*P, warp tile 64c x 32m, k=64 (4 k16 steps)
#pragma unroll
        for (int ks = 0; ks < 4; ks++) {
            int kp0 = ks * 8;
            unsigned a[4][4], bf[4][2];
#pragma unroll
            for (int i = 0; i < 4; i++) {
                int row = wm * 64 + i * 16 + gp;
                a[i][0] = sVh[row][kp0 + tg];
                a[i][1] = sVh[row + 8][kp0 + tg];
                a[i][2] = sVh[row][kp0 + 4 + tg];
                a[i][3] = sVh[row + 8][kp0 + 4 + tg];
            }
#pragma unroll
            for (int j = 0; j < 4; j++) {
                int col = wn * 32 + j * 8 + gp;
                bf[j][0] = *reinterpret_cast<const unsigned*>(&sPh[col][2 * kp0 + 2 * tg]);
                bf[j][1] = *reinterpret_cast<const unsigned*>(&sPh[col][2 * kp0 + 8 + 2 * tg]);
            }
#pragma unroll
            for (int i = 0; i < 4; i++)
#pragma unroll
                for (int j = 0; j < 4; j++)
                    mma_fp16(acc[i][j], a[i][0], a[i][1], a[i][2], a[i][3],
                             bf[j][0], bf[j][1]);
        }
    }
    __syncthreads();   // sCol final

#pragma unroll
    for (int j = 0; j < 4; j++) {
        int colr = wn * 32 + j * 8 + 2 * tg;
        float i0 = 1.f / (1e-9f + sCol[colr]);
        float i1 = 1.f / (1e-9f + sCol[colr + 1]);
#pragma unroll
        for (int i = 0; i < 4; i++) {
            int c = wm * 64 + i * 16 + gp;
            size_t base = ((size_t)b * CC + c) * NN + m0 + colr;
            float2 xv = *reinterpret_cast<const float2*>(&x[base]);
            float2 o;
            o.x = xv.x - acc[i][j][0] * i0;
            o.y = xv.y - acc[i][j][1] * i1;
            *reinterpret_cast<float2*>(&g_xd[base]) = o;
            size_t base2 = base + (size_t)8 * NN;
            float2 xv2 = *reinterpret_cast<const float2*>(&x[base2]);
            float2 o2;
            o2.x = xv2.x - acc[i][j][2] * i0;
            o2.y = xv2.y - acc[i][j][3] * i1;
            *reinterpret_cast<float2*>(&g_xd[base2]) = o2;
        }
    }
}

// ---------------------------------------------------------------------------
// BN stats: per channel c, mean/var over (B, N).
// ---------------------------------------------------------------------------
__global__ __launch_bounds__(256) void bnstats_kernel()
{
    const int c = blockIdx.x;
    float s = 0.f, s2 = 0.f;
    for (int i = threadIdx.x; i < BB * NN; i += 256) {
        int b = i >> 12;
        int n = i & (NN - 1);
        float v = g_t[((size_t)b * CC + c) * NN + n];
        s += v;
        s2 += v * v;
    }
    __shared__ float rs[256], rs2[256];
    rs[threadIdx.x] = s;
    rs2[threadIdx.x] = s2;
    __syncthreads();
    for (int st = 128; st; st >>= 1) {
        if (threadIdx.x < st) {
            rs[threadIdx.x]  += rs[threadIdx.x + st];
            rs2[threadIdx.x] += rs2[threadIdx.x + st];
        }
        __syncthreads();
    }
    if (threadIdx.x == 0) {
        const float invM = 1.f / (float)(BB * NN);
        float mean = rs[0] * invM;
        float var = rs2[0] * invM - mean * mean;
        g_mean[c] = mean;
        g_rstd[c] = rsqrtf(var + 1e-5f);
    }
}

// ---------------------------------------------------------------------------
// Final: out = x + relu(gamma * (t - mean) * rstd + beta)
// ---------------------------------------------------------------------------
__global__ __launch_bounds__(256) void final_kernel(
    const float* __restrict__ x, const float* __restrict__ gamma,
    const float* __restrict__ beta, float* __restrict__ out)
{
    size_t i = (size_t)blockIdx.x * 256 + threadIdx.x;
    int c = (int)((i >> 12) & 255);
    float t = g_t[i];
    float th = (t - g_mean[c]) * g_rstd[c];
    float r = fmaxf(0.f, gamma[c] * th + beta[c]);
    out[i] = x[i] + r;
}

// ---------------------------------------------------------------------------
extern "C" void kernel_launch(void* const* d_in, const int* in_sizes, int n_in,
                              void* d_out, int out_size)
{
    const float* x     = (const float*)d_in[0];
    const float* wq    = (const float*)d_in[1];
    const float* wv    = (const float*)d_in[2];
    const float* bv    = (const float*)d_in[3];
    const float* wt    = (const float*)d_in[4];
    const float* bt    = (const float*)d_in[5];
    const float* gamma = (const float*)d_in[6];
    const float* beta  = (const float*)d_in[7];
    float* out = (float*)d_out;

    void* p;
    cudaGetSymbolAddress(&p, g_v);  float* vp  = (float*)p;
    cudaGetSymbolAddress(&p, g_xd); float* xdp = (float*)p;
    cudaGetSymbolAddress(&p, g_t);  float* tp  = (float*)p;

    const int xa_smem = XA_SMEM_WORDS * 4;
    cudaFuncSetAttribute(xa_kernel,
                         cudaFuncAttributeMaxDynamicSharedMemorySize, xa_smem);

    // q projection (weight-tied Q/K) -> fp16 [B,N,64]
    convq_kernel<<<dim3(NN / 64, 1, BB), 256>>>(wq, x);
    // v projection: [B,C,N] fp32
    conv1x1_kernel<true><<<dim3(NN / 64, CC / 64, BB), 256>>>(wv, x, bv, vp, CC);
    // fused energy + row softmax stats (no E materialization)
    pass1_kernel<<<dim3(NN / 128, BB), 256>>>();
    // fused E-recompute + softmax + double-norm + V*P -> x_d (one wave, fp16)
    xa_kernel<<<dim3(NN / 128, BB), 512, xa_smem>>>(x);
    // trans conv: t = wt @ x_d + bt
    conv1x1_kernel<true><<<dim3(NN / 64, CC / 64, BB), 256>>>(wt, xdp, bt, tp, CC);
    // BN stats + final fused relu/residual
    bnstats_kernel<<<CC, 256>>>();
    final_kernel<<<(BB * CC * NN) / 256, 256>>>(x, gamma, beta, out);
}

// round 7
// speedup vs baseline: 3.7298x; 1.0660x over previous
#include <cuda_runtime.h>
#include <cuda_fp16.h>
#include <cstdint>

#define BB 4
#define CC 256
#define NN 4096
#define DD 64

// Scratch (device globals: allocation-free kernel_launch)
__device__ unsigned g_qh[(size_t)BB * NN * 32];        // 2 MB  q fp16 pairs [b][n][k/2]
__device__ unsigned g_vh[(size_t)BB * CC * (NN / 2)];  // 8 MB  v fp16 pairs [b][c][n/2]
__device__ float g_rowmax[BB * NN];
__device__ float g_rowinv[BB * NN];
__device__ float g_xd[(size_t)BB * CC * NN];           // 16 MB
__device__ float g_t[(size_t)BB * CC * NN];            // 16 MB
__device__ float g_mean[CC];
__device__ float g_rstd[CC];

// ---------------------------------------------------------------------------
// helpers
// ---------------------------------------------------------------------------
__device__ __forceinline__ void mma_fp16(
    float* c,
    unsigned a0, unsigned a1, unsigned a2, unsigned a3,
    unsigned b0, unsigned b1)
{
    asm volatile(
        "mma.sync.aligned.m16n8k16.row.col.f32.f16.f16.f32 "
        "{%0,%1,%2,%3}, {%4,%5,%6,%7}, {%8,%9}, {%0,%1,%2,%3};\n"
        : "+f"(c[0]), "+f"(c[1]), "+f"(c[2]), "+f"(c[3])
        : "r"(a0), "r"(a1), "r"(a2), "r"(a3), "r"(b0), "r"(b1));
}

__device__ __forceinline__ void cpa16(unsigned sdst, const void* gsrc)
{
    asm volatile("cp.async.cg.shared.global [%0], [%1], 16;\n"
                 :: "r"(sdst), "l"(gsrc));
}
__device__ __forceinline__ void cpa_commit()
{
    asm volatile("cp.async.commit_group;\n");
}
__device__ __forceinline__ void cpa_wait0()
{
    asm volatile("cp.async.wait_group 0;\n");
}

// ---------------------------------------------------------------------------
// 1x1 conv (fp32 out): out[o,n] = sum_c W[o,c]*x[b,c,n] (+bias). 64x64 tile.
// ---------------------------------------------------------------------------
template <bool HAS_BIAS>
__global__ __launch_bounds__(256) void conv1x1_kernel(
    const float* __restrict__ W, const float* __restrict__ x,
    const float* __restrict__ bias, float* __restrict__ out, int O)
{
    const int b  = blockIdx.z;
    const int o0 = blockIdx.y * 64;
    const int n0 = blockIdx.x * 64;
    const float* xb = x + (size_t)b * CC * NN;

    __shared__ float sW[16][64];      // [k][o]
    __shared__ float sX[16][65];      // [k][n]

    const int tid = threadIdx.x;
    const int tx = tid & 15, ty = tid >> 4;

    float acc[4][4] = {};

    for (int c0 = 0; c0 < CC; c0 += 16) {
#pragma unroll
        for (int r = 0; r < 4; r++) {
            int idx = tid + r * 256;
            int o = idx >> 4, k = idx & 15;
            sW[k][o] = W[(size_t)(o0 + o) * CC + c0 + k];
        }
#pragma unroll
        for (int r = 0; r < 4; r++) {
            int idx = tid + r * 256;
            int k = idx >> 6, n = idx & 63;
            sX[k][n] = xb[(size_t)(c0 + k) * NN + n0 + n];
        }
        __syncthreads();
#pragma unroll
        for (int k = 0; k < 16; k++) {
            float a[4], bv2[4];
#pragma unroll
            for (int i = 0; i < 4; i++) a[i] = sW[k][ty * 4 + i];
#pragma unroll
            for (int j = 0; j < 4; j++) bv2[j] = sX[k][tx * 4 + j];
#pragma unroll
            for (int i = 0; i < 4; i++)
#pragma unroll
                for (int j = 0; j < 4; j++) acc[i][j] += a[i] * bv2[j];
        }
        __syncthreads();
    }

#pragma unroll
    for (int i = 0; i < 4; i++) {
        int o = o0 + ty * 4 + i;
        float bi = HAS_BIAS ? bias[o] : 0.f;
        float4 v4;
        v4.x = acc[i][0] + bi; v4.y = acc[i][1] + bi;
        v4.z = acc[i][2] + bi; v4.w = acc[i][3] + bi;
        *reinterpret_cast<float4*>(
            &out[((size_t)b * O + o) * NN + n0 + tx * 4]) = v4;
    }
}

// ---------------------------------------------------------------------------
// q projection writing fp16 pairs: g_qh[(b*N+n)*32 + o/2]
// ---------------------------------------------------------------------------
__global__ __launch_bounds__(256) void convq_kernel(
    const float* __restrict__ W, const float* __restrict__ x)
{
    const int b  = blockIdx.z;
    const int n0 = blockIdx.x * 64;
    const float* xb = x + (size_t)b * CC * NN;

    __shared__ float sW[16][64];
    __shared__ float sX[16][65];

    const int tid = threadIdx.x;
    const int tx = tid & 15, ty = tid >> 4;

    float acc[4][4] = {};

    for (int c0 = 0; c0 < CC; c0 += 16) {
#pragma unroll
        for (int r = 0; r < 4; r++) {
            int idx = tid + r * 256;
            int o = idx >> 4, k = idx & 15;
            sW[k][o] = W[(size_t)o * CC + c0 + k];
        }
#pragma unroll
        for (int r = 0; r < 4; r++) {
            int idx = tid + r * 256;
            int k = idx >> 6, n = idx & 63;
            sX[k][n] = xb[(size_t)(c0 + k) * NN + n0 + n];
        }
        __syncthreads();
#pragma unroll
        for (int k = 0; k < 16; k++) {
            float a[4], bv2[4];
#pragma unroll
            for (int i = 0; i < 4; i++) a[i] = sW[k][ty * 4 + i];
#pragma unroll
            for (int j = 0; j < 4; j++) bv2[j] = sX[k][tx * 4 + j];
#pragma unroll
            for (int i = 0; i < 4; i++)
#pragma unroll
                for (int j = 0; j < 4; j++) acc[i][j] += a[i] * bv2[j];
        }
        __syncthreads();
    }

#pragma unroll
    for (int j = 0; j < 4; j++) {
        int n = n0 + tx * 4 + j;
        __half2 h0 = __floats2half2_rn(acc[0][j], acc[1][j]);
        __half2 h1 = __floats2half2_rn(acc[2][j], acc[3][j]);
        size_t base = ((size_t)b * NN + n) * 32 + ty * 2;
        g_qh[base]     = *reinterpret_cast<unsigned*>(&h0);
        g_qh[base + 1] = *reinterpret_cast<unsigned*>(&h1);
    }
}

// ---------------------------------------------------------------------------
// v projection writing fp16 pairs along n: g_vh[(b*C+o)*(N/2) + n/2]
// ---------------------------------------------------------------------------
__global__ __launch_bounds__(256) void convv_kernel(
    const float* __restrict__ W, const float* __restrict__ x,
    const float* __restrict__ bias)
{
    const int b  = blockIdx.z;
    const int o0 = blockIdx.y * 64;
    const int n0 = blockIdx.x * 64;
    const float* xb = x + (size_t)b * CC * NN;

    __shared__ float sW[16][64];
    __shared__ float sX[16][65];

    const int tid = threadIdx.x;
    const int tx = tid & 15, ty = tid >> 4;

    float acc[4][4] = {};

    for (int c0 = 0; c0 < CC; c0 += 16) {
#pragma unroll
        for (int r = 0; r < 4; r++) {
            int idx = tid + r * 256;
            int o = idx >> 4, k = idx & 15;
            sW[k][o] = W[(size_t)(o0 + o) * CC + c0 + k];
        }
#pragma unroll
        for (int r = 0; r < 4; r++) {
            int idx = tid + r * 256;
            int k = idx >> 6, n = idx & 63;
            sX[k][n] = xb[(size_t)(c0 + k) * NN + n0 + n];
        }
        __syncthreads();
#pragma unroll
        for (int k = 0; k < 16; k++) {
            float a[4], bv2[4];
#pragma unroll
            for (int i = 0; i < 4; i++) a[i] = sW[k][ty * 4 + i];
#pragma unroll
            for (int j = 0; j < 4; j++) bv2[j] = sX[k][tx * 4 + j];
#pragma unroll
            for (int i = 0; i < 4; i++)
#pragma unroll
                for (int j = 0; j < 4; j++) acc[i][j] += a[i] * bv2[j];
        }
        __syncthreads();
    }

#pragma unroll
    for (int i = 0; i < 4; i++) {
        int o = o0 + ty * 4 + i;
        float bi = bias[o];
        __half2 h0 = __floats2half2_rn(acc[i][0] + bi, acc[i][1] + bi);
        __half2 h1 = __floats2half2_rn(acc[i][2] + bi, acc[i][3] + bi);
        size_t base = ((size_t)b * CC + o) * (NN / 2) + (n0 + tx * 4) / 2;
        g_vh[base]     = *reinterpret_cast<unsigned*>(&h0);
        g_vh[base + 1] = *reinterpret_cast<unsigned*>(&h1);
    }
}

// ---------------------------------------------------------------------------
// pass1: fused energy + row softmax stats (flash pass).
// ---------------------------------------------------------------------------
__global__ __launch_bounds__(256) void pass1_kernel()
{
    const int b  = blockIdx.y;
    const int n0 = blockIdx.x * 128;
    const unsigned* qh = g_qh + (size_t)b * NN * 32;

    __shared__ unsigned sA[128][36];     // q_n fp16 pairs [row][k/2]
    __shared__ unsigned sB[128][36];     // q_m chunk
    __shared__ float2 sMrg[4][128];

    const int tid = threadIdx.x;
    const int lane = tid & 31, wid = tid >> 5;
    const int wm = wid >> 2, wn = wid & 3;
    const int gp = lane >> 2, tg = lane & 3;

#pragma unroll
    for (int r = 0; r < 16; r++) {
        int idx = tid + r * 256;
        int row = idx >> 5, kp = idx & 31;
        sA[row][kp] = qh[(size_t)(n0 + row) * 32 + kp];
    }

    float rmax[8], rsum[8];
#pragma unroll
    for (int i = 0; i < 8; i++) { rmax[i] = -1e30f; rsum[i] = 0.f; }

    for (int m0 = 0; m0 < NN; m0 += 128) {
        __syncthreads();
#pragma unroll
        for (int r = 0; r < 16; r++) {
            int idx = tid + r * 256;
            int row = idx >> 5, kp = idx & 31;
            sB[row][kp] = qh[(size_t)(m0 + row) * 32 + kp];
        }
        __syncthreads();

        float acc[4][4][4] = {};
#pragma unroll
        for (int ks = 0; ks < 4; ks++) {
            int kp0 = ks * 8;
            unsigned a[4][4], bf[4][2];
#pragma unroll
            for (int i = 0; i < 4; i++) {
                int row = wm * 64 + i * 16 + gp;
                a[i][0] = sA[row][kp0 + tg];
                a[i][1] = sA[row + 8][kp0 + tg];
                a[i][2] = sA[row][kp0 + 4 + tg];
                a[i][3] = sA[row + 8][kp0 + 4 + tg];
            }
#pragma unroll
            for (int j = 0; j < 4; j++) {
                int col = wn * 32 + j * 8 + gp;
                bf[j][0] = sB[col][kp0 + tg];
                bf[j][1] = sB[col][kp0 + 4 + tg];
            }
#pragma unroll
            for (int i = 0; i < 4; i++)
#pragma unroll
                for (int j = 0; j < 4; j++)
                    mma_fp16(acc[i][j], a[i][0], a[i][1], a[i][2], a[i][3],
                             bf[j][0], bf[j][1]);
        }

#pragma unroll
        for (int i = 0; i < 4; i++) {
            float m0v = -1e30f, m1v = -1e30f;
#pragma unroll
            for (int j = 0; j < 4; j++) {
                m0v = fmaxf(m0v, fmaxf(acc[i][j][0], acc[i][j][1]));
                m1v = fmaxf(m1v, fmaxf(acc[i][j][2], acc[i][j][3]));
            }
            m0v = fmaxf(m0v, __shfl_xor_sync(0xffffffffu, m0v, 1));
            m0v = fmaxf(m0v, __shfl_xor_sync(0xffffffffu, m0v, 2));
            m1v = fmaxf(m1v, __shfl_xor_sync(0xffffffffu, m1v, 1));
            m1v = fmaxf(m1v, __shfl_xor_sync(0xffffffffu, m1v, 2));
            float nm0 = fmaxf(rmax[2 * i],     m0v);
            float nm1 = fmaxf(rmax[2 * i + 1], m1v);
            float s0 = 0.f, s1 = 0.f;
#pragma unroll
            for (int j = 0; j < 4; j++) {
                s0 += __expf(acc[i][j][0] - nm0) + __expf(acc[i][j][1] - nm0);
                s1 += __expf(acc[i][j][2] - nm1) + __expf(acc[i][j][3] - nm1);
            }
            s0 += __shfl_xor_sync(0xffffffffu, s0, 1);
            s0 += __shfl_xor_sync(0xffffffffu, s0, 2);
            s1 += __shfl_xor_sync(0xffffffffu, s1, 1);
            s1 += __shfl_xor_sync(0xffffffffu, s1, 2);
            rsum[2 * i]     = rsum[2 * i]     * __expf(rmax[2 * i]     - nm0) + s0;
            rsum[2 * i + 1] = rsum[2 * i + 1] * __expf(rmax[2 * i + 1] - nm1) + s1;
            rmax[2 * i]     = nm0;
            rmax[2 * i + 1] = nm1;
        }
    }

    if (tg == 0) {
#pragma unroll
        for (int i = 0; i < 4; i++) {
            int row = wm * 64 + i * 16 + gp;
            sMrg[wn][row]     = make_float2(rmax[2 * i],     rsum[2 * i]);
            sMrg[wn][row + 8] = make_float2(rmax[2 * i + 1], rsum[2 * i + 1]);
        }
    }
    __syncthreads();
    if (tid < 128) {
        float2 v0 = sMrg[0][tid], v1 = sMrg[1][tid];
        float2 v2 = sMrg[2][tid], v3 = sMrg[3][tid];
        float M = fmaxf(fmaxf(v0.x, v1.x), fmaxf(v2.x, v3.x));
        float S = v0.y * __expf(v0.x - M) + v1.y * __expf(v1.x - M)
                + v2.y * __expf(v2.x - M) + v3.y * __expf(v3.x - M);
        g_rowmax[b * NN + n0 + tid] = M;
        g_rowinv[b * NN + n0 + tid] = 1.f / S;
    }
}

// ---------------------------------------------------------------------------
// xa: fused E-recompute + P + colsum + V*P, all-fp16 mma, cp.async
// double-buffered pipeline. 512 threads, CTA = [256c x 128m], NT=64.
// smem words: sVh 2x256x36 | sQm 128x36 | sQn 2x64x36 | sPh 2x(128x36) | sCol
// ---------------------------------------------------------------------------
#define XA_W_SVH 0
#define XA_W_SQM (2 * 256 * 36)
#define XA_W_SQN (XA_W_SQM + 128 * 36)
#define XA_W_SPH (XA_W_SQN + 2 * 64 * 36)
#define XA_W_COL (XA_W_SPH + 2 * 128 * 36)
#define XA_SMEM_WORDS (XA_W_COL + 128)

__global__ __launch_bounds__(512, 1) void xa_kernel(const float* __restrict__ x)
{
    const int b  = blockIdx.y;
    const int m0 = blockIdx.x * 128;
    const unsigned* vbh = g_vh + (size_t)b * CC * (NN / 2);
    const float* rmx = g_rowmax + b * NN;
    const float* rin = g_rowinv + b * NN;
    const unsigned* qh = g_qh + (size_t)b * NN * 32;

    extern __shared__ unsigned shm[];
    unsigned (*sQm)[36] = reinterpret_cast<unsigned(*)[36]>(shm + XA_W_SQM);
    float* sCol = reinterpret_cast<float*>(shm + XA_W_COL);
    const unsigned sbase = (unsigned)__cvta_generic_to_shared(shm);

    const int tid = threadIdx.x;
    const int lane = tid & 31, wid = tid >> 5;
    const int gp = lane >> 2, tg = lane & 3;
    const int nh = wid & 3, mh = wid >> 2;       // mma1 roles (4x4)
    const int wm = wid >> 2, wn = wid & 3;       // mma2 roles

    // q_m tile (constant for the block)
#pragma unroll
    for (int r = 0; r < 8; r++) {
        int idx = tid + r * 512;
        int row = idx >> 5, kp = idx & 31;
        sQm[row][kp] = qh[(size_t)(m0 + row) * 32 + kp];
    }
    if (tid < 128) sCol[tid] = 0.f;

    // async load of chunk (V: 256x32 u32, Qn: 64x32 u32) into buffer buf
    auto issue_loads = [&](int chunk, int buf) {
        int np0 = chunk * 32;
#pragma unroll
        for (int t = 0; t < 4; t++) {
            int idx = tid + t * 512;
            int row = idx >> 3, seg = idx & 7;
            unsigned dst = sbase + (XA_W_SVH + buf * 256 * 36 + row * 36 + seg * 4) * 4;
            cpa16(dst, vbh + (size_t)row * (NN / 2) + np0 + seg * 4);
        }
        {
            int row = tid >> 3, seg = tid & 7;
            unsigned dst = sbase + (XA_W_SQN + buf * 64 * 36 + row * 36 + seg * 4) * 4;
            cpa16(dst, qh + (size_t)(chunk * 64 + row) * 32 + seg * 4);
        }
        cpa_commit();
    };

    issue_loads(0, 0);
    issue_loads(1, 1);
    cpa_wait0();
    __syncthreads();

    float acc[4][4][4] = {};

    for (int i = 0; i < 64; i++) {
        const int buf = i & 1;
        const int n0 = i * 64;
        unsigned (*sQnB)[36] = reinterpret_cast<unsigned(*)[36]>(shm + XA_W_SQN + buf * 64 * 36);
        unsigned (*sVhB)[36] = reinterpret_cast<unsigned(*)[36]>(shm + XA_W_SVH + buf * 256 * 36);
        __half  (*sPhB)[72] = reinterpret_cast<__half(*)[72]>(shm + XA_W_SPH + buf * 128 * 36);

        // mma1: E chunk [64n x 128m]; warp rows nh*16+gp(+8), cols mh*32+j*8
        float e[4][4] = {};
#pragma unroll
        for (int ks = 0; ks < 4; ks++) {
            int kp0 = ks * 8;
            unsigned a0 = sQnB[nh * 16 + gp][kp0 + tg];
            unsigned a1 = sQnB[nh * 16 + gp + 8][kp0 + tg];
            unsigned a2 = sQnB[nh * 16 + gp][kp0 + 4 + tg];
            unsigned a3 = sQnB[nh * 16 + gp + 8][kp0 + 4 + tg];
#pragma unroll
            for (int j = 0; j < 4; j++) {
                int col = mh * 32 + j * 8 + gp;
                mma_fp16(e[j], a0, a1, a2, a3,
                         sQm[col][kp0 + tg], sQm[col][kp0 + 4 + tg]);
            }
        }

        int r0 = n0 + nh * 16 + gp;
        float mx0 = __ldg(&rmx[r0]),     iv0 = __ldg(&rin[r0]);
        float mx1 = __ldg(&rmx[r0 + 8]), iv1 = __ldg(&rin[r0 + 8]);
        int nr0 = nh * 16 + gp, nr1 = nr0 + 8;
#pragma unroll
        for (int j = 0; j < 4; j++) {
            int cb = mh * 32 + j * 8 + 2 * tg;
            sPhB[cb][nr0]     = __float2half(__expf(e[j][0] - mx0) * iv0);
            sPhB[cb + 1][nr0] = __float2half(__expf(e[j][1] - mx0) * iv0);
            sPhB[cb][nr1]     = __float2half(__expf(e[j][2] - mx1) * iv1);
            sPhB[cb + 1][nr1] = __float2half(__expf(e[j][3] - mx1) * iv1);
        }
        __syncthreads();   // P[i] visible

        // colsum spread over all 512 threads (4 segs x 16 halves per m)
        {
            int m = tid & 127, seg = tid >> 7;
            const __half2* prow = reinterpret_cast<const __half2*>(sPhB[m]);
            float cs = 0.f;
#pragma unroll
            for (int k = 0; k < 8; k++) {
                float2 f = __half22float2(prow[seg * 8 + k]);
                cs += f.x + f.y;
            }
            atomicAdd(&sCol[m], cs);
        }

        // mma2: acc[c,m] += V*P, warp tile 64c x 32m, k=64 (4 k16 steps)
#pragma unroll
        for (int ks = 0; ks < 4; ks++) {
            int kp0 = ks * 8;
            unsigned a[4][4], bf[4][2];
#pragma unroll
            for (int ii = 0; ii < 4; ii++) {
                int row = wm * 64 + ii * 16 + gp;
                a[ii][0] = sVhB[row][kp0 + tg];
                a[ii][1] = sVhB[row + 8][kp0 + tg];
                a[ii][2] = sVhB[row][kp0 + 4 + tg];
                a[ii][3] = sVhB[row + 8][kp0 + 4 + tg];
            }
#pragma unroll
            for (int j = 0; j < 4; j++) {
                int col = wn * 32 + j * 8 + gp;
                bf[j][0] = *reinterpret_cast<const unsigned*>(&sPhB[col][2 * kp0 + 2 * tg]);
                bf[j][1] = *reinterpret_cast<const unsigned*>(&sPhB[col][2 * kp0 + 8 + 2 * tg]);
            }
#pragma unroll
            for (int ii = 0; ii < 4; ii++)
#pragma unroll
                for (int j = 0; j < 4; j++)
                    mma_fp16(acc[ii][j], a[ii][0], a[ii][1], a[ii][2], a[ii][3],
                             bf[j][0], bf[j][1]);
        }

        cpa_wait0();       // loads for chunk i+1 (issued last iter) complete
        __syncthreads();   // loads visible; all warps done with buffer buf
        if (i + 2 < 64)
            issue_loads(i + 2, buf);
    }

#pragma unroll
    for (int j = 0; j < 4; j++) {
        int colr = wn * 32 + j * 8 + 2 * tg;
        float i0 = 1.f / (1e-9f + sCol[colr]);
        float i1 = 1.f / (1e-9f + sCol[colr + 1]);
#pragma unroll
        for (int i = 0; i < 4; i++) {
            int c = wm * 64 + i * 16 + gp;
            size_t base = ((size_t)b * CC + c) * NN + m0 + colr;
            float2 xv = *reinterpret_cast<const float2*>(&x[base]);
            float2 o;
            o.x = xv.x - acc[i][j][0] * i0;
            o.y = xv.y - acc[i][j][1] * i1;
            *reinterpret_cast<float2*>(&g_xd[base]) = o;
            size_t base2 = base + (size_t)8 * NN;
            float2 xv2 = *reinterpret_cast<const float2*>(&x[base2]);
            float2 o2;
            o2.x = xv2.x - acc[i][j][2] * i0;
            o2.y = xv2.y - acc[i][j][3] * i1;
            *reinterpret_cast<float2*>(&g_xd[base2]) = o2;
        }
    }
}

// ---------------------------------------------------------------------------
// BN stats: per channel c, mean/var over (B, N).
// ---------------------------------------------------------------------------
__global__ __launch_bounds__(256) void bnstats_kernel()
{
    const int c = blockIdx.x;
    float s = 0.f, s2 = 0.f;
    for (int i = threadIdx.x; i < BB * NN; i += 256) {
        int b = i >> 12;
        int n = i & (NN - 1);
        float v = g_t[((size_t)b * CC + c) * NN + n];
        s += v;
        s2 += v * v;
    }
    __shared__ float rs[256], rs2[256];
    rs[threadIdx.x] = s;
    rs2[threadIdx.x] = s2;
    __syncthreads();
    for (int st = 128; st; st >>= 1) {
        if (threadIdx.x < st) {
            rs[threadIdx.x]  += rs[threadIdx.x + st];
            rs2[threadIdx.x] += rs2[threadIdx.x + st];
        }
        __syncthreads();
    }
    if (threadIdx.x == 0) {
        const float invM = 1.f / (float)(BB * NN);
        float mean = rs[0] * invM;
        float var = rs2[0] * invM - mean * mean;
        g_mean[c] = mean;
        g_rstd[c] = rsqrtf(var + 1e-5f);
    }
}

// ---------------------------------------------------------------------------
// Final: out = x + relu(gamma * (t - mean) * rstd + beta)
// ---------------------------------------------------------------------------
__global__ __launch_bounds__(256) void final_kernel(
    const float* __restrict__ x, const float* __restrict__ gamma,
    const float* __restrict__ beta, float* __restrict__ out)
{
    size_t i = (size_t)blockIdx.x * 256 + threadIdx.x;
    int c = (int)((i >> 12) & 255);
    float t = g_t[i];
    float th = (t - g_mean[c]) * g_rstd[c];
    float r = fmaxf(0.f, gamma[c] * th + beta[c]);
    out[i] = x[i] + r;
}

// ---------------------------------------------------------------------------
extern "C" void kernel_launch(void* const* d_in, const int* in_sizes, int n_in,
                              void* d_out, int out_size)
{
    const float* x     = (const float*)d_in[0];
    const float* wq    = (const float*)d_in[1];
    const float* wv    = (const float*)d_in[2];
    const float* bv    = (const float*)d_in[3];
    const float* wt    = (const float*)d_in[4];
    const float* bt    = (const float*)d_in[5];
    const float* gamma = (const float*)d_in[6];
    const float* beta  = (const float*)d_in[7];
    float* out = (float*)d_out;

    void* p;
    cudaGetSymbolAddress(&p, g_xd); float* xdp = (float*)p;
    cudaGetSymbolAddress(&p, g_t);  float* tp  = (float*)p;

    const int xa_smem = XA_SMEM_WORDS * 4;
    cudaFuncSetAttribute(xa_kernel,
                         cudaFuncAttributeMaxDynamicSharedMemorySize, xa_smem);

    // q projection (weight-tied Q/K) -> fp16 [B,N,64]
    convq_kernel<<<dim3(NN / 64, 1, BB), 256>>>(wq, x);
    // v projection -> fp16 pairs [B,C,N/2]
    convv_kernel<<<dim3(NN / 64, CC / 64, BB), 256>>>(wv, x, bv);
    // fused energy + row softmax stats (no E materialization)
    pass1_kernel<<<dim3(NN / 128, BB), 256>>>();
    // fused E-recompute + softmax + double-norm + V*P -> x_d (pipelined)
    xa_kernel<<<dim3(NN / 128, BB), 512, xa_smem>>>(x);
    // trans conv: t = wt @ x_d + bt
    conv1x1_kernel<true><<<dim3(NN / 64, CC / 64, BB), 256>>>(wt, xdp, bt, tp, CC);
    // BN stats + final fused relu/residual
    bnstats_kernel<<<CC, 256>>>();
    final_kernel<<<(BB * CC * NN) / 256, 256>>>(x, gamma, beta, out);
}

// round 8
// speedup vs baseline: 6.0430x; 1.6202x over previous
#include <cuda_runtime.h>
#include <cuda_fp16.h>
#include <cstdint>

#define BB 4
#define CC 256
#define NN 4096
#define DD 64

// Scratch (device globals: allocation-free kernel_launch)
__device__ unsigned g_qh[(size_t)BB * NN * 32];         // 2 MB  q fp16 pairs [b][n][d/2]
__device__ unsigned g_vh[(size_t)BB * CC * (NN / 2)];   // 8 MB  v fp16 pairs [b][c][n/2]
__device__ unsigned g_xth[(size_t)BB * NN * (CC / 2)];  // 8 MB  x^T fp16 pairs [b][n][c/2]
__device__ unsigned g_xaTh[(size_t)BB * NN * (CC / 2)]; // 8 MB  x_a^T fp16 pairs [b][n][c/2]
__device__ unsigned g_wqh[DD * (CC / 2)];               // wq fp16 pairs [o][c/2]
__device__ unsigned g_wvh[CC * (CC / 2)];
__device__ unsigned g_wth[CC * (CC / 2)];
__device__ float g_rowmax[BB * NN];
__device__ float g_rowinv[BB * NN];
__device__ float g_t[(size_t)BB * CC * NN];             // 16 MB
__device__ float g_mean[CC];
__device__ float g_rstd[CC];

// ---------------------------------------------------------------------------
// helpers
// ---------------------------------------------------------------------------
__device__ __forceinline__ void mma_fp16(
    float* c,
    unsigned a0, unsigned a1, unsigned a2, unsigned a3,
    unsigned b0, unsigned b1)
{
    asm volatile(
        "mma.sync.aligned.m16n8k16.row.col.f32.f16.f16.f32 "
        "{%0,%1,%2,%3}, {%4,%5,%6,%7}, {%8,%9}, {%0,%1,%2,%3};\n"
        : "+f"(c[0]), "+f"(c[1]), "+f"(c[2]), "+f"(c[3])
        : "r"(a0), "r"(a1), "r"(a2), "r"(a3), "r"(b0), "r"(b1));
}

__device__ __forceinline__ void cpa16(unsigned sdst, const void* gsrc)
{
    asm volatile("cp.async.cg.shared.global [%0], [%1], 16;\n"
                 :: "r"(sdst), "l"(gsrc));
}
__device__ __forceinline__ void cpa_commit()
{
    asm volatile("cp.async.commit_group;\n");
}
__device__ __forceinline__ void cpa_wait0()
{
    asm volatile("cp.async.wait_group 0;\n");
}

__device__ __forceinline__ unsigned pack_h2(float a, float b)
{
    __half2 h = __floats2half2_rn(a, b);
    return *reinterpret_cast<unsigned*>(&h);
}

// ---------------------------------------------------------------------------
// xt: transpose + convert x[b][c][n] fp32 -> g_xth[(b*N+n)*128 + c/2] fp16 pairs
// ---------------------------------------------------------------------------
__global__ __launch_bounds__(256) void xt_kernel(const float* __restrict__ x)
{
    const int b  = blockIdx.z;
    const int c0 = blockIdx.y * 64;
    const int n0 = blockIdx.x * 64;
    const float* xb = x + ((size_t)b * CC + c0) * NN + n0;

    __shared__ float sT[64][65];
    const int tid = threadIdx.x;

#pragma unroll
    for (int r = 0; r < 16; r++) {
        int idx = tid + r * 256;
        int c = idx >> 6, n = idx & 63;
        sT[c][n] = xb[(size_t)c * NN + n];
    }
    __syncthreads();
#pragma unroll
    for (int r = 0; r < 8; r++) {
        int idx = tid + r * 256;
        int n = idx >> 5, cp = idx & 31;
        g_xth[((size_t)b * NN + n0 + n) * 128 + c0 / 2 + cp] =
            pack_h2(sT[2 * cp][n], sT[2 * cp + 1][n]);
    }
}

// ---------------------------------------------------------------------------
// wcvt: convert wq/wv/wt to fp16 pairs (k-contiguous)
// ---------------------------------------------------------------------------
__global__ __launch_bounds__(256) void wcvt_kernel(
    const float* __restrict__ wq, const float* __restrict__ wv,
    const float* __restrict__ wt)
{
    int idx = blockIdx.x * 256 + threadIdx.x;
    if (idx < 8192) {
        float2 f = *reinterpret_cast<const float2*>(&wq[idx * 2]);
        g_wqh[idx] = pack_h2(f.x, f.y);
    } else if (idx < 8192 + 32768) {
        int i = idx - 8192;
        float2 f = *reinterpret_cast<const float2*>(&wv[i * 2]);
        g_wvh[i] = pack_h2(f.x, f.y);
    } else if (idx < 8192 + 65536) {
        int i = idx - 8192 - 32768;
        float2 f = *reinterpret_cast<const float2*>(&wt[i * 2]);
        g_wth[i] = pack_h2(f.x, f.y);
    }
}

// ---------------------------------------------------------------------------
// convq_tc: q^T[n][o] = x^T[n][:] . wq[o][:]  -> g_qh[(b*N+n)*32 + o/2]
// block tile 128n x 64o, 8 warps (2x4), K=256 in 4 chunks.
// ---------------------------------------------------------------------------
__global__ __launch_bounds__(256) void convq_tc_kernel()
{
    const int b  = blockIdx.z;
    const int n0 = blockIdx.x * 128;
    const unsigned* xth = g_xth + (size_t)b * NN * 128;

    __shared__ unsigned sA[128][36];
    __shared__ unsigned sB[64][36];

    const int tid = threadIdx.x;
    const int lane = tid & 31, wid = tid >> 5;
    const int wm = wid >> 2, wn = wid & 3;
    const int gp = lane >> 2, tg = lane & 3;

    float acc[4][2][4] = {};

    for (int ks = 0; ks < 4; ks++) {
        int kp0g = ks * 32;
        __syncthreads();
#pragma unroll
        for (int r = 0; r < 16; r++) {
            int idx = tid + r * 256;
            int row = idx >> 5, kp = idx & 31;
            sA[row][kp] = xth[(size_t)(n0 + row) * 128 + kp0g + kp];
        }
#pragma unroll
        for (int r = 0; r < 8; r++) {
            int idx = tid + r * 256;
            int row = idx >> 5, kp = idx & 31;
            sB[row][kp] = g_wqh[(size_t)row * 128 + kp0g + kp];
        }
        __syncthreads();
#pragma unroll
        for (int kk = 0; kk < 4; kk++) {
            int kp0 = kk * 8;
            unsigned a[4][4], bf[2][2];
#pragma unroll
            for (int i = 0; i < 4; i++) {
                int row = wm * 64 + i * 16 + gp;
                a[i][0] = sA[row][kp0 + tg];
                a[i][1] = sA[row + 8][kp0 + tg];
                a[i][2] = sA[row][kp0 + 4 + tg];
                a[i][3] = sA[row + 8][kp0 + 4 + tg];
            }
#pragma unroll
            for (int j = 0; j < 2; j++) {
                int col = wn * 16 + j * 8 + gp;
                bf[j][0] = sB[col][kp0 + tg];
                bf[j][1] = sB[col][kp0 + 4 + tg];
            }
#pragma unroll
            for (int i = 0; i < 4; i++)
#pragma unroll
                for (int j = 0; j < 2; j++)
                    mma_fp16(acc[i][j], a[i][0], a[i][1], a[i][2], a[i][3],
                             bf[j][0], bf[j][1]);
        }
    }

#pragma unroll
    for (int i = 0; i < 4; i++) {
        int n = n0 + wm * 64 + i * 16 + gp;
#pragma unroll
        for (int j = 0; j < 2; j++) {
            int op = wn * 8 + j * 4 + tg;
            g_qh[((size_t)b * NN + n) * 32 + op]     = pack_h2(acc[i][j][0], acc[i][j][1]);
            g_qh[((size_t)b * NN + n + 8) * 32 + op] = pack_h2(acc[i][j][2], acc[i][j][3]);
        }
    }
}

// ---------------------------------------------------------------------------
// convv_tc: v[o][n] = wv[o][:] . x^T[n][:] + bv  -> g_vh[(b*C+o)*(N/2) + n/2]
// block tile 128o x 128n, 8 warps (2x4), K=256 in 4 chunks.
// ---------------------------------------------------------------------------
__global__ __launch_bounds__(256) void convv_tc_kernel(const float* __restrict__ bias)
{
    const int b  = blockIdx.z;
    const int o0 = blockIdx.y * 128;
    const int n0 = blockIdx.x * 128;
    const unsigned* xth = g_xth + (size_t)b * NN * 128;

    __shared__ unsigned sA[128][36];
    __shared__ unsigned sB[128][36];

    const int tid = threadIdx.x;
    const int lane = tid & 31, wid = tid >> 5;
    const int wm = wid >> 2, wn = wid & 3;
    const int gp = lane >> 2, tg = lane & 3;

    float acc[4][4][4] = {};

    for (int ks = 0; ks < 4; ks++) {
        int kp0g = ks * 32;
        __syncthreads();
#pragma unroll
        for (int r = 0; r < 16; r++) {
            int idx = tid + r * 256;
            int row = idx >> 5, kp = idx & 31;
            sA[row][kp] = g_wvh[(size_t)(o0 + row) * 128 + kp0g + kp];
            sB[row][kp] = xth[(size_t)(n0 + row) * 128 + kp0g + kp];
        }
        __syncthreads();
#pragma unroll
        for (int kk = 0; kk < 4; kk++) {
            int kp0 = kk * 8;
            unsigned a[4][4], bf[4][2];
#pragma unroll
            for (int i = 0; i < 4; i++) {
                int row = wm * 64 + i * 16 + gp;
                a[i][0] = sA[row][kp0 + tg];
                a[i][1] = sA[row + 8][kp0 + tg];
                a[i][2] = sA[row][kp0 + 4 + tg];
                a[i][3] = sA[row + 8][kp0 + 4 + tg];
            }
#pragma unroll
            for (int j = 0; j < 4; j++) {
                int col = wn * 32 + j * 8 + gp;
                bf[j][0] = sB[col][kp0 + tg];
                bf[j][1] = sB[col][kp0 + 4 + tg];
            }
#pragma unroll
            for (int i = 0; i < 4; i++)
#pragma unroll
                for (int j = 0; j < 4; j++)
                    mma_fp16(acc[i][j], a[i][0], a[i][1], a[i][2], a[i][3],
                             bf[j][0], bf[j][1]);
        }
    }

#pragma unroll
    for (int i = 0; i < 4; i++) {
        int o = o0 + wm * 64 + i * 16 + gp;
        float b0 = bias[o], b1 = bias[o + 8];
#pragma unroll
        for (int j = 0; j < 4; j++) {
            int np = (n0 + wn * 32 + j * 8 + 2 * tg) / 2;
            g_vh[((size_t)b * CC + o) * (NN / 2) + np] =
                pack_h2(acc[i][j][0] + b0, acc[i][j][1] + b0);
            g_vh[((size_t)b * CC + o + 8) * (NN / 2) + np] =
                pack_h2(acc[i][j][2] + b1, acc[i][j][3] + b1);
        }
    }
}

// ---------------------------------------------------------------------------
// convt_tc: t[o][n] = wt[o][:] . (x^T - x_a^T)[n][:] + bt  -> g_t fp32
// ---------------------------------------------------------------------------
__global__ __launch_bounds__(256) void convt_tc_kernel(const float* __restrict__ bias)
{
    const int b  = blockIdx.z;
    const int o0 = blockIdx.y * 128;
    const int n0 = blockIdx.x * 128;
    const unsigned* xth  = g_xth  + (size_t)b * NN * 128;
    const unsigned* xath = g_xaTh + (size_t)b * NN * 128;

    __shared__ unsigned sA[128][36];
    __shared__ unsigned sB[128][36];

    const int tid = threadIdx.x;
    const int lane = tid & 31, wid = tid >> 5;
    const int wm = wid >> 2, wn = wid & 3;
    const int gp = lane >> 2, tg = lane & 3;

    float acc[4][4][4] = {};

    for (int ks = 0; ks < 4; ks++) {
        int kp0g = ks * 32;
        __syncthreads();
#pragma unroll
        for (int r = 0; r < 16; r++) {
            int idx = tid + r * 256;
            int row = idx >> 5, kp = idx & 31;
            sA[row][kp] = g_wth[(size_t)(o0 + row) * 128 + kp0g + kp];
            size_t gi = (size_t)(n0 + row) * 128 + kp0g + kp;
            __half2 xv = *reinterpret_cast<const __half2*>(&xth[gi]);
            __half2 av = *reinterpret_cast<const __half2*>(&xath[gi]);
            __half2 d = __hsub2(xv, av);
            sB[row][kp] = *reinterpret_cast<unsigned*>(&d);
        }
        __syncthreads();
#pragma unroll
        for (int kk = 0; kk < 4; kk++) {
            int kp0 = kk * 8;
            unsigned a[4][4], bf[4][2];
#pragma unroll
            for (int i = 0; i < 4; i++) {
                int row = wm * 64 + i * 16 + gp;
                a[i][0] = sA[row][kp0 + tg];
                a[i][1] = sA[row + 8][kp0 + tg];
                a[i][2] = sA[row][kp0 + 4 + tg];
                a[i][3] = sA[row + 8][kp0 + 4 + tg];
            }
#pragma unroll
            for (int j = 0; j < 4; j++) {
                int col = wn * 32 + j * 8 + gp;
                bf[j][0] = sB[col][kp0 + tg];
                bf[j][1] = sB[col][kp0 + 4 + tg];
            }
#pragma unroll
            for (int i = 0; i < 4; i++)
#pragma unroll
                for (int j = 0; j < 4; j++)
                    mma_fp16(acc[i][j], a[i][0], a[i][1], a[i][2], a[i][3],
                             bf[j][0], bf[j][1]);
        }
    }

#pragma unroll
    for (int i = 0; i < 4; i++) {
        int o = o0 + wm * 64 + i * 16 + gp;
        float b0 = bias[o], b1 = bias[o + 8];
#pragma unroll
        for (int j = 0; j < 4; j++) {
            int n = n0 + wn * 32 + j * 8 + 2 * tg;
            float2 v0 = make_float2(acc[i][j][0] + b0, acc[i][j][1] + b0);
            float2 v1 = make_float2(acc[i][j][2] + b1, acc[i][j][3] + b1);
            *reinterpret_cast<float2*>(&g_t[((size_t)b * CC + o) * NN + n]) = v0;
            *reinterpret_cast<float2*>(&g_t[((size_t)b * CC + o + 8) * NN + n]) = v1;
        }
    }
}

// ---------------------------------------------------------------------------
// pass1: fused energy + row softmax stats (flash pass).
// ---------------------------------------------------------------------------
__global__ __launch_bounds__(256) void pass1_kernel()
{
    const int b  = blockIdx.y;
    const int n0 = blockIdx.x * 128;
    const unsigned* qh = g_qh + (size_t)b * NN * 32;

    __shared__ unsigned sA[128][36];
    __shared__ unsigned sB[128][36];
    __shared__ float2 sMrg[4][128];

    const int tid = threadIdx.x;
    const int lane = tid & 31, wid = tid >> 5;
    const int wm = wid >> 2, wn = wid & 3;
    const int gp = lane >> 2, tg = lane & 3;

#pragma unroll
    for (int r = 0; r < 16; r++) {
        int idx = tid + r * 256;
        int row = idx >> 5, kp = idx & 31;
        sA[row][kp] = qh[(size_t)(n0 + row) * 32 + kp];
    }

    float rmax[8], rsum[8];
#pragma unroll
    for (int i = 0; i < 8; i++) { rmax[i] = -1e30f; rsum[i] = 0.f; }

    for (int m0 = 0; m0 < NN; m0 += 128) {
        __syncthreads();
#pragma unroll
        for (int r = 0; r < 16; r++) {
            int idx = tid + r * 256;
            int row = idx >> 5, kp = idx & 31;
            sB[row][kp] = qh[(size_t)(m0 + row) * 32 + kp];
        }
        __syncthreads();

        float acc[4][4][4] = {};
#pragma unroll
        for (int ks = 0; ks < 4; ks++) {
            int kp0 = ks * 8;
            unsigned a[4][4], bf[4][2];
#pragma unroll
            for (int i = 0; i < 4; i++) {
                int row = wm * 64 + i * 16 + gp;
                a[i][0] = sA[row][kp0 + tg];
                a[i][1] = sA[row + 8][kp0 + tg];
                a[i][2] = sA[row][kp0 + 4 + tg];
                a[i][3] = sA[row + 8][kp0 + 4 + tg];
            }
#pragma unroll
            for (int j = 0; j < 4; j++) {
                int col = wn * 32 + j * 8 + gp;
                bf[j][0] = sB[col][kp0 + tg];
                bf[j][1] = sB[col][kp0 + 4 + tg];
            }
#pragma unroll
            for (int i = 0; i < 4; i++)
#pragma unroll
                for (int j = 0; j < 4; j++)
                    mma_fp16(acc[i][j], a[i][0], a[i][1], a[i][2], a[i][3],
                             bf[j][0], bf[j][1]);
        }

#pragma unroll
        for (int i = 0; i < 4; i++) {
            float m0v = -1e30f, m1v = -1e30f;
#pragma unroll
            for (int j = 0; j < 4; j++) {
                m0v = fmaxf(m0v, fmaxf(acc[i][j][0], acc[i][j][1]));
                m1v = fmaxf(m1v, fmaxf(acc[i][j][2], acc[i][j][3]));
            }
            m0v = fmaxf(m0v, __shfl_xor_sync(0xffffffffu, m0v, 1));
            m0v = fmaxf(m0v, __shfl_xor_sync(0xffffffffu, m0v, 2));
            m1v = fmaxf(m1v, __shfl_xor_sync(0xffffffffu, m1v, 1));
            m1v = fmaxf(m1v, __shfl_xor_sync(0xffffffffu, m1v, 2));
            float nm0 = fmaxf(rmax[2 * i],     m0v);
            float nm1 = fmaxf(rmax[2 * i + 1], m1v);
            float s0 = 0.f, s1 = 0.f;
#pragma unroll
            for (int j = 0; j < 4; j++) {
                s0 += __expf(acc[i][j][0] - nm0) + __expf(acc[i][j][1] - nm0);
                s1 += __expf(acc[i][j][2] - nm1) + __expf(acc[i][j][3] - nm1);
            }
            s0 += __shfl_xor_sync(0xffffffffu, s0, 1);
            s0 += __shfl_xor_sync(0xffffffffu, s0, 2);
            s1 += __shfl_xor_sync(0xffffffffu, s1, 1);
            s1 += __shfl_xor_sync(0xffffffffu, s1, 2);
            rsum[2 * i]     = rsum[2 * i]     * __expf(rmax[2 * i]     - nm0) + s0;
            rsum[2 * i + 1] = rsum[2 * i + 1] * __expf(rmax[2 * i + 1] - nm1) + s1;
            rmax[2 * i]     = nm0;
            rmax[2 * i + 1] = nm1;
        }
    }

    if (tg == 0) {
#pragma unroll
        for (int i = 0; i < 4; i++) {
            int row = wm * 64 + i * 16 + gp;
            sMrg[wn][row]     = make_float2(rmax[2 * i],     rsum[2 * i]);
            sMrg[wn][row + 8] = make_float2(rmax[2 * i + 1], rsum[2 * i + 1]);
        }
    }
    __syncthreads();
    if (tid < 128) {
        float2 v0 = sMrg[0][tid], v1 = sMrg[1][tid];
        float2 v2 = sMrg[2][tid], v3 = sMrg[3][tid];
        float M = fmaxf(fmaxf(v0.x, v1.x), fmaxf(v2.x, v3.x));
        float S = v0.y * __expf(v0.x - M) + v1.y * __expf(v1.x - M)
                + v2.y * __expf(v2.x - M) + v3.y * __expf(v3.x - M);
        g_rowmax[b * NN + n0 + tid] = M;
        g_rowinv[b * NN + n0 + tid] = 1.f / S;
    }
}

// ---------------------------------------------------------------------------
// xa: fused E-recompute + P + colsum + x_a^T = (P^T V^T) via swapped mma.
// Writes g_xaTh fp16 [m][c-pairs]. 512 threads, cp.async double-buffered.
// mma2: A = P[m][n] (sPh), B = V[c][n] (sVh)  ->  C[m][c], c-pairs contig.
// Warps for mma2: wm=wid>>2 over m (4x32), wn=wid&3 over c (4x64).
// ---------------------------------------------------------------------------
#define XA_W_SVH 0
#define XA_W_SQM (2 * 256 * 36)
#define XA_W_SQN (XA_W_SQM + 128 * 36)
#define XA_W_SPH (XA_W_SQN + 2 * 64 * 36)
#define XA_W_COL (XA_W_SPH + 2 * 128 * 36)
#define XA_SMEM_WORDS (XA_W_COL + 128)

__global__ __launch_bounds__(512, 1) void xa_kernel()
{
    const int b  = blockIdx.y;
    const int m0 = blockIdx.x * 128;
    const unsigned* vbh = g_vh + (size_t)b * CC * (NN / 2);
    const float* rmx = g_rowmax + b * NN;
    const float* rin = g_rowinv + b * NN;
    const unsigned* qh = g_qh + (size_t)b * NN * 32;

    extern __shared__ unsigned shm[];
    unsigned (*sQm)[36] = reinterpret_cast<unsigned(*)[36]>(shm + XA_W_SQM);
    float* sCol = reinterpret_cast<float*>(shm + XA_W_COL);
    const unsigned sbase = (unsigned)__cvta_generic_to_shared(shm);

    const int tid = threadIdx.x;
    const int lane = tid & 31, wid = tid >> 5;
    const int gp = lane >> 2, tg = lane & 3;
    const int nh = wid & 3, mh = wid >> 2;       // mma1 roles (4x4)
    const int wm = wid >> 2, wn = wid & 3;       // mma2 roles

    // q_m tile (constant for the block)
#pragma unroll
    for (int r = 0; r < 8; r++) {
        int idx = tid + r * 512;
        int row = idx >> 5, kp = idx & 31;
        sQm[row][kp] = qh[(size_t)(m0 + row) * 32 + kp];
    }
    if (tid < 128) sCol[tid] = 0.f;

    auto issue_loads = [&](int chunk, int buf) {
        int np0 = chunk * 32;
#pragma unroll
        for (int t = 0; t < 4; t++) {
            int idx = tid + t * 512;
            int row = idx >> 3, seg = idx & 7;
            unsigned dst = sbase + (XA_W_SVH + buf * 256 * 36 + row * 36 + seg * 4) * 4;
            cpa16(dst, vbh + (size_t)row * (NN / 2) + np0 + seg * 4);
        }
        {
            int row = tid >> 3, seg = tid & 7;
            unsigned dst = sbase + (XA_W_SQN + buf * 64 * 36 + row * 36 + seg * 4) * 4;
            cpa16(dst, qh + (size_t)(chunk * 64 + row) * 32 + seg * 4);
        }
        cpa_commit();
    };

    issue_loads(0, 0);
    issue_loads(1, 1);
    cpa_wait0();
    __syncthreads();

    float acc[2][8][4] = {};

    for (int i = 0; i < 64; i++) {
        const int buf = i & 1;
        const int n0 = i * 64;
        unsigned (*sQnB)[36] = reinterpret_cast<unsigned(*)[36]>(shm + XA_W_SQN + buf * 64 * 36);
        unsigned (*sVhB)[36] = reinterpret_cast<unsigned(*)[36]>(shm + XA_W_SVH + buf * 256 * 36);
        __half  (*sPhB)[72] = reinterpret_cast<__half(*)[72]>(shm + XA_W_SPH + buf * 128 * 36);
        unsigned (*sPhU)[36] = reinterpret_cast<unsigned(*)[36]>(shm + XA_W_SPH + buf * 128 * 36);

        // mma1: E chunk [64n x 128m]; warp rows nh*16+gp(+8), cols mh*32+j*8
        float e[4][4] = {};
#pragma unroll
        for (int ks = 0; ks < 4; ks++) {
            int kp0 = ks * 8;
            unsigned a0 = sQnB[nh * 16 + gp][kp0 + tg];
            unsigned a1 = sQnB[nh * 16 + gp + 8][kp0 + tg];
            unsigned a2 = sQnB[nh * 16 + gp][kp0 + 4 + tg];
            unsigned a3 = sQnB[nh * 16 + gp + 8][kp0 + 4 + tg];
#pragma unroll
            for (int j = 0; j < 4; j++) {
                int col = mh * 32 + j * 8 + gp;
                mma_fp16(e[j], a0, a1, a2, a3,
                         sQm[col][kp0 + tg], sQm[col][kp0 + 4 + tg]);
            }
        }

        int r0 = n0 + nh * 16 + gp;
        float mx0 = __ldg(&rmx[r0]),     iv0 = __ldg(&rin[r0]);
        float mx1 = __ldg(&rmx[r0 + 8]), iv1 = __ldg(&rin[r0 + 8]);
        int nr0 = nh * 16 + gp, nr1 = nr0 + 8;
#pragma unroll
        for (int j = 0; j < 4; j++) {
            int cb = mh * 32 + j * 8 + 2 * tg;
            sPhB[cb][nr0]     = __float2half(__expf(e[j][0] - mx0) * iv0);
            sPhB[cb + 1][nr0] = __float2half(__expf(e[j][1] - mx0) * iv0);
            sPhB[cb][nr1]     = __float2half(__expf(e[j][2] - mx1) * iv1);
            sPhB[cb + 1][nr1] = __float2half(__expf(e[j][3] - mx1) * iv1);
        }
        __syncthreads();   // P[i] visible

        // colsum spread over all 512 threads
        {
            int m = tid & 127, seg = tid >> 7;
            const __half2* prow = reinterpret_cast<const __half2*>(sPhB[m]);
            float cs = 0.f;
#pragma unroll
            for (int k = 0; k < 8; k++) {
                float2 f = __half22float2(prow[seg * 8 + k]);
                cs += f.x + f.y;
            }
            atomicAdd(&sCol[m], cs);
        }

        // mma2 (swapped): acc[m,c] += P[m][n] * V[c][n]
#pragma unroll
        for (int ks = 0; ks < 4; ks++) {
            int kp0 = ks * 8;
            unsigned pa[2][4], bf[8][2];
#pragma unroll
            for (int ii = 0; ii < 2; ii++) {
                int row = wm * 32 + ii * 16 + gp;
                pa[ii][0] = sPhU[row][kp0 + tg];
                pa[ii][1] = sPhU[row + 8][kp0 + tg];
                pa[ii][2] = sPhU[row][kp0 + 4 + tg];
                pa[ii][3] = sPhU[row + 8][kp0 + 4 + tg];
            }
#pragma unroll
            for (int j = 0; j < 8; j++) {
                int col = wn * 64 + j * 8 + gp;
                bf[j][0] = sVhB[col][kp0 + tg];
                bf[j][1] = sVhB[col][kp0 + 4 + tg];
            }
#pragma unroll
            for (int ii = 0; ii < 2; ii++)
#pragma unroll
                for (int j = 0; j < 8; j++)
                    mma_fp16(acc[ii][j], pa[ii][0], pa[ii][1], pa[ii][2], pa[ii][3],
                             bf[j][0], bf[j][1]);
        }

        cpa_wait0();
        __syncthreads();
        if (i + 2 < 64)
            issue_loads(i + 2, buf);
    }

    // epilogue: x_a^T[m][c] = acc * inv(m); write fp16 pairs (c contig)
#pragma unroll
    for (int ii = 0; ii < 2; ii++) {
        int mr = wm * 32 + ii * 16 + gp;
        float i0 = 1.f / (1e-9f + sCol[mr]);
        float i1 = 1.f / (1e-9f + sCol[mr + 8]);
        size_t r0 = ((size_t)b * NN + m0 + mr) * 128;
        size_t r1 = r0 + 8 * 128;
#pragma unroll
        for (int j = 0; j < 8; j++) {
            int cp = wn * 32 + j * 4 + tg;
            g_xaTh[r0 + cp] = pack_h2(acc[ii][j][0] * i0, acc[ii][j][1] * i0);
            g_xaTh[r1 + cp] = pack_h2(acc[ii][j][2] * i1, acc[ii][j][3] * i1);
        }
    }
}

// ---------------------------------------------------------------------------
// BN stats: per channel c, mean/var over (B, N).
// ---------------------------------------------------------------------------
__global__ __launch_bounds__(256) void bnstats_kernel()
{
    const int c = blockIdx.x;
    float s = 0.f, s2 = 0.f;
    for (int i = threadIdx.x; i < BB * NN; i += 256) {
        int b = i >> 12;
        int n = i & (NN - 1);
        float v = g_t[((size_t)b * CC + c) * NN + n];
        s += v;
        s2 += v * v;
    }
    __shared__ float rs[256], rs2[256];
    rs[threadIdx.x] = s;
    rs2[threadIdx.x] = s2;
    __syncthreads();
    for (int st = 128; st; st >>= 1) {
        if (threadIdx.x < st) {
            rs[threadIdx.x]  += rs[threadIdx.x + st];
            rs2[threadIdx.x] += rs2[threadIdx.x + st];
        }
        __syncthreads();
    }
    if (threadIdx.x == 0) {
        const float invM = 1.f / (float)(BB * NN);
        float mean = rs[0] * invM;
        float var = rs2[0] * invM - mean * mean;
        g_mean[c] = mean;
        g_rstd[c] = rsqrtf(var + 1e-5f);
    }
}

// ---------------------------------------------------------------------------
// Final: out = x + relu(gamma * (t - mean) * rstd + beta)
// ---------------------------------------------------------------------------
__global__ __launch_bounds__(256) void final_kernel(
    const float* __restrict__ x, const float* __restrict__ gamma,
    const float* __restrict__ beta, float* __restrict__ out)
{
    size_t i = (size_t)blockIdx.x * 256 + threadIdx.x;
    int c = (int)((i >> 12) & 255);
    float t = g_t[i];
    float th = (t - g_mean[c]) * g_rstd[c];
    float r = fmaxf(0.f, gamma[c] * th + beta[c]);
    out[i] = x[i] + r;
}

// ---------------------------------------------------------------------------
extern "C" void kernel_launch(void* const* d_in, const int* in_sizes, int n_in,
                              void* d_out, int out_size)
{
    const float* x     = (const float*)d_in[0];
    const float* wq    = (const float*)d_in[1];
    const float* wv    = (const float*)d_in[2];
    const float* bv    = (const float*)d_in[3];
    const float* wt    = (const float*)d_in[4];
    const float* bt    = (const float*)d_in[5];
    const float* gamma = (const float*)d_in[6];
    const float* beta  = (const float*)d_in[7];
    float* out = (float*)d_out;

    const int xa_smem = XA_SMEM_WORDS * 4;
    cudaFuncSetAttribute(xa_kernel,
                         cudaFuncAttributeMaxDynamicSharedMemorySize, xa_smem);

    // x^T fp16 + weight fp16 conversions
    xt_kernel<<<dim3(NN / 64, CC / 64, BB), 256>>>(x);
    wcvt_kernel<<<(8192 + 65536 + 255) / 256, 256>>>(wq, wv, wt);
    // q^T = x^T wq^T  (weight-tied Q/K), fp16 mma
    convq_tc_kernel<<<dim3(NN / 128, 1, BB), 256>>>();
    // v = wv x + bv, fp16 mma
    convv_tc_kernel<<<dim3(NN / 128, CC / 128, BB), 256>>>(bv);
    // fused energy + row softmax stats
    pass1_kernel<<<dim3(NN / 128, BB), 256>>>();
    // fused E-recompute + softmax + double-norm + x_a^T (pipelined fp16)
    xa_kernel<<<dim3(NN / 128, BB), 512, xa_smem>>>();
    // t = wt (x - x_a) + bt, fp16 mma (subtraction in B-tile fill)
    convt_tc_kernel<<<dim3(NN / 128, CC / 128, BB), 256>>>(bt);
    // BN stats + final fused relu/residual
    bnstats_kernel<<<CC, 256>>>();
    final_kernel<<<(BB * CC * NN) / 256, 256>>>(x, gamma, beta, out);
}

// round 9
// speedup vs baseline: 6.0475x; 1.0007x over previous
#include <cuda_runtime.h>
#include <cuda_fp16.h>
#include <cstdint>

#define BB 4
#define CC 256
#define NN 4096
#define DD 64

// Scratch (device globals: allocation-free kernel_launch)
__device__ unsigned g_qh[(size_t)BB * NN * 32];         // 2 MB  q fp16 pairs [b][n][d/2]
__device__ unsigned g_vh[(size_t)BB * CC * (NN / 2)];   // 8 MB  v fp16 pairs [b][c][n/2]
__device__ unsigned g_xth[(size_t)BB * NN * (CC / 2)];  // 8 MB  x^T fp16 pairs [b][n][c/2]
__device__ unsigned g_xaTh[(size_t)BB * NN * (CC / 2)]; // 8 MB  x_a^T fp16 pairs [b][n][c/2]
__device__ unsigned g_wqh[DD * (CC / 2)];               // wq fp16 pairs [o][c/2]
__device__ unsigned g_wvh[CC * (CC / 2)];
__device__ unsigned g_wth[CC * (CC / 2)];
__device__ float g_rowmax[BB * NN];
__device__ float g_rowinv[BB * NN];
__device__ float g_t[(size_t)BB * CC * NN];             // 16 MB
__device__ float g_mean[CC];
__device__ float g_rstd[CC];

// ---------------------------------------------------------------------------
// helpers
// ---------------------------------------------------------------------------
__device__ __forceinline__ void mma_fp16(
    float* c,
    unsigned a0, unsigned a1, unsigned a2, unsigned a3,
    unsigned b0, unsigned b1)
{
    asm volatile(
        "mma.sync.aligned.m16n8k16.row.col.f32.f16.f16.f32 "
        "{%0,%1,%2,%3}, {%4,%5,%6,%7}, {%8,%9}, {%0,%1,%2,%3};\n"
        : "+f"(c[0]), "+f"(c[1]), "+f"(c[2]), "+f"(c[3])
        : "r"(a0), "r"(a1), "r"(a2), "r"(a3), "r"(b0), "r"(b1));
}

__device__ __forceinline__ void cpa16(unsigned sdst, const void* gsrc)
{
    asm volatile("cp.async.cg.shared.global [%0], [%1], 16;\n"
                 :: "r"(sdst), "l"(gsrc));
}
__device__ __forceinline__ void cpa_commit()
{
    asm volatile("cp.async.commit_group;\n");
}
__device__ __forceinline__ void cpa_wait0()
{
    asm volatile("cp.async.wait_group 0;\n");
}

__device__ __forceinline__ unsigned pack_h2(float a, float b)
{
    __half2 h = __floats2half2_rn(a, b);
    return *reinterpret_cast<unsigned*>(&h);
}

// ---------------------------------------------------------------------------
// xt: transpose + convert x[b][c][n] fp32 -> g_xth[(b*N+n)*128 + c/2] fp16 pairs
// ---------------------------------------------------------------------------
__global__ __launch_bounds__(256) void xt_kernel(const float* __restrict__ x)
{
    const int b  = blockIdx.z;
    const int c0 = blockIdx.y * 64;
    const int n0 = blockIdx.x * 64;
    const float* xb = x + ((size_t)b * CC + c0) * NN + n0;

    __shared__ float sT[64][65];
    const int tid = threadIdx.x;

#pragma unroll
    for (int r = 0; r < 16; r++) {
        int idx = tid + r * 256;
        int c = idx >> 6, n = idx & 63;
        sT[c][n] = xb[(size_t)c * NN + n];
    }
    __syncthreads();
#pragma unroll
    for (int r = 0; r < 8; r++) {
        int idx = tid + r * 256;
        int n = idx >> 5, cp = idx & 31;
        g_xth[((size_t)b * NN + n0 + n) * 128 + c0 / 2 + cp] =
            pack_h2(sT[2 * cp][n], sT[2 * cp + 1][n]);
    }
}

// ---------------------------------------------------------------------------
// wcvt: convert wq/wv/wt to fp16 pairs (k-contiguous)
// ---------------------------------------------------------------------------
__global__ __launch_bounds__(256) void wcvt_kernel(
    const float* __restrict__ wq, const float* __restrict__ wv,
    const float* __restrict__ wt)
{
    int idx = blockIdx.x * 256 + threadIdx.x;
    if (idx < 8192) {
        float2 f = *reinterpret_cast<const float2*>(&wq[idx * 2]);
        g_wqh[idx] = pack_h2(f.x, f.y);
    } else if (idx < 8192 + 32768) {
        int i = idx - 8192;
        float2 f = *reinterpret_cast<const float2*>(&wv[i * 2]);
        g_wvh[i] = pack_h2(f.x, f.y);
    } else if (idx < 8192 + 65536) {
        int i = idx - 8192 - 32768;
        float2 f = *reinterpret_cast<const float2*>(&wt[i * 2]);
        g_wth[i] = pack_h2(f.x, f.y);
    }
}

// ---------------------------------------------------------------------------
// convq_tc: q^T[n][o] = x^T[n][:] . wq[o][:]  -> g_qh[(b*N+n)*32 + o/2]
// block tile 128n x 64o, 8 warps (2x4), K=256 in 4 chunks.
// ---------------------------------------------------------------------------
__global__ __launch_bounds__(256) void convq_tc_kernel()
{
    const int b  = blockIdx.z;
    const int n0 = blockIdx.x * 128;
    const unsigned* xth = g_xth + (size_t)b * NN * 128;

    __shared__ unsigned sA[128][36];
    __shared__ unsigned sB[64][36];

    const int tid = threadIdx.x;
    const int lane = tid & 31, wid = tid >> 5;
    const int wm = wid >> 2, wn = wid & 3;
    const int gp = lane >> 2, tg = lane & 3;

    float acc[4][2][4] = {};

    for (int ks = 0; ks < 4; ks++) {
        int kp0g = ks * 32;
        __syncthreads();
#pragma unroll
        for (int r = 0; r < 16; r++) {
            int idx = tid + r * 256;
            int row = idx >> 5, kp = idx & 31;
            sA[row][kp] = xth[(size_t)(n0 + row) * 128 + kp0g + kp];
        }
#pragma unroll
        for (int r = 0; r < 8; r++) {
            int idx = tid + r * 256;
            int row = idx >> 5, kp = idx & 31;
            sB[row][kp] = g_wqh[(size_t)row * 128 + kp0g + kp];
        }
        __syncthreads();
#pragma unroll
        for (int kk = 0; kk < 4; kk++) {
            int kp0 = kk * 8;
            unsigned a[4][4], bf[2][2];
#pragma unroll
            for (int i = 0; i < 4; i++) {
                int row = wm * 64 + i * 16 + gp;
                a[i][0] = sA[row][kp0 + tg];
                a[i][1] = sA[row + 8][kp0 + tg];
                a[i][2] = sA[row][kp0 + 4 + tg];
                a[i][3] = sA[row + 8][kp0 + 4 + tg];
            }
#pragma unroll
            for (int j = 0; j < 2; j++) {
                int col = wn * 16 + j * 8 + gp;
                bf[j][0] = sB[col][kp0 + tg];
                bf[j][1] = sB[col][kp0 + 4 + tg];
            }
#pragma unroll
            for (int i = 0; i < 4; i++)
#pragma unroll
                for (int j = 0; j < 2; j++)
                    mma_fp16(acc[i][j], a[i][0], a[i][1], a[i][2], a[i][3],
                             bf[j][0], bf[j][1]);
        }
    }

#pragma unroll
    for (int i = 0; i < 4; i++) {
        int n = n0 + wm * 64 + i * 16 + gp;
#pragma unroll
        for (int j = 0; j < 2; j++) {
            int op = wn * 8 + j * 4 + tg;
            g_qh[((size_t)b * NN + n) * 32 + op]     = pack_h2(acc[i][j][0], acc[i][j][1]);
            g_qh[((size_t)b * NN + n + 8) * 32 + op] = pack_h2(acc[i][j][2], acc[i][j][3]);
        }
    }
}

// ---------------------------------------------------------------------------
// convv_tc: v[o][n] = wv[o][:] . x^T[n][:] + bv  -> g_vh[(b*C+o)*(N/2) + n/2]
// block tile 128o x 128n, 8 warps (2x4), K=256 in 4 chunks.
// ---------------------------------------------------------------------------
__global__ __launch_bounds__(256) void convv_tc_kernel(const float* __restrict__ bias)
{
    const int b  = blockIdx.z;
    const int o0 = blockIdx.y * 128;
    const int n0 = blockIdx.x * 128;
    const unsigned* xth = g_xth + (size_t)b * NN * 128;

    __shared__ unsigned sA[128][36];
    __shared__ unsigned sB[128][36];

    const int tid = threadIdx.x;
    const int lane = tid & 31, wid = tid >> 5;
    const int wm = wid >> 2, wn = wid & 3;
    const int gp = lane >> 2, tg = lane & 3;

    float acc[4][4][4] = {};

    for (int ks = 0; ks < 4; ks++) {
        int kp0g = ks * 32;
        __syncthreads();
#pragma unroll
        for (int r = 0; r < 16; r++) {
            int idx = tid + r * 256;
            int row = idx >> 5, kp = idx & 31;
            sA[row][kp] = g_wvh[(size_t)(o0 + row) * 128 + kp0g + kp];
            sB[row][kp] = xth[(size_t)(n0 + row) * 128 + kp0g + kp];
        }
        __syncthreads();
#pragma unroll
        for (int kk = 0; kk < 4; kk++) {
            int kp0 = kk * 8;
            unsigned a[4][4], bf[4][2];
#pragma unroll
            for (int i = 0; i < 4; i++) {
                int row = wm * 64 + i * 16 + gp;
                a[i][0] = sA[row][kp0 + tg];
                a[i][1] = sA[row + 8][kp0 + tg];
                a[i][2] = sA[row][kp0 + 4 + tg];
                a[i][3] = sA[row + 8][kp0 + 4 + tg];
            }
#pragma unroll
            for (int j = 0; j < 4; j++) {
                int col = wn * 32 + j * 8 + gp;
                bf[j][0] = sB[col][kp0 + tg];
                bf[j][1] = sB[col][kp0 + 4 + tg];
            }
#pragma unroll
            for (int i = 0; i < 4; i++)
#pragma unroll
                for (int j = 0; j < 4; j++)
                    mma_fp16(acc[i][j], a[i][0], a[i][1], a[i][2], a[i][3],
                             bf[j][0], bf[j][1]);
        }
    }

#pragma unroll
    for (int i = 0; i < 4; i++) {
        int o = o0 + wm * 64 + i * 16 + gp;
        float b0 = bias[o], b1 = bias[o + 8];
#pragma unroll
        for (int j = 0; j < 4; j++) {
            int np = (n0 + wn * 32 + j * 8 + 2 * tg) / 2;
            g_vh[((size_t)b * CC + o) * (NN / 2) + np] =
                pack_h2(acc[i][j][0] + b0, acc[i][j][1] + b0);
            g_vh[((size_t)b * CC + o + 8) * (NN / 2) + np] =
                pack_h2(acc[i][j][2] + b1, acc[i][j][3] + b1);
        }
    }
}

// ---------------------------------------------------------------------------
// convt_tc: t[o][n] = wt[o][:] . (x^T - x_a^T)[n][:] + bt  -> g_t fp32
// ---------------------------------------------------------------------------
__global__ __launch_bounds__(256) void convt_tc_kernel(const float* __restrict__ bias)
{
    const int b  = blockIdx.z;
    const int o0 = blockIdx.y * 128;
    const int n0 = blockIdx.x * 128;
    const unsigned* xth  = g_xth  + (size_t)b * NN * 128;
    const unsigned* xath = g_xaTh + (size_t)b * NN * 128;

    __shared__ unsigned sA[128][36];
    __shared__ unsigned sB[128][36];

    const int tid = threadIdx.x;
    const int lane = tid & 31, wid = tid >> 5;
    const int wm = wid >> 2, wn = wid & 3;
    const int gp = lane >> 2, tg = lane & 3;

    float acc[4][4][4] = {};

    for (int ks = 0; ks < 4; ks++) {
        int kp0g = ks * 32;
        __syncthreads();
#pragma unroll
        for (int r = 0; r < 16; r++) {
            int idx = tid + r * 256;
            int row = idx >> 5, kp = idx & 31;
            sA[row][kp] = g_wth[(size_t)(o0 + row) * 128 + kp0g + kp];
            size_t gi = (size_t)(n0 + row) * 128 + kp0g + kp;
            __half2 xv = *reinterpret_cast<const __half2*>(&xth[gi]);
            __half2 av = *reinterpret_cast<const __half2*>(&xath[gi]);
            __half2 d = __hsub2(xv, av);
            sB[row][kp] = *reinterpret_cast<unsigned*>(&d);
        }
        __syncthreads();
#pragma unroll
        for (int kk = 0; kk < 4; kk++) {
            int kp0 = kk * 8;
            unsigned a[4][4], bf[4][2];
#pragma unroll
            for (int i = 0; i < 4; i++) {
                int row = wm * 64 + i * 16 + gp;
                a[i][0] = sA[row][kp0 + tg];
                a[i][1] = sA[row + 8][kp0 + tg];
                a[i][2] = sA[row][kp0 + 4 + tg];
                a[i][3] = sA[row + 8][kp0 + 4 + tg];
            }
#pragma unroll
            for (int j = 0; j < 4; j++) {
                int col = wn * 32 + j * 8 + gp;
                bf[j][0] = sB[col][kp0 + tg];
                bf[j][1] = sB[col][kp0 + 4 + tg];
            }
#pragma unroll
            for (int i = 0; i < 4; i++)
#pragma unroll
                for (int j = 0; j < 4; j++)
                    mma_fp16(acc[i][j], a[i][0], a[i][1], a[i][2], a[i][3],
                             bf[j][0], bf[j][1]);
        }
    }

#pragma unroll
    for (int i = 0; i < 4; i++) {
        int o = o0 + wm * 64 + i * 16 + gp;
        float b0 = bias[o], b1 = bias[o + 8];
#pragma unroll
        for (int j = 0; j < 4; j++) {
            int n = n0 + wn * 32 + j * 8 + 2 * tg;
            float2 v0 = make_float2(acc[i][j][0] + b0, acc[i][j][1] + b0);
            float2 v1 = make_float2(acc[i][j][2] + b1, acc[i][j][3] + b1);
            *reinterpret_cast<float2*>(&g_t[((size_t)b * CC + o) * NN + n]) = v0;
            *reinterpret_cast<float2*>(&g_t[((size_t)b * CC + o + 8) * NN + n]) = v1;
        }
    }
}

// ---------------------------------------------------------------------------
// pass1: fused energy + row softmax stats (flash pass).
// ---------------------------------------------------------------------------
__global__ __launch_bounds__(256) void pass1_kernel()
{
    const int b  = blockIdx.y;
    const int n0 = blockIdx.x * 128;
    const unsigned* qh = g_qh + (size_t)b * NN * 32;

    __shared__ unsigned sA[128][36];
    __shared__ unsigned sB[128][36];
    __shared__ float2 sMrg[4][128];

    const int tid = threadIdx.x;
    const int lane = tid & 31, wid = tid >> 5;
    const int wm = wid >> 2, wn = wid & 3;
    const int gp = lane >> 2, tg = lane & 3;

#pragma unroll
    for (int r = 0; r < 16; r++) {
        int idx = tid + r * 256;
        int row = idx >> 5, kp = idx & 31;
        sA[row][kp] = qh[(size_t)(n0 + row) * 32 + kp];
    }

    float rmax[8], rsum[8];
#pragma unroll
    for (int i = 0; i < 8; i++) { rmax[i] = -1e30f; rsum[i] = 0.f; }

    for (int m0 = 0; m0 < NN; m0 += 128) {
        __syncthreads();
#pragma unroll
        for (int r = 0; r < 16; r++) {
            int idx = tid + r * 256;
            int row = idx >> 5, kp = idx & 31;
            sB[row][kp] = qh[(size_t)(m0 + row) * 32 + kp];
        }
        __syncthreads();

        float acc[4][4][4] = {};
#pragma unroll
        for (int ks = 0; ks < 4; ks++) {
            int kp0 = ks * 8;
            unsigned a[4][4], bf[4][2];
#pragma unroll
            for (int i = 0; i < 4; i++) {
                int row = wm * 64 + i * 16 + gp;
                a[i][0] = sA[row][kp0 + tg];
                a[i][1] = sA[row + 8][kp0 + tg];
                a[i][2] = sA[row][kp0 + 4 + tg];
                a[i][3] = sA[row + 8][kp0 + 4 + tg];
            }
#pragma unroll
            for (int j = 0; j < 4; j++) {
                int col = wn * 32 + j * 8 + gp;
                bf[j][0] = sB[col][kp0 + tg];
                bf[j][1] = sB[col][kp0 + 4 + tg];
            }
#pragma unroll
            for (int i = 0; i < 4; i++)
#pragma unroll
                for (int j = 0; j < 4; j++)
                    mma_fp16(acc[i][j], a[i][0], a[i][1], a[i][2], a[i][3],
                             bf[j][0], bf[j][1]);
        }

#pragma unroll
        for (int i = 0; i < 4; i++) {
            float m0v = -1e30f, m1v = -1e30f;
#pragma unroll
            for (int j = 0; j < 4; j++) {
                m0v = fmaxf(m0v, fmaxf(acc[i][j][0], acc[i][j][1]));
                m1v = fmaxf(m1v, fmaxf(acc[i][j][2], acc[i][j][3]));
            }
            m0v = fmaxf(m0v, __shfl_xor_sync(0xffffffffu, m0v, 1));
            m0v = fmaxf(m0v, __shfl_xor_sync(0xffffffffu, m0v, 2));
            m1v = fmaxf(m1v, __shfl_xor_sync(0xffffffffu, m1v, 1));
            m1v = fmaxf(m1v, __shfl_xor_sync(0xffffffffu, m1v, 2));
            float nm0 = fmaxf(rmax[2 * i],     m0v);
            float nm1 = fmaxf(rmax[2 * i + 1], m1v);
            float s0 = 0.f, s1 = 0.f;
#pragma unroll
            for (int j = 0; j < 4; j++) {
                s0 += __expf(acc[i][j][0] - nm0) + __expf(acc[i][j][1] - nm0);
                s1 += __expf(acc[i][j][2] - nm1) + __expf(acc[i][j][3] - nm1);
            }
            s0 += __shfl_xor_sync(0xffffffffu, s0, 1);
            s0 += __shfl_xor_sync(0xffffffffu, s0, 2);
            s1 += __shfl_xor_sync(0xffffffffu, s1, 1);
            s1 += __shfl_xor_sync(0xffffffffu, s1, 2);
            rsum[2 * i]     = rsum[2 * i]     * __expf(rmax[2 * i]     - nm0) + s0;
            rsum[2 * i + 1] = rsum[2 * i + 1] * __expf(rmax[2 * i + 1] - nm1) + s1;
            rmax[2 * i]     = nm0;
            rmax[2 * i + 1] = nm1;
        }
    }

    if (tg == 0) {
#pragma unroll
        for (int i = 0; i < 4; i++) {
            int row = wm * 64 + i * 16 + gp;
            sMrg[wn][row]     = make_float2(rmax[2 * i],     rsum[2 * i]);
            sMrg[wn][row + 8] = make_float2(rmax[2 * i + 1], rsum[2 * i + 1]);
        }
    }
    __syncthreads();
    if (tid < 128) {
        float2 v0 = sMrg[0][tid], v1 = sMrg[1][tid];
        float2 v2 = sMrg[2][tid], v3 = sMrg[3][tid];
        float M = fmaxf(fmaxf(v0.x, v1.x), fmaxf(v2.x, v3.x));
        float S = v0.y * __expf(v0.x - M) + v1.y * __expf(v1.x - M)
                + v2.y * __expf(v2.x - M) + v3.y * __expf(v3.x - M);
        g_rowmax[b * NN + n0 + tid] = M;
        g_rowinv[b * NN + n0 + tid] = 1.f / S;
    }
}

// ---------------------------------------------------------------------------
// xa: fused E-recompute + P + colsum + x_a^T = (P^T V^T) via swapped mma.
// Writes g_xaTh fp16 [m][c-pairs]. 512 threads, cp.async double-buffered.
// mma2: A = P[m][n] (sPh), B = V[c][n] (sVh)  ->  C[m][c], c-pairs contig.
// Warps for mma2: wm=wid>>2 over m (4x32), wn=wid&3 over c (4x64).
// ---------------------------------------------------------------------------
#define XA_W_SVH 0
#define XA_W_SQM (2 * 256 * 36)
#define XA_W_SQN (XA_W_SQM + 128 * 36)
#define XA_W_SPH (XA_W_SQN + 2 * 64 * 36)
#define XA_W_COL (XA_W_SPH + 2 * 128 * 36)
#define XA_SMEM_WORDS (XA_W_COL + 128)

__global__ __launch_bounds__(512, 1) void xa_kernel()
{
    const int b  = blockIdx.y;
    const int m0 = blockIdx.x * 128;
    const unsigned* vbh = g_vh + (size_t)b * CC * (NN / 2);
    const float* rmx = g_rowmax + b * NN;
    const float* rin = g_rowinv + b * NN;
    const unsigned* qh = g_qh + (size_t)b * NN * 32;

    extern __shared__ unsigned shm[];
    unsigned (*sQm)[36] = reinterpret_cast<unsigned(*)[36]>(shm + XA_W_SQM);
    float* sCol = reinterpret_cast<float*>(shm + XA_W_COL);
    const unsigned sbase = (unsigned)__cvta_generic_to_shared(shm);

    const int tid = threadIdx.x;
    const int lane = tid & 31, wid = tid >> 5;
    const int gp = lane >> 2, tg = lane & 3;
    const int nh = wid & 3, mh = wid >> 2;       // mma1 roles (4x4)
    const int wm = wid >> 2, wn = wid & 3;       // mma2 roles

    // q_m tile (constant for the block)
#pragma unroll
    for (int r = 0; r < 8; r++) {
        int idx = tid + r * 512;
        int row = idx >> 5, kp = idx & 31;
        sQm[row][kp] = qh[(size_t)(m0 + row) * 32 + kp];
    }
    if (tid < 128) sCol[tid] = 0.f;

    auto issue_loads = [&](int chunk, int buf) {
        int np0 = chunk * 32;
#pragma unroll
        for (int t = 0; t < 4; t++) {
            int idx = tid + t * 512;
            int row = idx >> 3, seg = idx & 7;
            unsigned dst = sbase + (XA_W_SVH + buf * 256 * 36 + row * 36 + seg * 4) * 4;
            cpa16(dst, vbh + (size_t)row * (NN / 2) + np0 + seg * 4);
        }
        {
            int row = tid >> 3, seg = tid & 7;
            unsigned dst = sbase + (XA_W_SQN + buf * 64 * 36 + row * 36 + seg * 4) * 4;
            cpa16(dst, qh + (size_t)(chunk * 64 + row) * 32 + seg * 4);
        }
        cpa_commit();
    };

    issue_loads(0, 0);
    issue_loads(1, 1);
    cpa_wait0();
    __syncthreads();

    float acc[2][8][4] = {};

    for (int i = 0; i < 64; i++) {
        const int buf = i & 1;
        const int n0 = i * 64;
        unsigned (*sQnB)[36] = reinterpret_cast<unsigned(*)[36]>(shm + XA_W_SQN + buf * 64 * 36);
        unsigned (*sVhB)[36] = reinterpret_cast<unsigned(*)[36]>(shm + XA_W_SVH + buf * 256 * 36);
        __half  (*sPhB)[72] = reinterpret_cast<__half(*)[72]>(shm + XA_W_SPH + buf * 128 * 36);
        unsigned (*sPhU)[36] = reinterpret_cast<unsigned(*)[36]>(shm + XA_W_SPH + buf * 128 * 36);

        // mma1: E chunk [64n x 128m]; warp rows nh*16+gp(+8), cols mh*32+j*8
        float e[4][4] = {};
#pragma unroll
        for (int ks = 0; ks < 4; ks++) {
            int kp0 = ks * 8;
            unsigned a0 = sQnB[nh * 16 + gp][kp0 + tg];
            unsigned a1 = sQnB[nh * 16 + gp + 8][kp0 + tg];
            unsigned a2 = sQnB[nh * 16 + gp][kp0 + 4 + tg];
            unsigned a3 = sQnB[nh * 16 + gp + 8][kp0 + 4 + tg];
#pragma unroll
            for (int j = 0; j < 4; j++) {
                int col = mh * 32 + j * 8 + gp;
                mma_fp16(e[j], a0, a1, a2, a3,
                         sQm[col][kp0 + tg], sQm[col][kp0 + 4 + tg]);
            }
        }

        int r0 = n0 + nh * 16 + gp;
        float mx0 = __ldg(&rmx[r0]),     iv0 = __ldg(&rin[r0]);
        float mx1 = __ldg(&rmx[r0 + 8]), iv1 = __ldg(&rin[r0 + 8]);
        int nr0 = nh * 16 + gp, nr1 = nr0 + 8;
#pragma unroll
        for (int j = 0; j < 4; j++) {
            int cb = mh * 32 + j * 8 + 2 * tg;
            sPhB[cb][nr0]     = __float2half(__expf(e[j][0] - mx0) * iv0);
            sPhB[cb + 1][nr0] = __float2half(__expf(e[j][1] - mx0) * iv0);
            sPhB[cb][nr1]     = __float2half(__expf(e[j][2] - mx1) * iv1);
            sPhB[cb + 1][nr1] = __float2half(__expf(e[j][3] - mx1) * iv1);
        }
        __syncthreads();   // P[i] visible

        // colsum spread over all 512 threads
        {
            int m = tid & 127, seg = tid >> 7;
            const __half2* prow = reinterpret_cast<const __half2*>(sPhB[m]);
            float cs = 0.f;
#pragma unroll
            for (int k = 0; k < 8; k++) {
                float2 f = __half22float2(prow[seg * 8 + k]);
                cs += f.x + f.y;
            }
            atomicAdd(&sCol[m], cs);
        }

        // mma2 (swapped): acc[m,c] += P[m][n] * V[c][n]
#pragma unroll
        for (int ks = 0; ks < 4; ks++) {
            int kp0 = ks * 8;
            unsigned pa[2][4], bf[8][2];
#pragma unroll
            for (int ii = 0; ii < 2; ii++) {
                int row = wm * 32 + ii * 16 + gp;
                pa[ii][0] = sPhU[row][kp0 + tg];
                pa[ii][1] = sPhU[row + 8][kp0 + tg];
                pa[ii][2] = sPhU[row][kp0 + 4 + tg];
                pa[ii][3] = sPhU[row + 8][kp0 + 4 + tg];
            }
#pragma unroll
            for (int j = 0; j < 8; j++) {
                int col = wn * 64 + j * 8 + gp;
                bf[j][0] = sVhB[col][kp0 + tg];
                bf[j][1] = sVhB[col][kp0 + 4 + tg];
            }
#pragma unroll
            for (int ii = 0; ii < 2; ii++)
#pragma unroll
                for (int j = 0; j < 8; j++)
                    mma_fp16(acc[ii][j], pa[ii][0], pa[ii][1], pa[ii][2], pa[ii][3],
                             bf[j][0], bf[j][1]);
        }

        cpa_wait0();
        __syncthreads();
        if (i + 2 < 64)
            issue_loads(i + 2, buf);
    }

    // epilogue: x_a^T[m][c] = acc * inv(m); write fp16 pairs (c contig)
#pragma unroll
    for (int ii = 0; ii < 2; ii++) {
        int mr = wm * 32 + ii * 16 + gp;
        float i0 = 1.f / (1e-9f + sCol[mr]);
        float i1 = 1.f / (1e-9f + sCol[mr + 8]);
        size_t r0 = ((size_t)b * NN + m0 + mr) * 128;
        size_t r1 = r0 + 8 * 128;
#pragma unroll
        for (int j = 0; j < 8; j++) {
            int cp = wn * 32 + j * 4 + tg;
            g_xaTh[r0 + cp] = pack_h2(acc[ii][j][0] * i0, acc[ii][j][1] * i0);
            g_xaTh[r1 + cp] = pack_h2(acc[ii][j][2] * i1, acc[ii][j][3] * i1);
        }
    }
}

// ---------------------------------------------------------------------------
// BN stats: per channel c, mean/var over (B, N).
// ---------------------------------------------------------------------------
__global__ __launch_bounds__(256) void bnstats_kernel()
{
    const int c = blockIdx.x;
    float s = 0.f, s2 = 0.f;
    for (int i = threadIdx.x; i < BB * NN; i += 256) {
        int b = i >> 12;
        int n = i & (NN - 1);
        float v = g_t[((size_t)b * CC + c) * NN + n];
        s += v;
        s2 += v * v;
    }
    __shared__ float rs[256], rs2[256];
    rs[threadIdx.x] = s;
    rs2[threadIdx.x] = s2;
    __syncthreads();
    for (int st = 128; st; st >>= 1) {
        if (threadIdx.x < st) {
            rs[threadIdx.x]  += rs[threadIdx.x + st];
            rs2[threadIdx.x] += rs2[threadIdx.x + st];
        }
        __syncthreads();
    }
    if (threadIdx.x == 0) {
        const float invM = 1.f / (float)(BB * NN);
        float mean = rs[0] * invM;
        float var = rs2[0] * invM - mean * mean;
        g_mean[c] = mean;
        g_rstd[c] = rsqrtf(var + 1e-5f);
    }
}

// ---------------------------------------------------------------------------
// Final: out = x + relu(gamma * (t - mean) * rstd + beta)
// ---------------------------------------------------------------------------
__global__ __launch_bounds__(256) void final_kernel(
    const float* __restrict__ x, const float* __restrict__ gamma,
    const float* __restrict__ beta, float* __restrict__ out)
{
    size_t i = (size_t)blockIdx.x * 256 + threadIdx.x;
    int c = (int)((i >> 12) & 255);
    float t = g_t[i];
    float th = (t - g_mean[c]) * g_rstd[c];
    float r = fmaxf(0.f, gamma[c] * th + beta[c]);
    out[i] = x[i] + r;
}

// ---------------------------------------------------------------------------
extern "C" void kernel_launch(void* const* d_in, const int* in_sizes, int n_in,
                              void* d_out, int out_size)
{
    const float* x     = (const float*)d_in[0];
    const float* wq    = (const float*)d_in[1];
    const float* wv    = (const float*)d_in[2];
    const float* bv    = (const float*)d_in[3];
    const float* wt    = (const float*)d_in[4];
    const float* bt    = (const float*)d_in[5];
    const float* gamma = (const float*)d_in[6];
    const float* beta  = (const float*)d_in[7];
    float* out = (float*)d_out;

    const int xa_smem = XA_SMEM_WORDS * 4;
    cudaFuncSetAttribute(xa_kernel,
                         cudaFuncAttributeMaxDynamicSharedMemorySize, xa_smem);

    // x^T fp16 + weight fp16 conversions
    xt_kernel<<<dim3(NN / 64, CC / 64, BB), 256>>>(x);
    wcvt_kernel<<<(8192 + 65536 + 255) / 256, 256>>>(wq, wv, wt);
    // q^T = x^T wq^T  (weight-tied Q/K), fp16 mma
    convq_tc_kernel<<<dim3(NN / 128, 1, BB), 256>>>();
    // v = wv x + bv, fp16 mma
    convv_tc_kernel<<<dim3(NN / 128, CC / 128, BB), 256>>>(bv);
    // fused energy + row softmax stats
    pass1_kernel<<<dim3(NN / 128, BB), 256>>>();
    // fused E-recompute + softmax + double-norm + x_a^T (pipelined fp16)
    xa_kernel<<<dim3(NN / 128, BB), 512, xa_smem>>>();
    // t = wt (x - x_a) + bt, fp16 mma (subtraction in B-tile fill)
    convt_tc_kernel<<<dim3(NN / 128, CC / 128, BB), 256>>>(bt);
    // BN stats + final fused relu/residual
    bnstats_kernel<<<CC, 256>>>();
    final_kernel<<<(BB * CC * NN) / 256, 256>>>(x, gamma, beta, out);
}

// round 10
// speedup vs baseline: 6.2194x; 1.0284x over previous
#include <cuda_runtime.h>
#include <cuda_fp16.h>
#include <cstdint>

#define BB 4
#define CC 256
#define NN 4096
#define DD 64

// Scratch (device globals: allocation-free kernel_launch)
__device__ unsigned g_qh[(size_t)BB * NN * 32];         // 2 MB  q fp16 pairs [b][n][d/2]
__device__ unsigned g_vh[(size_t)BB * CC * (NN / 2)];   // 8 MB  v fp16 pairs [b][c][n/2]
__device__ unsigned g_xth[(size_t)BB * NN * (CC / 2)];  // 8 MB  x^T fp16 pairs [b][n][c/2]
__device__ unsigned g_xaTh[(size_t)BB * NN * (CC / 2)]; // 8 MB  x_a^T fp16 pairs [b][n][c/2]
__device__ unsigned g_wqh[DD * (CC / 2)];               // wq fp16 pairs [o][c/2]
__device__ unsigned g_wvh[CC * (CC / 2)];
__device__ unsigned g_wth[CC * (CC / 2)];
__device__ float g_rowmax[BB * NN];
__device__ float g_rowinv[BB * NN];
__device__ float g_t[(size_t)BB * CC * NN];             // 16 MB
__device__ float g_bnsum[CC];
__device__ float g_bnsum2[CC];
__device__ float g_mean[CC];
__device__ float g_rstd[CC];

// ---------------------------------------------------------------------------
// helpers
// ---------------------------------------------------------------------------
__device__ __forceinline__ void mma_fp16(
    float* c,
    unsigned a0, unsigned a1, unsigned a2, unsigned a3,
    unsigned b0, unsigned b1)
{
    asm volatile(
        "mma.sync.aligned.m16n8k16.row.col.f32.f16.f16.f32 "
        "{%0,%1,%2,%3}, {%4,%5,%6,%7}, {%8,%9}, {%0,%1,%2,%3};\n"
        : "+f"(c[0]), "+f"(c[1]), "+f"(c[2]), "+f"(c[3])
        : "r"(a0), "r"(a1), "r"(a2), "r"(a3), "r"(b0), "r"(b1));
}

__device__ __forceinline__ void cpa16(unsigned sdst, const void* gsrc)
{
    asm volatile("cp.async.cg.shared.global [%0], [%1], 16;\n"
                 :: "r"(sdst), "l"(gsrc));
}
__device__ __forceinline__ void cpa_commit()
{
    asm volatile("cp.async.commit_group;\n");
}
__device__ __forceinline__ void cpa_wait0()
{
    asm volatile("cp.async.wait_group 0;\n");
}

__device__ __forceinline__ unsigned pack_h2(float a, float b)
{
    __half2 h = __floats2half2_rn(a, b);
    return *reinterpret_cast<unsigned*>(&h);
}

// ---------------------------------------------------------------------------
// xt: transpose + convert x[b][c][n] fp32 -> g_xth[(b*N+n)*128 + c/2] fp16 pairs
// ---------------------------------------------------------------------------
__global__ __launch_bounds__(256) void xt_kernel(const float* __restrict__ x)
{
    const int b  = blockIdx.z;
    const int c0 = blockIdx.y * 64;
    const int n0 = blockIdx.x * 64;
    const float* xb = x + ((size_t)b * CC + c0) * NN + n0;

    __shared__ float sT[64][65];
    const int tid = threadIdx.x;

#pragma unroll
    for (int r = 0; r < 16; r++) {
        int idx = tid + r * 256;
        int c = idx >> 6, n = idx & 63;
        sT[c][n] = xb[(size_t)c * NN + n];
    }
    __syncthreads();
#pragma unroll
    for (int r = 0; r < 8; r++) {
        int idx = tid + r * 256;
        int n = idx >> 5, cp = idx & 31;
        g_xth[((size_t)b * NN + n0 + n) * 128 + c0 / 2 + cp] =
            pack_h2(sT[2 * cp][n], sT[2 * cp + 1][n]);
    }
}

// ---------------------------------------------------------------------------
// wcvt: convert wq/wv/wt to fp16 pairs; also zero BN accumulators
// ---------------------------------------------------------------------------
__global__ __launch_bounds__(256) void wcvt_kernel(
    const float* __restrict__ wq, const float* __restrict__ wv,
    const float* __restrict__ wt)
{
    int idx = blockIdx.x * 256 + threadIdx.x;
    if (idx < 256) { g_bnsum[idx] = 0.f; g_bnsum2[idx] = 0.f; }
    if (idx < 8192) {
        float2 f = *reinterpret_cast<const float2*>(&wq[idx * 2]);
        g_wqh[idx] = pack_h2(f.x, f.y);
    } else if (idx < 8192 + 32768) {
        int i = idx - 8192;
        float2 f = *reinterpret_cast<const float2*>(&wv[i * 2]);
        g_wvh[i] = pack_h2(f.x, f.y);
    } else if (idx < 8192 + 65536) {
        int i = idx - 8192 - 32768;
        float2 f = *reinterpret_cast<const float2*>(&wt[i * 2]);
        g_wth[i] = pack_h2(f.x, f.y);
    }
}

// ---------------------------------------------------------------------------
// convq_tc: q^T[n][o] = x^T[n][:] . wq[o][:]  -> g_qh[(b*N+n)*32 + o/2]
// ---------------------------------------------------------------------------
__global__ __launch_bounds__(256) void convq_tc_kernel()
{
    const int b  = blockIdx.z;
    const int n0 = blockIdx.x * 128;
    const unsigned* xth = g_xth + (size_t)b * NN * 128;

    __shared__ unsigned sA[128][36];
    __shared__ unsigned sB[64][36];

    const int tid = threadIdx.x;
    const int lane = tid & 31, wid = tid >> 5;
    const int wm = wid >> 2, wn = wid & 3;
    const int gp = lane >> 2, tg = lane & 3;

    float acc[4][2][4] = {};

    for (int ks = 0; ks < 4; ks++) {
        int kp0g = ks * 32;
        __syncthreads();
#pragma unroll
        for (int r = 0; r < 16; r++) {
            int idx = tid + r * 256;
            int row = idx >> 5, kp = idx & 31;
            sA[row][kp] = xth[(size_t)(n0 + row) * 128 + kp0g + kp];
        }
#pragma unroll
        for (int r = 0; r < 8; r++) {
            int idx = tid + r * 256;
            int row = idx >> 5, kp = idx & 31;
            sB[row][kp] = g_wqh[(size_t)row * 128 + kp0g + kp];
        }
        __syncthreads();
#pragma unroll
        for (int kk = 0; kk < 4; kk++) {
            int kp0 = kk * 8;
            unsigned a[4][4], bf[2][2];
#pragma unroll
            for (int i = 0; i < 4; i++) {
                int row = wm * 64 + i * 16 + gp;
                a[i][0] = sA[row][kp0 + tg];
                a[i][1] = sA[row + 8][kp0 + tg];
                a[i][2] = sA[row][kp0 + 4 + tg];
                a[i][3] = sA[row + 8][kp0 + 4 + tg];
            }
#pragma unroll
            for (int j = 0; j < 2; j++) {
                int col = wn * 16 + j * 8 + gp;
                bf[j][0] = sB[col][kp0 + tg];
                bf[j][1] = sB[col][kp0 + 4 + tg];
            }
#pragma unroll
            for (int i = 0; i < 4; i++)
#pragma unroll
                for (int j = 0; j < 2; j++)
                    mma_fp16(acc[i][j], a[i][0], a[i][1], a[i][2], a[i][3],
                             bf[j][0], bf[j][1]);
        }
    }

#pragma unroll
    for (int i = 0; i < 4; i++) {
        int n = n0 + wm * 64 + i * 16 + gp;
#pragma unroll
        for (int j = 0; j < 2; j++) {
            int op = wn * 8 + j * 4 + tg;
            g_qh[((size_t)b * NN + n) * 32 + op]     = pack_h2(acc[i][j][0], acc[i][j][1]);
            g_qh[((size_t)b * NN + n + 8) * 32 + op] = pack_h2(acc[i][j][2], acc[i][j][3]);
        }
    }
}

// ---------------------------------------------------------------------------
// convv_tc: v[o][n] = wv[o][:] . x^T[n][:] + bv  -> g_vh[(b*C+o)*(N/2) + n/2]
// ---------------------------------------------------------------------------
__global__ __launch_bounds__(256) void convv_tc_kernel(const float* __restrict__ bias)
{
    const int b  = blockIdx.z;
    const int o0 = blockIdx.y * 128;
    const int n0 = blockIdx.x * 128;
    const unsigned* xth = g_xth + (size_t)b * NN * 128;

    __shared__ unsigned sA[128][36];
    __shared__ unsigned sB[128][36];

    const int tid = threadIdx.x;
    const int lane = tid & 31, wid = tid >> 5;
    const int wm = wid >> 2, wn = wid & 3;
    const int gp = lane >> 2, tg = lane & 3;

    float acc[4][4][4] = {};

    for (int ks = 0; ks < 4; ks++) {
        int kp0g = ks * 32;
        __syncthreads();
#pragma unroll
        for (int r = 0; r < 16; r++) {
            int idx = tid + r * 256;
            int row = idx >> 5, kp = idx & 31;
            sA[row][kp] = g_wvh[(size_t)(o0 + row) * 128 + kp0g + kp];
            sB[row][kp] = xth[(size_t)(n0 + row) * 128 + kp0g + kp];
        }
        __syncthreads();
#pragma unroll
        for (int kk = 0; kk < 4; kk++) {
            int kp0 = kk * 8;
            unsigned a[4][4], bf[4][2];
#pragma unroll
            for (int i = 0; i < 4; i++) {
                int row = wm * 64 + i * 16 + gp;
                a[i][0] = sA[row][kp0 + tg];
                a[i][1] = sA[row + 8][kp0 + tg];
                a[i][2] = sA[row][kp0 + 4 + tg];
                a[i][3] = sA[row + 8][kp0 + 4 + tg];
            }
#pragma unroll
            for (int j = 0; j < 4; j++) {
                int col = wn * 32 + j * 8 + gp;
                bf[j][0] = sB[col][kp0 + tg];
                bf[j][1] = sB[col][kp0 + 4 + tg];
            }
#pragma unroll
            for (int i = 0; i < 4; i++)
#pragma unroll
                for (int j = 0; j < 4; j++)
                    mma_fp16(acc[i][j], a[i][0], a[i][1], a[i][2], a[i][3],
                             bf[j][0], bf[j][1]);
        }
    }

#pragma unroll
    for (int i = 0; i < 4; i++) {
        int o = o0 + wm * 64 + i * 16 + gp;
        float b0 = bias[o], b1 = bias[o + 8];
#pragma unroll
        for (int j = 0; j < 4; j++) {
            int np = (n0 + wn * 32 + j * 8 + 2 * tg) / 2;
            g_vh[((size_t)b * CC + o) * (NN / 2) + np] =
                pack_h2(acc[i][j][0] + b0, acc[i][j][1] + b0);
            g_vh[((size_t)b * CC + o + 8) * (NN / 2) + np] =
                pack_h2(acc[i][j][2] + b1, acc[i][j][3] + b1);
        }
    }
}

// ---------------------------------------------------------------------------
// convt_tc: t[o][n] = wt[o][:] . (x^T - x_a^T)[n][:] + bt  -> g_t fp32
// Fused BN partial sums: per-channel sum/sumsq -> g_bnsum/g_bnsum2 (atomics).
// ---------------------------------------------------------------------------
__global__ __launch_bounds__(256) void convt_tc_kernel(const float* __restrict__ bias)
{
    const int b  = blockIdx.z;
    const int o0 = blockIdx.y * 128;
    const int n0 = blockIdx.x * 128;
    const unsigned* xth  = g_xth  + (size_t)b * NN * 128;
    const unsigned* xath = g_xaTh + (size_t)b * NN * 128;

    __shared__ unsigned sA[128][36];
    __shared__ unsigned sB[128][36];
    __shared__ float sS[128], sS2[128];

    const int tid = threadIdx.x;
    const int lane = tid & 31, wid = tid >> 5;
    const int wm = wid >> 2, wn = wid & 3;
    const int gp = lane >> 2, tg = lane & 3;

    if (tid < 128) { sS[tid] = 0.f; sS2[tid] = 0.f; }

    float acc[4][4][4] = {};

    for (int ks = 0; ks < 4; ks++) {
        int kp0g = ks * 32;
        __syncthreads();
#pragma unroll
        for (int r = 0; r < 16; r++) {
            int idx = tid + r * 256;
            int row = idx >> 5, kp = idx & 31;
            sA[row][kp] = g_wth[(size_t)(o0 + row) * 128 + kp0g + kp];
            size_t gi = (size_t)(n0 + row) * 128 + kp0g + kp;
            __half2 xv = *reinterpret_cast<const __half2*>(&xth[gi]);
            __half2 av = *reinterpret_cast<const __half2*>(&xath[gi]);
            __half2 d = __hsub2(xv, av);
            sB[row][kp] = *reinterpret_cast<unsigned*>(&d);
        }
        __syncthreads();
#pragma unroll
        for (int kk = 0; kk < 4; kk++) {
            int kp0 = kk * 8;
            unsigned a[4][4], bf[4][2];
#pragma unroll
            for (int i = 0; i < 4; i++) {
                int row = wm * 64 + i * 16 + gp;
                a[i][0] = sA[row][kp0 + tg];
                a[i][1] = sA[row + 8][kp0 + tg];
                a[i][2] = sA[row][kp0 + 4 + tg];
                a[i][3] = sA[row + 8][kp0 + 4 + tg];
            }
#pragma unroll
            for (int j = 0; j < 4; j++) {
                int col = wn * 32 + j * 8 + gp;
                bf[j][0] = sB[col][kp0 + tg];
                bf[j][1] = sB[col][kp0 + 4 + tg];
            }
#pragma unroll
            for (int i = 0; i < 4; i++)
#pragma unroll
                for (int j = 0; j < 4; j++)
                    mma_fp16(acc[i][j], a[i][0], a[i][1], a[i][2], a[i][3],
                             bf[j][0], bf[j][1]);
        }
    }

#pragma unroll
    for (int i = 0; i < 4; i++) {
        int ol = wm * 64 + i * 16 + gp;
        int o = o0 + ol;
        float b0 = bias[o], b1 = bias[o + 8];
        float sa = 0.f, sa2 = 0.f, sb = 0.f, sb2 = 0.f;
#pragma unroll
        for (int j = 0; j < 4; j++) {
            int n = n0 + wn * 32 + j * 8 + 2 * tg;
            float t00 = acc[i][j][0] + b0, t01 = acc[i][j][1] + b0;
            float t10 = acc[i][j][2] + b1, t11 = acc[i][j][3] + b1;
            sa += t00 + t01;  sa2 += t00 * t00 + t01 * t01;
            sb += t10 + t11;  sb2 += t10 * t10 + t11 * t11;
            *reinterpret_cast<float2*>(&g_t[((size_t)b * CC + o) * NN + n]) =
                make_float2(t00, t01);
            *reinterpret_cast<float2*>(&g_t[((size_t)b * CC + o + 8) * NN + n]) =
                make_float2(t10, t11);
        }
        // reduce across tg (4 lanes share the same rows)
#pragma unroll
        for (int off = 1; off <= 2; off <<= 1) {
            sa  += __shfl_xor_sync(0xffffffffu, sa,  off);
            sa2 += __shfl_xor_sync(0xffffffffu, sa2, off);
            sb  += __shfl_xor_sync(0xffffffffu, sb,  off);
            sb2 += __shfl_xor_sync(0xffffffffu, sb2, off);
        }
        if (tg == 0) {
            atomicAdd(&sS[ol], sa);      atomicAdd(&sS2[ol], sa2);
            atomicAdd(&sS[ol + 8], sb);  atomicAdd(&sS2[ol + 8], sb2);
        }
    }
    __syncthreads();
    if (tid < 128) {
        atomicAdd(&g_bnsum[o0 + tid], sS[tid]);
        atomicAdd(&g_bnsum2[o0 + tid], sS2[tid]);
    }
}

// ---------------------------------------------------------------------------
// bnfin: mean/rstd from accumulated sums (1 block)
// ---------------------------------------------------------------------------
__global__ void bnfin_kernel()
{
    int c = threadIdx.x;
    const float invM = 1.f / (float)(BB * NN);
    float mean = g_bnsum[c] * invM;
    float var = g_bnsum2[c] * invM - mean * mean;
    g_mean[c] = mean;
    g_rstd[c] = rsqrtf(var + 1e-5f);
}

// ---------------------------------------------------------------------------
// pass1: fused energy + row softmax stats (flash pass).
// ---------------------------------------------------------------------------
__global__ __launch_bounds__(256) void pass1_kernel()
{
    const int b  = blockIdx.y;
    const int n0 = blockIdx.x * 128;
    const unsigned* qh = g_qh + (size_t)b * NN * 32;

    __shared__ unsigned sA[128][36];
    __shared__ unsigned sB[128][36];
    __shared__ float2 sMrg[4][128];

    const int tid = threadIdx.x;
    const int lane = tid & 31, wid = tid >> 5;
    const int wm = wid >> 2, wn = wid & 3;
    const int gp = lane >> 2, tg = lane & 3;

#pragma unroll
    for (int r = 0; r < 16; r++) {
        int idx = tid + r * 256;
        int row = idx >> 5, kp = idx & 31;
        sA[row][kp] = qh[(size_t)(n0 + row) * 32 + kp];
    }

    float rmax[8], rsum[8];
#pragma unroll
    for (int i = 0; i < 8; i++) { rmax[i] = -1e30f; rsum[i] = 0.f; }

    for (int m0 = 0; m0 < NN; m0 += 128) {
        __syncthreads();
#pragma unroll
        for (int r = 0; r < 16; r++) {
            int idx = tid + r * 256;
            int row = idx >> 5, kp = idx & 31;
            sB[row][kp] = qh[(size_t)(m0 + row) * 32 + kp];
        }
        __syncthreads();

        float acc[4][4][4] = {};
#pragma unroll
        for (int ks = 0; ks < 4; ks++) {
            int kp0 = ks * 8;
            unsigned a[4][4], bf[4][2];
#pragma unroll
            for (int i = 0; i < 4; i++) {
                int row = wm * 64 + i * 16 + gp;
                a[i][0] = sA[row][kp0 + tg];
                a[i][1] = sA[row + 8][kp0 + tg];
                a[i][2] = sA[row][kp0 + 4 + tg];
                a[i][3] = sA[row + 8][kp0 + 4 + tg];
            }
#pragma unroll
            for (int j = 0; j < 4; j++) {
                int col = wn * 32 + j * 8 + gp;
                bf[j][0] = sB[col][kp0 + tg];
                bf[j][1] = sB[col][kp0 + 4 + tg];
            }
#pragma unroll
            for (int i = 0; i < 4; i++)
#pragma unroll
                for (int j = 0; j < 4; j++)
                    mma_fp16(acc[i][j], a[i][0], a[i][1], a[i][2], a[i][3],
                             bf[j][0], bf[j][1]);
        }

#pragma unroll
        for (int i = 0; i < 4; i++) {
            float m0v = -1e30f, m1v = -1e30f;
#pragma unroll
            for (int j = 0; j < 4; j++) {
                m0v = fmaxf(m0v, fmaxf(acc[i][j][0], acc[i][j][1]));
                m1v = fmaxf(m1v, fmaxf(acc[i][j][2], acc[i][j][3]));
            }
            m0v = fmaxf(m0v, __shfl_xor_sync(0xffffffffu, m0v, 1));
            m0v = fmaxf(m0v, __shfl_xor_sync(0xffffffffu, m0v, 2));
            m1v = fmaxf(m1v, __shfl_xor_sync(0xffffffffu, m1v, 1));
            m1v = fmaxf(m1v, __shfl_xor_sync(0xffffffffu, m1v, 2));
            float nm0 = fmaxf(rmax[2 * i],     m0v);
            float nm1 = fmaxf(rmax[2 * i + 1], m1v);
            float s0 = 0.f, s1 = 0.f;
#pragma unroll
            for (int j = 0; j < 4; j++) {
                s0 += __expf(acc[i][j][0] - nm0) + __expf(acc[i][j][1] - nm0);
                s1 += __expf(acc[i][j][2] - nm1) + __expf(acc[i][j][3] - nm1);
            }
            s0 += __shfl_xor_sync(0xffffffffu, s0, 1);
            s0 += __shfl_xor_sync(0xffffffffu, s0, 2);
            s1 += __shfl_xor_sync(0xffffffffu, s1, 1);
            s1 += __shfl_xor_sync(0xffffffffu, s1, 2);
            rsum[2 * i]     = rsum[2 * i]     * __expf(rmax[2 * i]     - nm0) + s0;
            rsum[2 * i + 1] = rsum[2 * i + 1] * __expf(rmax[2 * i + 1] - nm1) + s1;
            rmax[2 * i]     = nm0;
            rmax[2 * i + 1] = nm1;
        }
    }

    if (tg == 0) {
#pragma unroll
        for (int i = 0; i < 4; i++) {
            int row = wm * 64 + i * 16 + gp;
            sMrg[wn][row]     = make_float2(rmax[2 * i],     rsum[2 * i]);
            sMrg[wn][row + 8] = make_float2(rmax[2 * i + 1], rsum[2 * i + 1]);
        }
    }
    __syncthreads();
    if (tid < 128) {
        float2 v0 = sMrg[0][tid], v1 = sMrg[1][tid];
        float2 v2 = sMrg[2][tid], v3 = sMrg[3][tid];
        float M = fmaxf(fmaxf(v0.x, v1.x), fmaxf(v2.x, v3.x));
        float S = v0.y * __expf(v0.x - M) + v1.y * __expf(v1.x - M)
                + v2.y * __expf(v2.x - M) + v3.y * __expf(v3.x - M);
        g_rowmax[b * NN + n0 + tid] = M;
        g_rowinv[b * NN + n0 + tid] = 1.f / S;
    }
}

// ---------------------------------------------------------------------------
// xa: fused E-recompute + P + colsum + x_a^T, single-sync software pipeline.
// iter i: mma1(i+1) -> P(i+1) write | colsum(i) | mma2(i) | wait | sync | loads
// ---------------------------------------------------------------------------
#define XA_W_SVH 0
#define XA_W_SQM (2 * 256 * 36)
#define XA_W_SQN (XA_W_SQM + 128 * 36)
#define XA_W_SPH (XA_W_SQN + 2 * 64 * 36)
#define XA_W_COL (XA_W_SPH + 2 * 128 * 36)
#define XA_SMEM_WORDS (XA_W_COL + 128)

__global__ __launch_bounds__(512, 1) void xa_kernel()
{
    const int b  = blockIdx.y;
    const int m0 = blockIdx.x * 128;
    const unsigned* vbh = g_vh + (size_t)b * CC * (NN / 2);
    const float* rmx = g_rowmax + b * NN;
    const float* rin = g_rowinv + b * NN;
    const unsigned* qh = g_qh + (size_t)b * NN * 32;

    extern __shared__ unsigned shm[];
    unsigned (*sQm)[36] = reinterpret_cast<unsigned(*)[36]>(shm + XA_W_SQM);
    float* sCol = reinterpret_cast<float*>(shm + XA_W_COL);
    const unsigned sbase = (unsigned)__cvta_generic_to_shared(shm);

    const int tid = threadIdx.x;
    const int lane = tid & 31, wid = tid >> 5;
    const int gp = lane >> 2, tg = lane & 3;
    const int nh = wid & 3, mh = wid >> 2;       // mma1 roles (4x4)
    const int wm = wid >> 2, wn = wid & 3;       // mma2 roles

    // q_m tile (constant for the block)
#pragma unroll
    for (int r = 0; r < 8; r++) {
        int idx = tid + r * 512;
        int row = idx >> 5, kp = idx & 31;
        sQm[row][kp] = qh[(size_t)(m0 + row) * 32 + kp];
    }
    if (tid < 128) sCol[tid] = 0.f;

    auto issue_V = [&](int chunk) {
        int buf = chunk & 1;
        int np0 = chunk * 32;
#pragma unroll
        for (int t = 0; t < 4; t++) {
            int idx = tid + t * 512;
            int row = idx >> 3, seg = idx & 7;
            unsigned dst = sbase + (XA_W_SVH + buf * 256 * 36 + row * 36 + seg * 4) * 4;
            cpa16(dst, vbh + (size_t)row * (NN / 2) + np0 + seg * 4);
        }
    };
    auto issue_Qn = [&](int chunk) {
        int buf = chunk & 1;
        int row = tid >> 3, seg = tid & 7;
        unsigned dst = sbase + (XA_W_SQN + buf * 64 * 36 + row * 36 + seg * 4) * 4;
        cpa16(dst, qh + (size_t)(chunk * 64 + row) * 32 + seg * 4);
    };

    // mma1 for chunk: compute E^chunk and write P into sPh[chunk&1]
    auto do_mma1 = [&](int chunk) {
        int buf = chunk & 1;
        unsigned (*sQnB)[36] = reinterpret_cast<unsigned(*)[36]>(shm + XA_W_SQN + buf * 64 * 36);
        __half (*sPhB)[72] = reinterpret_cast<__half(*)[72]>(shm + XA_W_SPH + buf * 128 * 36);
        float e[4][4] = {};
#pragma unroll
        for (int ks = 0; ks < 4; ks++) {
            int kp0 = ks * 8;
            unsigned a0 = sQnB[nh * 16 + gp][kp0 + tg];
            unsigned a1 = sQnB[nh * 16 + gp + 8][kp0 + tg];
            unsigned a2 = sQnB[nh * 16 + gp][kp0 + 4 + tg];
            unsigned a3 = sQnB[nh * 16 + gp + 8][kp0 + 4 + tg];
#pragma unroll
            for (int j = 0; j < 4; j++) {
                int col = mh * 32 + j * 8 + gp;
                mma_fp16(e[j], a0, a1, a2, a3,
                         sQm[col][kp0 + tg], sQm[col][kp0 + 4 + tg]);
            }
        }
        int r0 = chunk * 64 + nh * 16 + gp;
        float mx0 = __ldg(&rmx[r0]),     iv0 = __ldg(&rin[r0]);
        float mx1 = __ldg(&rmx[r0 + 8]), iv1 = __ldg(&rin[r0 + 8]);
        int nr0 = nh * 16 + gp, nr1 = nr0 + 8;
#pragma unroll
        for (int j = 0; j < 4; j++) {
            int cb = mh * 32 + j * 8 + 2 * tg;
            sPhB[cb][nr0]     = __float2half(__expf(e[j][0] - mx0) * iv0);
            sPhB[cb + 1][nr0] = __float2half(__expf(e[j][1] - mx0) * iv0);
            sPhB[cb][nr1]     = __float2half(__expf(e[j][2] - mx1) * iv1);
            sPhB[cb + 1][nr1] = __float2half(__expf(e[j][3] - mx1) * iv1);
        }
    };

    // prologue: V(0),V(1),Qn(0),Qn(1) in flight
    issue_V(0); issue_V(1); issue_Qn(0); issue_Qn(1); cpa_commit();
    cpa_wait0();
    __syncthreads();

    do_mma1(0);            // P(0)
    __syncthreads();
    issue_Qn(2); cpa_commit();

    float acc[2][8][4] = {};

    for (int i = 0; i < 64; i++) {
        const int buf = i & 1;
        unsigned (*sVhB)[36] = reinterpret_cast<unsigned(*)[36]>(shm + XA_W_SVH + buf * 256 * 36);
        __half  (*sPhB)[72] = reinterpret_cast<__half(*)[72]>(shm + XA_W_SPH + buf * 128 * 36);
        unsigned (*sPhU)[36] = reinterpret_cast<unsigned(*)[36]>(shm + XA_W_SPH + buf * 128 * 36);

        // 1. mma1(i+1): E chunk + P(i+1) into the other buffer (safe: all
        //    readers of P(i-1) retired at the previous iteration's sync)
        if (i < 63)
            do_mma1(i + 1);

        // 2. colsum(i)
        {
            int m = tid & 127, seg = tid >> 7;
            const __half2* prow = reinterpret_cast<const __half2*>(sPhB[m]);
            float cs = 0.f;
#pragma unroll
            for (int k = 0; k < 8; k++) {
                float2 f = __half22float2(prow[seg * 8 + k]);
                cs += f.x + f.y;
            }
            atomicAdd(&sCol[m], cs);
        }

        // 3. mma2(i): acc[m,c] += P[m][n] * V[c][n]
#pragma unroll
        for (int ks = 0; ks < 4; ks++) {
            int kp0 = ks * 8;
            unsigned pa[2][4], bf[8][2];
#pragma unroll
            for (int ii = 0; ii < 2; ii++) {
                int row = wm * 32 + ii * 16 + gp;
                pa[ii][0] = sPhU[row][kp0 + tg];
                pa[ii][1] = sPhU[row + 8][kp0 + tg];
                pa[ii][2] = sPhU[row][kp0 + 4 + tg];
                pa[ii][3] = sPhU[row + 8][kp0 + 4 + tg];
            }
#pragma unroll
            for (int j = 0; j < 8; j++) {
                int col = wn * 64 + j * 8 + gp;
                bf[j][0] = sVhB[col][kp0 + tg];
                bf[j][1] = sVhB[col][kp0 + 4 + tg];
            }
#pragma unroll
            for (int ii = 0; ii < 2; ii++)
#pragma unroll
                for (int j = 0; j < 8; j++)
                    mma_fp16(acc[ii][j], pa[ii][0], pa[ii][1], pa[ii][2], pa[ii][3],
                             bf[j][0], bf[j][1]);
        }

        // 4. wait for V(i+1), Qn(i+2); 5. single sync; 6. next loads
        cpa_wait0();
        __syncthreads();
        if (i + 2 < 64) issue_V(i + 2);
        if (i + 3 < 64) issue_Qn(i + 3);
        cpa_commit();
    }

    // epilogue: x_a^T[m][c] = acc * inv(m); write fp16 pairs (c contig)
#pragma unroll
    for (int ii = 0; ii < 2; ii++) {
        int mr = wm * 32 + ii * 16 + gp;
        float i0 = 1.f / (1e-9f + sCol[mr]);
        float i1 = 1.f / (1e-9f + sCol[mr + 8]);
        size_t r0 = ((size_t)b * NN + m0 + mr) * 128;
        size_t r1 = r0 + 8 * 128;
#pragma unroll
        for (int j = 0; j < 8; j++) {
            int cp = wn * 32 + j * 4 + tg;
            g_xaTh[r0 + cp] = pack_h2(acc[ii][j][0] * i0, acc[ii][j][1] * i0);
            g_xaTh[r1 + cp] = pack_h2(acc[ii][j][2] * i1, acc[ii][j][3] * i1);
        }
    }
}

// ---------------------------------------------------------------------------
// Final: out = x + relu(gamma * (t - mean) * rstd + beta)
// ---------------------------------------------------------------------------
__global__ __launch_bounds__(256) void final_kernel(
    const float* __restrict__ x, const float* __restrict__ gamma,
    const float* __restrict__ beta, float* __restrict__ out)
{
    size_t i = (size_t)blockIdx.x * 256 + threadIdx.x;
    int c = (int)((i >> 12) & 255);
    float t = g_t[i];
    float th = (t - g_mean[c]) * g_rstd[c];
    float r = fmaxf(0.f, gamma[c] * th + beta[c]);
    out[i] = x[i] + r;
}

// ---------------------------------------------------------------------------
extern "C" void kernel_launch(void* const* d_in, const int* in_sizes, int n_in,
                              void* d_out, int out_size)
{
    const float* x     = (const float*)d_in[0];
    const float* wq    = (const float*)d_in[1];
    const float* wv    = (const float*)d_in[2];
    const float* bv    = (const float*)d_in[3];
    const float* wt    = (const float*)d_in[4];
    const float* bt    = (const float*)d_in[5];
    const float* gamma = (const float*)d_in[6];
    const float* beta  = (const float*)d_in[7];
    float* out = (float*)d_out;

    const int xa_smem = XA_SMEM_WORDS * 4;
    cudaFuncSetAttribute(xa_kernel,
                         cudaFuncAttributeMaxDynamicSharedMemorySize, xa_smem);

    // x^T fp16 + weight fp16 conversions (also zeroes BN accumulators)
    xt_kernel<<<dim3(NN / 64, CC / 64, BB), 256>>>(x);
    wcvt_kernel<<<(8192 + 65536 + 255) / 256, 256>>>(wq, wv, wt);
    // q^T = x^T wq^T  (weight-tied Q/K), fp16 mma
    convq_tc_kernel<<<dim3(NN / 128, 1, BB), 256>>>();
    // v = wv x + bv, fp16 mma
    convv_tc_kernel<<<dim3(NN / 128, CC / 128, BB), 256>>>(bv);
    // fused energy + row softmax stats
    pass1_kernel<<<dim3(NN / 128, BB), 256>>>();
    // fused E-recompute + softmax + double-norm + x_a^T (1-sync pipeline)
    xa_kernel<<<dim3(NN / 128, BB), 512, xa_smem>>>();
    // t = wt (x - x_a) + bt, fp16 mma, fused BN partial sums
    convt_tc_kernel<<<dim3(NN / 128, CC / 128, BB), 256>>>(bt);
    // BN finalize + fused relu/residual
    bnfin_kernel<<<1, CC>>>();
    final_kernel<<<(BB * CC * NN) / 256, 256>>>(x, gamma, beta, out);
}